// round 14
// baseline (speedup 1.0000x reference)
#include <cuda_runtime.h>
#include <cstdint>
#include <math.h>

// ---------------- problem constants ----------------
#define BATCH 16384
#define ZD 32
#define NE 512
#define GAMMA 0.99f
#define ONE_M_GAMMA 0.01f
#define BETA 1.0f

#define OFF_SCAL (BATCH * 784)   // x_rec size
// d_out layout: [x_rec (B*784)][quant][commit][perplexity][emb_new (512*32)]

// ---------------- scratch ----------------
__device__ float g_h2[BATCH * 32 * 7 * 7];
__device__ float g_a [BATCH * 224];
__device__ float g_z [BATCH * ZD];
__device__ int   g_idx[BATCH];
__device__ float g_enorm[NE];
__device__ float g_counts[NE];
__device__ float g_sums[NE * ZD];
__device__ float g_loss[1];
// fragment-order weight textures: [s][kk][oct][lane] -> (b0,b1)
__device__ float2 g_wf_r1[9216];   // res1 w1 (raw fp32)
__device__ float2 g_wf_r2[9216];   // res2 w1 (tf32)
__device__ float2 g_wf_c2[4096];   // conv2 w  (raw fp32)

// ---------------- tf32 mma helpers ----------------
__device__ __forceinline__ float to_tf32(float x) {
    float y;
    asm("cvt.rna.tf32.f32 %0, %1;" : "=f"(y) : "f"(x));
    return y;
}

// Bitwise hi/lo split: hi = RZ-truncated tf32 (LOP3), lo = v - hi (exact FADD).
__device__ __forceinline__ void split_tf32(float v, unsigned& hi, unsigned& lo) {
    unsigned h = __float_as_uint(v) & 0xffffe000u;
    hi = h;
    lo = __float_as_uint(v - __uint_as_float(h));
}

__device__ __forceinline__ void mma_tf32(float* d, const unsigned* a,
                                         unsigned b0, unsigned b1) {
    asm volatile(
        "mma.sync.aligned.m16n8k8.row.col.f32.tf32.tf32.f32 "
        "{%0,%1,%2,%3}, {%4,%5,%6,%7}, {%8,%9}, {%0,%1,%2,%3};\n"
        : "+f"(d[0]), "+f"(d[1]), "+f"(d[2]), "+f"(d[3])
        : "r"(a[0]), "r"(a[1]), "r"(a[2]), "r"(a[3]), "r"(b0), "r"(b1));
}

// 3-pass split mma: acc += a*b with ~fp32 accuracy
__device__ __forceinline__ void mma3(float* d, const unsigned* ah, const unsigned* al,
                                     unsigned bh0, unsigned bh1,
                                     unsigned bl0, unsigned bl1) {
    mma_tf32(d, ah, bl0, bl1);
    mma_tf32(d, al, bh0, bh1);
    mma_tf32(d, ah, bh0, bh1);
}

// ======================================================================
// weight repack kernels (run once per launch; tiny)
// ======================================================================
__global__ void repack_res(const float* __restrict__ w1,
                           float2* __restrict__ out, int cvt) {
    int i = blockIdx.x * 256 + threadIdx.x;
    if (i >= 9216) return;
    int lane = i & 31, oct = (i >> 5) & 7, kk = (i >> 8) & 3, s = i >> 10;
    int grp = lane >> 2, tig = lane & 3;
    int oc = oct * 8 + grp, ic = kk * 8 + tig;
    float b0 = w1[oc * 288 + ic * 9 + s];
    float b1 = w1[oc * 288 + (ic + 4) * 9 + s];
    if (cvt) { b0 = to_tf32(b0); b1 = to_tf32(b1); }
    out[i] = make_float2(b0, b1);
}

__global__ void repack_c2(const float* __restrict__ w,
                          float2* __restrict__ out) {
    int i = blockIdx.x * 256 + threadIdx.x;
    if (i >= 4096) return;
    int lane = i & 31, oct = (i >> 5) & 3, kk = (i >> 7) & 1, s = i >> 8;
    int grp = lane >> 2, tig = lane & 3;
    int oc = oct * 8 + grp, ic = kk * 8 + tig;
    out[i] = make_float2(w[oc * 256 + ic * 16 + s],
                         w[oc * 256 + (ic + 4) * 16 + s]);
}

// ======================================================================
// FUSED conv1+conv2 (encoder): 4 img/CTA, warp = (img, mh), ni=4 octs
// (doubles input-fragment reuse vs round-12). Bit-identical math.
// ======================================================================
#define C14_ZOFF 18432                   // zero block (5th image slot)
#define C14_XIN  23040                   // 5 * 4608
#define C14_XP   C14_XIN                 // x padded: 4 * 900 = 3600
#define C14_W1   (C14_XP + 3600)         // 26640
#define C14_B1   (C14_W1 + 256)          // 26896
#define C14_TOT  26912
#define C14_SMEM (C14_TOT * 4)           // 107648 B -> 2 CTA/SM

__global__ void __launch_bounds__(256) conv12_tc3(
        const float* __restrict__ x,
        const float* __restrict__ c1wg,
        const float* __restrict__ c1bg,
        const float2* __restrict__ wf,
        const float* __restrict__ bias,
        float* __restrict__ out) {
    extern __shared__ float sm[];
    float* xin = sm;
    float* xp  = sm + C14_XP;
    float* c1w = sm + C14_W1;
    float* c1b = sm + C14_B1;
    int t = threadIdx.x;
    int b0 = blockIdx.x * 4;

    for (int i = t; i < C14_XIN; i += 256) xin[i] = 0.f;
    for (int i = t; i < 3600; i += 256) xp[i] = 0.f;
    if (t < 256) c1w[t] = c1wg[t];
    if (t < 16)  c1b[t] = c1bg[t];
    __syncthreads();
    for (int i = t; i < 4 * 784; i += 256) {
        int im = i / 784, j = i % 784;
        int iy = j / 28, ix = j % 28;
        xp[im * 900 + (iy + 1) * 30 + (ix + 1)] = x[(size_t)(b0 + im) * 784 + j];
    }
    __syncthreads();

    // conv1 phase: 784 pixel-tasks (4 img x 196), each computes all 16 oc
    for (int pi = t; pi < 784; pi += 256) {
        int im = pi / 196, pix = pi % 196;
        int oy = pix / 14, ox = pix % 14;
        const float* basep = xp + im * 900 + (2 * oy) * 30 + 2 * ox;
        float patch[16];
        #pragma unroll
        for (int ky = 0; ky < 4; ky++)
            #pragma unroll
            for (int kx = 0; kx < 4; kx++)
                patch[ky * 4 + kx] = basep[ky * 30 + kx];
        float* dst = xin + im * 4608 + ((oy + 1) * 16 + (ox + 1)) * 18;
        #pragma unroll
        for (int oc = 0; oc < 16; oc++) {
            float acc = c1b[oc];
            #pragma unroll
            for (int tap = 0; tap < 16; tap++)
                acc += patch[tap] * c1w[oc * 16 + tap];
            dst[oc] = fmaxf(acc, 0.f);
        }
    }
    __syncthreads();

    // conv2 mma phase: warp = (img, mh); ni=4 octs (full 32 oc)
    int lane = t & 31, wrp = t >> 5;
    int grp = lane >> 2, tig = lane & 3;
    int img = wrp >> 1, mh = wrp & 1;

    int rb[2][2];
    #pragma unroll
    for (int mi = 0; mi < 2; mi++)
        #pragma unroll
        for (int h = 0; h < 2; h++) {
            int p = mh * 32 + mi * 16 + grp + h * 8;
            rb[mi][h] = (p < 49)
                ? img * 4608 + ((p / 7) * 32 + (p % 7) * 2) * 18
                : C14_ZOFF;
        }

    float acc[2][4][4];
    #pragma unroll
    for (int mi = 0; mi < 2; mi++)
        #pragma unroll
        for (int ni = 0; ni < 4; ni++)
            #pragma unroll
            for (int c = 0; c < 4; c++) acc[mi][ni][c] = 0.f;

    #pragma unroll
    for (int ky = 0; ky < 4; ky++) {
        #pragma unroll
        for (int kx = 0; kx < 4; kx++) {
            int s = ky * 4 + kx;
            int soff = (ky * 16 + kx) * 18;
            #pragma unroll
            for (int kk = 0; kk < 2; kk++) {
                int kb = kk * 8;
                unsigned ah[2][4], al[2][4];
                #pragma unroll
                for (int mi = 0; mi < 2; mi++) {
                    split_tf32(xin[rb[mi][0] + soff + kb + tig],     ah[mi][0], al[mi][0]);
                    split_tf32(xin[rb[mi][1] + soff + kb + tig],     ah[mi][1], al[mi][1]);
                    split_tf32(xin[rb[mi][0] + soff + kb + tig + 4], ah[mi][2], al[mi][2]);
                    split_tf32(xin[rb[mi][1] + soff + kb + tig + 4], ah[mi][3], al[mi][3]);
                }
                #pragma unroll
                for (int ni = 0; ni < 4; ni++) {
                    float2 bw = __ldg(wf + (size_t)s * 256 + kk * 128 + ni * 32 + lane);
                    unsigned bh0, bl0, bh1, bl1;
                    split_tf32(bw.x, bh0, bl0);
                    split_tf32(bw.y, bh1, bl1);
                    mma3(acc[0][ni], ah[0], al[0], bh0, bh1, bl0, bl1);
                    mma3(acc[1][ni], ah[1], al[1], bh0, bh1, bl0, bl1);
                }
            }
        }
    }

    #pragma unroll
    for (int mi = 0; mi < 2; mi++) {
        #pragma unroll
        for (int ni = 0; ni < 4; ni++) {
            #pragma unroll
            for (int ci = 0; ci < 4; ci++) {
                int p = mh * 32 + mi * 16 + grp + ((ci >= 2) ? 8 : 0);
                if (p < 49) {
                    int oc = ni * 8 + tig * 2 + (ci & 1);
                    out[(size_t)(b0 + img) * 1568 + oc * 49 + p] =
                        acc[mi][ni][ci] + __ldg(bias + oc);
                }
            }
        }
    }
}

// ======================================================================
// res stack 3xTF32 (encoder)                           [round-10 proven]
// ======================================================================
#define E3_RS   5832
#define E3_W2   14536
#define E3_TOT  16840
#define E3_SMEM (E3_TOT * 4)

__global__ void __launch_bounds__(256) res_tc3(
        float* __restrict__ buf,
        const float2* __restrict__ wf,
        const float* __restrict__ pw2) {
    extern __shared__ float sm[];
    float* xin = sm;
    float* rs  = sm + E3_RS;
    float* w2s = sm + E3_W2;
    int t = threadIdx.x;
    int b0 = blockIdx.x * 2;

    for (int i = t; i < E3_RS; i += 256) xin[i] = 0.f;
    __syncthreads();
    for (int i = t; i < 2048; i += 256) {
        int oc = i >> 6, ic = i & 63;
        w2s[ic * 36 + oc] = pw2[i];
    }
    for (int i = t; i < 2 * 1568; i += 256) {
        int img = i / 1568, j = i % 1568;
        int ch = j / 49, p = j % 49;
        float v = buf[(size_t)(b0 + img) * 1568 + j];
        xin[img * 2916 + ((p / 7 + 1) * 9 + (p % 7 + 1)) * 36 + ch] = fmaxf(v, 0.f);
    }
    __syncthreads();

    int lane = t & 31, wrp = t >> 5;
    int grp = lane >> 2, tig = lane & 3;
    int img = wrp >> 2, mh = (wrp >> 1) & 1, nh = wrp & 1;
    int rbase = img * 64 + mh * 32;

    int rb[2][2];
    #pragma unroll
    for (int mi = 0; mi < 2; mi++)
        #pragma unroll
        for (int h = 0; h < 2; h++) {
            int p = mh * 32 + mi * 16 + grp + h * 8;
            rb[mi][h] = (p < 49) ? img * 2916 + ((p / 7) * 9 + (p % 7)) * 36 : 0;
        }

    float acc[2][4][4];
    #pragma unroll
    for (int mi = 0; mi < 2; mi++)
        #pragma unroll
        for (int ni = 0; ni < 4; ni++)
            #pragma unroll
            for (int c = 0; c < 4; c++) acc[mi][ni][c] = 0.f;

    #pragma unroll
    for (int ky = 0; ky < 3; ky++) {
        #pragma unroll
        for (int kx = 0; kx < 3; kx++) {
            int s = ky * 3 + kx;
            int soff = (ky * 9 + kx) * 36;
            #pragma unroll
            for (int kk = 0; kk < 4; kk++) {
                int kb = kk * 8;
                unsigned ah[2][4], al[2][4];
                #pragma unroll
                for (int mi = 0; mi < 2; mi++) {
                    split_tf32(xin[rb[mi][0] + soff + kb + tig],     ah[mi][0], al[mi][0]);
                    split_tf32(xin[rb[mi][1] + soff + kb + tig],     ah[mi][1], al[mi][1]);
                    split_tf32(xin[rb[mi][0] + soff + kb + tig + 4], ah[mi][2], al[mi][2]);
                    split_tf32(xin[rb[mi][1] + soff + kb + tig + 4], ah[mi][3], al[mi][3]);
                }
                #pragma unroll
                for (int ni = 0; ni < 4; ni++) {
                    int oct = nh * 4 + ni;
                    float2 bw = __ldg(wf + (size_t)s * 1024 + kk * 256 + oct * 32 + lane);
                    unsigned bh0, bl0, bh1, bl1;
                    split_tf32(bw.x, bh0, bl0);
                    split_tf32(bw.y, bh1, bl1);
                    mma3(acc[0][ni], ah[0], al[0], bh0, bh1, bl0, bl1);
                    mma3(acc[1][ni], ah[1], al[1], bh0, bh1, bl0, bl1);
                }
            }
        }
    }

    #pragma unroll
    for (int mi = 0; mi < 2; mi++) {
        int rlo = rbase + mi * 16 + grp, rhi = rlo + 8;
        #pragma unroll
        for (int ni = 0; ni < 4; ni++) {
            int c0 = nh * 32 + ni * 8 + tig * 2;
            rs[rlo * 68 + c0]     = fmaxf(acc[mi][ni][0], 0.f);
            rs[rlo * 68 + c0 + 1] = fmaxf(acc[mi][ni][1], 0.f);
            rs[rhi * 68 + c0]     = fmaxf(acc[mi][ni][2], 0.f);
            rs[rhi * 68 + c0 + 1] = fmaxf(acc[mi][ni][3], 0.f);
        }
    }
    __syncthreads();

    float acc2[2][2][4];
    #pragma unroll
    for (int mi = 0; mi < 2; mi++)
        #pragma unroll
        for (int ni = 0; ni < 2; ni++)
            #pragma unroll
            for (int c = 0; c < 4; c++) acc2[mi][ni][c] = 0.f;

    #pragma unroll
    for (int kk = 0; kk < 8; kk++) {
        int kb = kk * 8;
        unsigned ah[2][4], al[2][4];
        #pragma unroll
        for (int mi = 0; mi < 2; mi++) {
            int rlo = rbase + mi * 16 + grp;
            split_tf32(rs[rlo * 68 + kb + tig],           ah[mi][0], al[mi][0]);
            split_tf32(rs[(rlo + 8) * 68 + kb + tig],     ah[mi][1], al[mi][1]);
            split_tf32(rs[rlo * 68 + kb + tig + 4],       ah[mi][2], al[mi][2]);
            split_tf32(rs[(rlo + 8) * 68 + kb + tig + 4], ah[mi][3], al[mi][3]);
        }
        #pragma unroll
        for (int ni = 0; ni < 2; ni++) {
            int c = nh * 16 + ni * 8 + grp;
            unsigned bh0, bl0, bh1, bl1;
            split_tf32(w2s[(kb + tig) * 36 + c],     bh0, bl0);
            split_tf32(w2s[(kb + tig + 4) * 36 + c], bh1, bl1);
            mma3(acc2[0][ni], ah[0], al[0], bh0, bh1, bl0, bl1);
            mma3(acc2[1][ni], ah[1], al[1], bh0, bh1, bl0, bl1);
        }
    }

    #pragma unroll
    for (int mi = 0; mi < 2; mi++) {
        #pragma unroll
        for (int ni = 0; ni < 2; ni++) {
            #pragma unroll
            for (int ci = 0; ci < 4; ci++) {
                int p = mh * 32 + mi * 16 + grp + ((ci >= 2) ? 8 : 0);
                if (p < 49) {
                    int ch = nh * 16 + ni * 8 + tig * 2 + (ci & 1);
                    size_t g = (size_t)(b0 + img) * 1568 + ch * 49 + p;
                    float v = acc2[mi][ni][ci] + __ldg(buf + g);
                    buf[g] = fmaxf(v, 0.f);
                }
            }
        }
    }
}

// ======================================================================
// res stack single-TF32 (decoder)                      [round-10 proven]
// ======================================================================
#define D3_RS   5346
#define D3_W2   14050
#define D3_TOT  16354
#define D3_SMEM (D3_TOT * 4)

__global__ void __launch_bounds__(256) res_tcd(
        float* __restrict__ buf,
        const float2* __restrict__ wf,
        const float* __restrict__ pw2) {
    extern __shared__ float sm[];
    float* xin = sm;
    float* rs  = sm + D3_RS;
    float* w2s = sm + D3_W2;
    int t = threadIdx.x;
    int b0 = blockIdx.x * 2;

    for (int i = t; i < D3_RS; i += 256) xin[i] = 0.f;
    __syncthreads();
    for (int i = t; i < 2048; i += 256) {
        int oc = i >> 6, ic = i & 63;
        w2s[ic * 36 + oc] = to_tf32(pw2[i]);
    }
    for (int i = t; i < 2 * 1568; i += 256) {
        int img = i / 1568, j = i % 1568;
        int ch = j / 49, p = j % 49;
        float v = buf[(size_t)(b0 + img) * 1568 + j];
        xin[img * 2673 + ((p / 7 + 1) * 9 + (p % 7 + 1)) * 33 + ch] =
            to_tf32(fmaxf(v, 0.f));
    }
    __syncthreads();

    int lane = t & 31, wrp = t >> 5;
    int grp = lane >> 2, tig = lane & 3;
    int img = wrp >> 2, mh = (wrp >> 1) & 1, nh = wrp & 1;
    int rbase = img * 64 + mh * 32;

    int rb[2][2];
    #pragma unroll
    for (int mi = 0; mi < 2; mi++)
        #pragma unroll
        for (int h = 0; h < 2; h++) {
            int p = mh * 32 + mi * 16 + grp + h * 8;
            rb[mi][h] = (p < 49) ? img * 2673 + ((p / 7) * 9 + (p % 7)) * 33 : 0;
        }

    float acc[2][4][4];
    #pragma unroll
    for (int mi = 0; mi < 2; mi++)
        #pragma unroll
        for (int ni = 0; ni < 4; ni++)
            #pragma unroll
            for (int c = 0; c < 4; c++) acc[mi][ni][c] = 0.f;

    #pragma unroll
    for (int ky = 0; ky < 3; ky++) {
        #pragma unroll
        for (int kx = 0; kx < 3; kx++) {
            int s = ky * 3 + kx;
            int soff = (ky * 9 + kx) * 33;
            #pragma unroll
            for (int kk = 0; kk < 4; kk++) {
                int kb = kk * 8;
                unsigned a[2][4];
                #pragma unroll
                for (int mi = 0; mi < 2; mi++) {
                    a[mi][0] = __float_as_uint(xin[rb[mi][0] + soff + kb + tig]);
                    a[mi][1] = __float_as_uint(xin[rb[mi][1] + soff + kb + tig]);
                    a[mi][2] = __float_as_uint(xin[rb[mi][0] + soff + kb + tig + 4]);
                    a[mi][3] = __float_as_uint(xin[rb[mi][1] + soff + kb + tig + 4]);
                }
                #pragma unroll
                for (int ni = 0; ni < 4; ni++) {
                    int oct = nh * 4 + ni;
                    float2 bw = __ldg(wf + (size_t)s * 1024 + kk * 256 + oct * 32 + lane);
                    unsigned bb0 = __float_as_uint(bw.x);
                    unsigned bb1 = __float_as_uint(bw.y);
                    mma_tf32(acc[0][ni], a[0], bb0, bb1);
                    mma_tf32(acc[1][ni], a[1], bb0, bb1);
                }
            }
        }
    }

    #pragma unroll
    for (int mi = 0; mi < 2; mi++) {
        int rlo = rbase + mi * 16 + grp, rhi = rlo + 8;
        #pragma unroll
        for (int ni = 0; ni < 4; ni++) {
            int c0 = nh * 32 + ni * 8 + tig * 2;
            rs[rlo * 68 + c0]     = to_tf32(fmaxf(acc[mi][ni][0], 0.f));
            rs[rlo * 68 + c0 + 1] = to_tf32(fmaxf(acc[mi][ni][1], 0.f));
            rs[rhi * 68 + c0]     = to_tf32(fmaxf(acc[mi][ni][2], 0.f));
            rs[rhi * 68 + c0 + 1] = to_tf32(fmaxf(acc[mi][ni][3], 0.f));
        }
    }
    __syncthreads();

    float acc2[2][2][4];
    #pragma unroll
    for (int mi = 0; mi < 2; mi++)
        #pragma unroll
        for (int ni = 0; ni < 2; ni++)
            #pragma unroll
            for (int c = 0; c < 4; c++) acc2[mi][ni][c] = 0.f;

    #pragma unroll
    for (int kk = 0; kk < 8; kk++) {
        int kb = kk * 8;
        unsigned a[2][4];
        #pragma unroll
        for (int mi = 0; mi < 2; mi++) {
            int rlo = rbase + mi * 16 + grp;
            a[mi][0] = __float_as_uint(rs[rlo * 68 + kb + tig]);
            a[mi][1] = __float_as_uint(rs[(rlo + 8) * 68 + kb + tig]);
            a[mi][2] = __float_as_uint(rs[rlo * 68 + kb + tig + 4]);
            a[mi][3] = __float_as_uint(rs[(rlo + 8) * 68 + kb + tig + 4]);
        }
        #pragma unroll
        for (int ni = 0; ni < 2; ni++) {
            int c = nh * 16 + ni * 8 + grp;
            unsigned bb0 = __float_as_uint(w2s[(kb + tig) * 36 + c]);
            unsigned bb1 = __float_as_uint(w2s[(kb + tig + 4) * 36 + c]);
            mma_tf32(acc2[0][ni], a[0], bb0, bb1);
            mma_tf32(acc2[1][ni], a[1], bb0, bb1);
        }
    }

    #pragma unroll
    for (int mi = 0; mi < 2; mi++) {
        #pragma unroll
        for (int ni = 0; ni < 2; ni++) {
            #pragma unroll
            for (int ci = 0; ci < 4; ci++) {
                int p = mh * 32 + mi * 16 + grp + ((ci >= 2) ? 8 : 0);
                if (p < 49) {
                    int ch = nh * 16 + ni * 8 + tig * 2 + (ci & 1);
                    size_t g = (size_t)(b0 + img) * 1568 + ch * 49 + p;
                    float v = acc2[mi][ni][ci] + __ldg(buf + g);
                    buf[g] = fmaxf(v, 0.f);
                }
            }
        }
    }
}

// ======================================================================
// TF32 GEMM (decoder fc4): double-buffered smem        [round-13]
// ======================================================================
__global__ void __launch_bounds__(256) gemm_tc(
        const float* __restrict__ A,
        const float* __restrict__ W,
        const float* __restrict__ bias,
        float* __restrict__ C,
        int M, int N, int K) {
    __shared__ float As[2][128][17];
    __shared__ float Ws[2][64][17];
    int t = threadIdx.x, lane = t & 31, w = t >> 5;
    int grp = lane >> 2, tig = lane & 3;
    int m0 = blockIdx.x * 128, n0 = blockIdx.y * 64;
    int mw = (w & 3) * 32, nw = (w >> 2) * 32;
    float acc[2][4][4];
    #pragma unroll
    for (int mi = 0; mi < 2; mi++)
        #pragma unroll
        for (int ni = 0; ni < 4; ni++)
            #pragma unroll
            for (int c = 0; c < 4; c++) acc[mi][ni][c] = 0.f;

    int ar = t >> 1, ak = (t & 1) * 8;
    int wr = t >> 2, wk = (t & 3) * 4;
    const float* apb = A + (size_t)(m0 + ar) * K + ak;
    bool wval = (n0 + wr < N);
    const float* wpb = W + (size_t)(n0 + wr) * K + wk;

    float4 v0 = *(const float4*)apb;
    float4 v1 = *(const float4*)(apb + 4);
    float4 wv = wval ? *(const float4*)wpb : make_float4(0.f, 0.f, 0.f, 0.f);
    int s = 0;
    As[0][ar][ak + 0] = to_tf32(v0.x); As[0][ar][ak + 1] = to_tf32(v0.y);
    As[0][ar][ak + 2] = to_tf32(v0.z); As[0][ar][ak + 3] = to_tf32(v0.w);
    As[0][ar][ak + 4] = to_tf32(v1.x); As[0][ar][ak + 5] = to_tf32(v1.y);
    As[0][ar][ak + 6] = to_tf32(v1.z); As[0][ar][ak + 7] = to_tf32(v1.w);
    Ws[0][wr][wk + 0] = to_tf32(wv.x); Ws[0][wr][wk + 1] = to_tf32(wv.y);
    Ws[0][wr][wk + 2] = to_tf32(wv.z); Ws[0][wr][wk + 3] = to_tf32(wv.w);
    __syncthreads();

    for (int k0 = 0; k0 < K; k0 += 16) {
        bool more = (k0 + 16 < K);
        if (more) {
            v0 = *(const float4*)(apb + k0 + 16);
            v1 = *(const float4*)(apb + k0 + 20);
            wv = wval ? *(const float4*)(wpb + k0 + 16)
                      : make_float4(0.f, 0.f, 0.f, 0.f);
        }
        #pragma unroll
        for (int kk = 0; kk < 2; kk++) {
            int kb = kk * 8;
            unsigned a[2][4];
            #pragma unroll
            for (int mi = 0; mi < 2; mi++) {
                int r = mw + mi * 16 + grp;
                a[mi][0] = __float_as_uint(As[s][r][kb + tig]);
                a[mi][1] = __float_as_uint(As[s][r + 8][kb + tig]);
                a[mi][2] = __float_as_uint(As[s][r][kb + tig + 4]);
                a[mi][3] = __float_as_uint(As[s][r + 8][kb + tig + 4]);
            }
            #pragma unroll
            for (int ni = 0; ni < 4; ni++) {
                int n = nw + ni * 8 + grp;
                unsigned bb0 = __float_as_uint(Ws[s][n][kb + tig]);
                unsigned bb1 = __float_as_uint(Ws[s][n][kb + tig + 4]);
                mma_tf32(acc[0][ni], a[0], bb0, bb1);
                mma_tf32(acc[1][ni], a[1], bb0, bb1);
            }
        }
        if (more) {
            int d = s ^ 1;
            As[d][ar][ak + 0] = to_tf32(v0.x); As[d][ar][ak + 1] = to_tf32(v0.y);
            As[d][ar][ak + 2] = to_tf32(v0.z); As[d][ar][ak + 3] = to_tf32(v0.w);
            As[d][ar][ak + 4] = to_tf32(v1.x); As[d][ar][ak + 5] = to_tf32(v1.y);
            As[d][ar][ak + 6] = to_tf32(v1.z); As[d][ar][ak + 7] = to_tf32(v1.w);
            Ws[d][wr][wk + 0] = to_tf32(wv.x); Ws[d][wr][wk + 1] = to_tf32(wv.y);
            Ws[d][wr][wk + 2] = to_tf32(wv.z); Ws[d][wr][wk + 3] = to_tf32(wv.w);
            __syncthreads();
            s = d;
        }
    }
    #pragma unroll
    for (int mi = 0; mi < 2; mi++) {
        #pragma unroll
        for (int ni = 0; ni < 4; ni++) {
            #pragma unroll
            for (int ci = 0; ci < 4; ci++) {
                int r = m0 + mw + mi * 16 + grp + ((ci >= 2) ? 8 : 0);
                int n = n0 + nw + ni * 8 + tig * 2 + (ci & 1);
                if (n < N)
                    C[(size_t)r * N + n] = fmaxf(acc[mi][ni][ci] + bias[n], 0.f);
            }
        }
    }
}

// ======================================================================
// 3xTF32 GEMM (encoder fc1): double-buffered smem      [round-13]
// ======================================================================
__global__ void __launch_bounds__(256) gemm_tc3(
        const float* __restrict__ A,
        const float* __restrict__ W,
        const float* __restrict__ bias,
        float* __restrict__ C,
        int M, int N, int K) {
    __shared__ float As[2][128][17];
    __shared__ float Ws[2][64][17];
    int t = threadIdx.x, lane = t & 31, w = t >> 5;
    int grp = lane >> 2, tig = lane & 3;
    int m0 = blockIdx.x * 128, n0 = blockIdx.y * 64;
    int mw = (w & 3) * 32, nw = (w >> 2) * 32;
    float acc[2][4][4];
    #pragma unroll
    for (int mi = 0; mi < 2; mi++)
        #pragma unroll
        for (int ni = 0; ni < 4; ni++)
            #pragma unroll
            for (int c = 0; c < 4; c++) acc[mi][ni][c] = 0.f;

    int ar = t >> 1, ak = (t & 1) * 8;
    int wr = t >> 2, wk = (t & 3) * 4;
    const float* apb = A + (size_t)(m0 + ar) * K + ak;
    bool wval = (n0 + wr < N);
    const float* wpb = W + (size_t)(n0 + wr) * K + wk;

    float4 v0 = *(const float4*)apb;
    float4 v1 = *(const float4*)(apb + 4);
    float4 wv = wval ? *(const float4*)wpb : make_float4(0.f, 0.f, 0.f, 0.f);
    int s = 0;
    As[0][ar][ak + 0] = v0.x; As[0][ar][ak + 1] = v0.y;
    As[0][ar][ak + 2] = v0.z; As[0][ar][ak + 3] = v0.w;
    As[0][ar][ak + 4] = v1.x; As[0][ar][ak + 5] = v1.y;
    As[0][ar][ak + 6] = v1.z; As[0][ar][ak + 7] = v1.w;
    Ws[0][wr][wk + 0] = wv.x; Ws[0][wr][wk + 1] = wv.y;
    Ws[0][wr][wk + 2] = wv.z; Ws[0][wr][wk + 3] = wv.w;
    __syncthreads();

    for (int k0 = 0; k0 < K; k0 += 16) {
        bool more = (k0 + 16 < K);
        if (more) {
            v0 = *(const float4*)(apb + k0 + 16);
            v1 = *(const float4*)(apb + k0 + 20);
            wv = wval ? *(const float4*)(wpb + k0 + 16)
                      : make_float4(0.f, 0.f, 0.f, 0.f);
        }
        #pragma unroll
        for (int kk = 0; kk < 2; kk++) {
            int kb = kk * 8;
            unsigned ah[2][4], al[2][4];
            #pragma unroll
            for (int mi = 0; mi < 2; mi++) {
                int r = mw + mi * 16 + grp;
                split_tf32(As[s][r][kb + tig],         ah[mi][0], al[mi][0]);
                split_tf32(As[s][r + 8][kb + tig],     ah[mi][1], al[mi][1]);
                split_tf32(As[s][r][kb + tig + 4],     ah[mi][2], al[mi][2]);
                split_tf32(As[s][r + 8][kb + tig + 4], ah[mi][3], al[mi][3]);
            }
            #pragma unroll
            for (int ni = 0; ni < 4; ni++) {
                int n = nw + ni * 8 + grp;
                unsigned bh0, bl0, bh1, bl1;
                split_tf32(Ws[s][n][kb + tig],     bh0, bl0);
                split_tf32(Ws[s][n][kb + tig + 4], bh1, bl1);
                mma3(acc[0][ni], ah[0], al[0], bh0, bh1, bl0, bl1);
                mma3(acc[1][ni], ah[1], al[1], bh0, bh1, bl0, bl1);
            }
        }
        if (more) {
            int d = s ^ 1;
            As[d][ar][ak + 0] = v0.x; As[d][ar][ak + 1] = v0.y;
            As[d][ar][ak + 2] = v0.z; As[d][ar][ak + 3] = v0.w;
            As[d][ar][ak + 4] = v1.x; As[d][ar][ak + 5] = v1.y;
            As[d][ar][ak + 6] = v1.z; As[d][ar][ak + 7] = v1.w;
            Ws[d][wr][wk + 0] = wv.x; Ws[d][wr][wk + 1] = wv.y;
            Ws[d][wr][wk + 2] = wv.z; Ws[d][wr][wk + 3] = wv.w;
            __syncthreads();
            s = d;
        }
    }
    #pragma unroll
    for (int mi = 0; mi < 2; mi++) {
        #pragma unroll
        for (int ni = 0; ni < 4; ni++) {
            #pragma unroll
            for (int ci = 0; ci < 4; ci++) {
                int r = m0 + mw + mi * 16 + grp + ((ci >= 2) ? 8 : 0);
                int n = n0 + nw + ni * 8 + tig * 2 + (ci & 1);
                if (n < N)
                    C[(size_t)r * N + n] = fmaxf(acc[mi][ni][ci] + bias[n], 0.f);
            }
        }
    }
}

// ======================================================================
// convt2 inner body (compile-time tap tables)          [round-7 proven]
// ======================================================================
template<int DY0, int KY0, int DY1, int KY1,
         int DX0, int KX0, int DX1, int KX1>
__device__ __forceinline__ void ct2_body(
        const float* __restrict__ base, const float* __restrict__ w,
        float bv, float* __restrict__ outp, int m) {
    float acc[14];
    #pragma unroll
    for (int j = 0; j < 14; j++) acc[j] = bv;
    for (int ic = 0; ic < 16; ic++) {
        const float* xc = base + ic * 256;
        #pragma unroll
        for (int sy = 0; sy < 2; sy++) {
            int iy = m + (sy ? DY1 : DY0);
            float row[16];
            #pragma unroll
            for (int j = 0; j < 16; j++) row[j] = xc[(iy + 1) * 16 + j];
            {
                float wv = __ldg(w + ic * 16 + (sy ? KY1 : KY0) * 4 + KX0);
                #pragma unroll
                for (int n = 0; n < 14; n++) acc[n] += row[n + DX0 + 1] * wv;
            }
            {
                float wv = __ldg(w + ic * 16 + (sy ? KY1 : KY0) * 4 + KX1);
                #pragma unroll
                for (int n = 0; n < 14; n++) acc[n] += row[n + DX1 + 1] * wv;
            }
        }
    }
    #pragma unroll
    for (int n = 0; n < 14; n++) outp[2 * n] = acc[n];
}

// ======================================================================
// FUSED convt1+convt2 (decoder)                        [round-12 proven]
// ======================================================================
#define T12_IMSZ 2916
#define T12_ZB   6240
#define T12_XIN  6664
#define T12_W    T12_XIN
#define T12_HP   (T12_W + 16 * 32 * 24)
#define T12_TOT  (T12_HP + 2 * 4096)
#define T12_SMEM (T12_TOT * 4)

__global__ void __launch_bounds__(256) convt12_tc(
        const float* __restrict__ in,
        const float* __restrict__ w,
        const float* __restrict__ bias,
        const float* __restrict__ c2w,
        const float* __restrict__ c2b,
        float* __restrict__ out) {
    extern __shared__ float sm[];
    float* xin = sm;
    float* wt  = sm + T12_W;
    float* hp  = sm + T12_HP;
    int t = threadIdx.x;
    int b0 = blockIdx.x * 2;

    for (int i = t; i < T12_XIN; i += 256) xin[i] = 0.f;
    for (int i = t; i < 8192; i += 256) hp[i] = 0.f;
    __syncthreads();
    for (int i = t; i < 2 * 1568; i += 256) {
        int img = i / 1568, j = i % 1568;
        int ic = j / 49, p = j % 49, iy = p / 7, ix = p % 7;
        xin[img * T12_IMSZ + ((iy + 1) * 9 + (ix + 1)) * 36 + ic] =
            to_tf32(in[(size_t)(b0 + img) * 1568 + j]);
    }
    for (int i = t; i < 32 * 256; i += 256) {
        int ic = i / 256, r = i % 256, oc = r / 16, s = r % 16;
        wt[s * 768 + ic * 24 + oc] = to_tf32(w[i]);
    }
    __syncthreads();

    int lane = t & 31, wrp = t >> 5;
    int grp = lane >> 2, tig = lane & 3;
    int img = wrp >> 2, ph = wrp & 3;
    int a = ph >> 1, bp = ph & 1;
    int dyv[2], kyv[2], dxv[2], kxv[2];
    if (a == 0) { dyv[0] = 0; kyv[0] = 1; dyv[1] = -1; kyv[1] = 3; }
    else        { dyv[0] = 1; kyv[0] = 0; dyv[1] =  0; kyv[1] = 2; }
    if (bp == 0) { dxv[0] = 0; kxv[0] = 1; dxv[1] = -1; kxv[1] = 3; }
    else         { dxv[0] = 1; kxv[0] = 0; dxv[1] =  0; kxv[1] = 2; }

    int rb[4][2];
    #pragma unroll
    for (int mi = 0; mi < 4; mi++)
        #pragma unroll
        for (int h = 0; h < 2; h++) {
            int p = mi * 16 + grp + h * 8;
            rb[mi][h] = (p < 49)
                ? img * T12_IMSZ + ((p / 7 + 1) * 9 + (p % 7 + 1)) * 36
                : T12_ZB;
        }

    float acc[4][2][4];
    #pragma unroll
    for (int mi = 0; mi < 4; mi++)
        #pragma unroll
        for (int ni = 0; ni < 2; ni++)
            #pragma unroll
            for (int c = 0; c < 4; c++) acc[mi][ni][c] = 0.f;

    #pragma unroll
    for (int sy = 0; sy < 2; sy++) {
        #pragma unroll
        for (int sx = 0; sx < 2; sx++) {
            int soff = (dyv[sy] * 9 + dxv[sx]) * 36;
            const float* wsl = wt + (kyv[sy] * 4 + kxv[sx]) * 768;
            #pragma unroll
            for (int kk = 0; kk < 4; kk++) {
                int kb = kk * 8;
                unsigned afr[4][4];
                #pragma unroll
                for (int mi = 0; mi < 4; mi++) {
                    afr[mi][0] = __float_as_uint(xin[rb[mi][0] + soff + kb + tig]);
                    afr[mi][1] = __float_as_uint(xin[rb[mi][1] + soff + kb + tig]);
                    afr[mi][2] = __float_as_uint(xin[rb[mi][0] + soff + kb + tig + 4]);
                    afr[mi][3] = __float_as_uint(xin[rb[mi][1] + soff + kb + tig + 4]);
                }
                #pragma unroll
                for (int ni = 0; ni < 2; ni++) {
                    unsigned bb0 = __float_as_uint(wsl[(kb + tig) * 24 + ni * 8 + grp]);
                    unsigned bb1 = __float_as_uint(wsl[(kb + tig + 4) * 24 + ni * 8 + grp]);
                    #pragma unroll
                    for (int mi = 0; mi < 4; mi++)
                        mma_tf32(acc[mi][ni], afr[mi], bb0, bb1);
                }
            }
        }
    }

    #pragma unroll
    for (int mi = 0; mi < 4; mi++) {
        #pragma unroll
        for (int ni = 0; ni < 2; ni++) {
            #pragma unroll
            for (int ci = 0; ci < 4; ci++) {
                int p = mi * 16 + grp + ((ci >= 2) ? 8 : 0);
                if (p < 49) {
                    int m = p / 7, n = p % 7;
                    int oc = ni * 8 + tig * 2 + (ci & 1);
                    int oy = 2 * m + a, ox = 2 * n + bp;
                    float v = acc[mi][ni][ci] + __ldg(bias + oc);
                    hp[img * 4096 + oc * 256 + (oy + 1) * 16 + (ox + 1)] =
                        fmaxf(v, 0.f);
                }
            }
        }
    }
    __syncthreads();

    if (t < 112) {
        int ph2 = t / 28, r2 = t % 28;
        int img2 = r2 / 14, m2 = r2 % 14;
        int a2 = ph2 >> 1, b2 = ph2 & 1;
        const float* base2 = hp + img2 * 4096;
        float bv2 = c2b[0];
        float* outp = out + (size_t)(b0 + img2) * 784 + (2 * m2 + a2) * 28 + b2;
        if (ph2 == 0)      ct2_body<0, 1, -1, 3,  0, 1, -1, 3>(base2, c2w, bv2, outp, m2);
        else if (ph2 == 1) ct2_body<0, 1, -1, 3,  1, 0,  0, 2>(base2, c2w, bv2, outp, m2);
        else if (ph2 == 2) ct2_body<1, 0,  0, 2,  0, 1, -1, 3>(base2, c2w, bv2, outp, m2);
        else               ct2_body<1, 0,  0, 2,  1, 0,  0, 2>(base2, c2w, bv2, outp, m2);
    }
}

// ======================================================================
// fc2: z[B,32] = A[B,224] @ w^T + b  (fp32, feeds VQ)   [round-8]
// ======================================================================
__global__ void __launch_bounds__(256) fc2_kernel(
        const float* __restrict__ A,
        const float* __restrict__ w,
        const float* __restrict__ bias,
        float* __restrict__ out) {
    __shared__ float ws[32 * 224];
    int t = threadIdx.x;
    for (int i = t; i < 7168; i += 256) ws[i] = w[i];
    __syncthreads();
    int n = t & 31, r = t >> 5;
    float bv = bias[n];
    const float* wp = ws + n * 224;
    #pragma unroll
    for (int rr = 0; rr < 4; rr++) {
        int b = blockIdx.x * 32 + rr * 8 + r;
        const float* ap = A + (size_t)b * 224;
        float acc = bv;
        #pragma unroll 8
        for (int k = 0; k < 224; k++) acc += ap[k] * wp[k];
        out[(size_t)b * 32 + n] = acc;
    }
}

// ======================================================================
// VQ helpers (fp32 exact)
// ======================================================================
__global__ void enorm_kernel(const float* __restrict__ emb, float* __restrict__ enorm) {
    int e = blockIdx.x * blockDim.x + threadIdx.x;
    if (e < NE) {
        float s = 0.f;
        #pragma unroll
        for (int d = 0; d < ZD; d++) { float v = emb[e * ZD + d]; s += v * v; }
        enorm[e] = s;
    }
}

__global__ void zero_kernel(float* __restrict__ counts, float* __restrict__ sums,
                            float* __restrict__ loss) {
    int i = blockIdx.x * blockDim.x + threadIdx.x;
    if (i < NE) counts[i] = 0.f;
    if (i < NE * ZD) sums[i] = 0.f;
    if (i == 0) loss[0] = 0.f;
}

#define VQ_SMEM (NE * 36 * 4)

__global__ void __launch_bounds__(256) vq_kernel(
        const float* __restrict__ z,
        const float* __restrict__ emb,
        const float* __restrict__ enorm,
        int* __restrict__ idx,
        float* __restrict__ counts,
        float* __restrict__ sums,
        float* __restrict__ loss) {
    extern __shared__ float es[];          // [512][36]
    __shared__ float en[NE];
    __shared__ float zs[8][ZD];
    int t = threadIdx.x, lane = t & 31, wl = t >> 5;
    for (int i = t; i < NE * ZD; i += 256) {
        int e = i >> 5, d = i & 31;
        es[e * 36 + d] = emb[i];
    }
    for (int i = t; i < NE; i += 256) en[i] = enorm[i];
    __syncthreads();

    for (int rr = 0; rr < 8; rr++) {
        int row = blockIdx.x * 64 + wl * 8 + rr;
        zs[wl][lane] = z[(size_t)row * ZD + lane];
        __syncwarp();
        float best = 3.4e38f; int bi = NE;
        for (int e = lane; e < NE; e += 32) {
            const float* ep = es + e * 36;
            float dot = 0.f;
            #pragma unroll
            for (int d = 0; d < ZD; d += 4) {
                float4 v = *(const float4*)(ep + d);
                dot += zs[wl][d + 0] * v.x;
                dot += zs[wl][d + 1] * v.y;
                dot += zs[wl][d + 2] * v.z;
                dot += zs[wl][d + 3] * v.w;
            }
            float s = en[e] - 2.f * dot;
            if (s < best) { best = s; bi = e; }
        }
        #pragma unroll
        for (int off = 16; off; off >>= 1) {
            float ob = __shfl_xor_sync(0xffffffffu, best, off);
            int   oi = __shfl_xor_sync(0xffffffffu, bi, off);
            if (ob < best || (ob == best && oi < bi)) { best = ob; bi = oi; }
        }
        float zl = zs[wl][lane];
        float diff = es[bi * 36 + lane] - zl;
        float d2 = diff * diff;
        #pragma unroll
        for (int off = 16; off; off >>= 1)
            d2 += __shfl_xor_sync(0xffffffffu, d2, off);
        if (lane == 0) {
            idx[row] = bi;
            atomicAdd(&counts[bi], 1.f);
            atomicAdd(loss, d2);
        }
        atomicAdd(&sums[bi * ZD + lane], zl);
        __syncwarp();
    }
}

__global__ void embnew_kernel(const float* __restrict__ m_mat,
                              const float* __restrict__ n_mat,
                              const float* __restrict__ sums,
                              const float* __restrict__ counts,
                              float* __restrict__ out) {
    int i = blockIdx.x * blockDim.x + threadIdx.x;
    if (i < NE * ZD) {
        int e = i >> 5;
        float m = m_mat[i] * GAMMA + sums[i] * ONE_M_GAMMA;
        float n = n_mat[e] * GAMMA + counts[e] * ONE_M_GAMMA;
        out[i] = m / n;
    }
}

__global__ void finalize_kernel(const float* __restrict__ counts,
                                const float* __restrict__ loss,
                                float* __restrict__ out_scalars) {
    __shared__ float red[NE];
    int t = threadIdx.x;
    float c = counts[t];
    float em = c * (1.f / (float)BATCH);
    red[t] = em * logf(em + 1e-10f);
    __syncthreads();
    for (int s = 256; s; s >>= 1) {
        if (t < s) red[t] += red[t + s];
        __syncthreads();
    }
    if (t == 0) {
        float q = loss[0] * (1.f / ((float)BATCH * (float)ZD));
        out_scalars[0] = q;
        out_scalars[1] = BETA * q;
        out_scalars[2] = expf(-red[0]);
    }
}

// ======================================================================
// fc3 (fp32): 16 images/CTA                           [round-8, proven]
// ======================================================================
__global__ void __launch_bounds__(224) fc3_kernel(
        const float* __restrict__ emb,
        const int* __restrict__ idx,
        const float* __restrict__ w,
        const float* __restrict__ bias,
        float* __restrict__ out) {
    __shared__ float ws[224 * ZD];
    __shared__ float zq[16][ZD + 1];
    int b0 = blockIdx.x * 16, t = threadIdx.x;
    for (int i = t; i < 224 * ZD; i += 224) ws[i] = w[i];
    for (int i = t; i < 16 * ZD; i += 224) {
        int im = i >> 5, d = i & 31;
        zq[im][d] = emb[(size_t)idx[b0 + im] * ZD + d];
    }
    __syncthreads();
    float bv = bias[t];
    float wreg[ZD];
    const float* wp = ws + t * ZD;
    #pragma unroll
    for (int k = 0; k < ZD; k++) wreg[k] = wp[k];
    #pragma unroll 4
    for (int im = 0; im < 16; im++) {
        float acc = bv;
        #pragma unroll
        for (int k = 0; k < ZD; k++) acc += zq[im][k] * wreg[k];
        out[(size_t)(b0 + im) * 224 + t] = fmaxf(acc, 0.f);
    }
}

// ======================================================================
// launch
// ======================================================================
extern "C" void kernel_launch(void* const* d_in, const int* in_sizes, int n_in,
                              void* d_out, int out_size) {
    const float* x        = (const float*)d_in[0];
    const float* conv1_w  = (const float*)d_in[1];
    const float* conv1_b  = (const float*)d_in[2];
    const float* conv2_w  = (const float*)d_in[3];
    const float* conv2_b  = (const float*)d_in[4];
    const float* res1_w1  = (const float*)d_in[5];
    const float* res1_w2  = (const float*)d_in[6];
    const float* fc1_w    = (const float*)d_in[7];
    const float* fc1_b    = (const float*)d_in[8];
    const float* fc2_w    = (const float*)d_in[9];
    const float* fc2_b    = (const float*)d_in[10];
    const float* emb      = (const float*)d_in[11];
    const float* n_mat    = (const float*)d_in[12];
    const float* m_mat    = (const float*)d_in[13];
    const float* fc3_w    = (const float*)d_in[14];
    const float* fc3_b    = (const float*)d_in[15];
    const float* fc4_w    = (const float*)d_in[16];
    const float* fc4_b    = (const float*)d_in[17];
    const float* res2_w1  = (const float*)d_in[18];
    const float* res2_w2  = (const float*)d_in[19];
    const float* convt1_w = (const float*)d_in[20];
    const float* convt1_b = (const float*)d_in[21];
    const float* convt2_w = (const float*)d_in[22];
    const float* convt2_b = (const float*)d_in[23];
    float* out = (float*)d_out;

    float *h2, *a, *z, *enorm, *counts, *sums, *loss;
    int* idx;
    float2 *wf_r1, *wf_r2, *wf_c2;
    cudaGetSymbolAddress((void**)&h2,     g_h2);
    cudaGetSymbolAddress((void**)&a,      g_a);
    cudaGetSymbolAddress((void**)&z,      g_z);
    cudaGetSymbolAddress((void**)&idx,    g_idx);
    cudaGetSymbolAddress((void**)&enorm,  g_enorm);
    cudaGetSymbolAddress((void**)&counts, g_counts);
    cudaGetSymbolAddress((void**)&sums,   g_sums);
    cudaGetSymbolAddress((void**)&loss,   g_loss);
    cudaGetSymbolAddress((void**)&wf_r1,  g_wf_r1);
    cudaGetSymbolAddress((void**)&wf_r2,  g_wf_r2);
    cudaGetSymbolAddress((void**)&wf_c2,  g_wf_c2);

    cudaFuncSetAttribute(conv12_tc3,
                         cudaFuncAttributeMaxDynamicSharedMemorySize, C14_SMEM);
    cudaFuncSetAttribute(res_tc3,
                         cudaFuncAttributeMaxDynamicSharedMemorySize, E3_SMEM);
    cudaFuncSetAttribute(res_tcd,
                         cudaFuncAttributeMaxDynamicSharedMemorySize, D3_SMEM);
    cudaFuncSetAttribute(convt12_tc,
                         cudaFuncAttributeMaxDynamicSharedMemorySize, T12_SMEM);
    cudaFuncSetAttribute(vq_kernel,
                         cudaFuncAttributeMaxDynamicSharedMemorySize, VQ_SMEM);

    // weight repack (fragment-order textures)
    repack_res<<<36, 256>>>(res1_w1, wf_r1, 0);
    repack_res<<<36, 256>>>(res2_w1, wf_r2, 1);
    repack_c2 <<<16, 256>>>(conv2_w, wf_c2);

    // encoder (3xTF32 = fp32-class accuracy; VQ path preserved)
    conv12_tc3<<<BATCH / 4, 256, C14_SMEM>>>(x, conv1_w, conv1_b, wf_c2,
                                             conv2_b, h2);
    res_tc3  <<<BATCH / 2, 256, E3_SMEM>>>(h2, wf_r1, res1_w2);
    gemm_tc3<<<dim3(BATCH / 128, 4), 256>>>(h2, fc1_w, fc1_b, a,
                                            BATCH, 224, 1568);
    fc2_kernel<<<BATCH / 32, 256>>>(a, fc2_w, fc2_b, z);

    // VQ
    zero_kernel <<<(NE * ZD + 255) / 256, 256>>>(counts, sums, loss);
    enorm_kernel<<<2, 256>>>(emb, enorm);
    vq_kernel   <<<BATCH / 64, 256, VQ_SMEM>>>(z, emb, enorm, idx, counts,
                                               sums, loss);
    embnew_kernel  <<<(NE * ZD + 255) / 256, 256>>>(m_mat, n_mat, sums, counts,
                                                    out + OFF_SCAL + 3);
    finalize_kernel<<<1, NE>>>(counts, loss, out + OFF_SCAL);

    // decoder (single tf32)
    fc3_kernel<<<BATCH / 16, 224>>>(emb, idx, fc3_w, fc3_b, a);
    gemm_tc<<<dim3(BATCH / 128, 25), 256>>>(a, fc4_w, fc4_b, h2,
                                            BATCH, 1568, 224);
    res_tcd<<<BATCH / 2, 256, D3_SMEM>>>(h2, wf_r2, res2_w2);
    convt12_tc<<<BATCH / 2, 256, T12_SMEM>>>(h2, convt1_w, convt1_b,
                                             convt2_w, convt2_b, out);
}

// round 15
// speedup vs baseline: 1.0279x; 1.0279x over previous
#include <cuda_runtime.h>
#include <cstdint>
#include <math.h>

// ---------------- problem constants ----------------
#define BATCH 16384
#define ZD 32
#define NE 512
#define GAMMA 0.99f
#define ONE_M_GAMMA 0.01f
#define BETA 1.0f

#define OFF_SCAL (BATCH * 784)   // x_rec size
// d_out layout: [x_rec (B*784)][quant][commit][perplexity][emb_new (512*32)]

// ---------------- scratch ----------------
__device__ float g_h2[BATCH * 32 * 7 * 7];
__device__ float g_a [BATCH * 224];
__device__ float g_z [BATCH * ZD];
__device__ int   g_idx[BATCH];
__device__ float g_enorm[NE];
__device__ float g_counts[NE];
__device__ float g_sums[NE * ZD];
__device__ float g_loss[1];
// fragment-order weight textures: [s][kk][oct][lane] -> (b0,b1)
__device__ float2 g_wf_r1[9216];   // res1 w1 (raw fp32)
__device__ float2 g_wf_r2[9216];   // res2 w1 (tf32)
__device__ float2 g_wf_c2[4096];   // conv2 w  (raw fp32)

// ---------------- tf32 mma helpers ----------------
__device__ __forceinline__ float to_tf32(float x) {
    float y;
    asm("cvt.rna.tf32.f32 %0, %1;" : "=f"(y) : "f"(x));
    return y;
}

// Bitwise hi/lo split: hi = RZ-truncated tf32 (LOP3), lo = v - hi (exact FADD).
__device__ __forceinline__ void split_tf32(float v, unsigned& hi, unsigned& lo) {
    unsigned h = __float_as_uint(v) & 0xffffe000u;
    hi = h;
    lo = __float_as_uint(v - __uint_as_float(h));
}

__device__ __forceinline__ void mma_tf32(float* d, const unsigned* a,
                                         unsigned b0, unsigned b1) {
    asm volatile(
        "mma.sync.aligned.m16n8k8.row.col.f32.tf32.tf32.f32 "
        "{%0,%1,%2,%3}, {%4,%5,%6,%7}, {%8,%9}, {%0,%1,%2,%3};\n"
        : "+f"(d[0]), "+f"(d[1]), "+f"(d[2]), "+f"(d[3])
        : "r"(a[0]), "r"(a[1]), "r"(a[2]), "r"(a[3]), "r"(b0), "r"(b1));
}

// 3-pass split mma: acc += a*b with ~fp32 accuracy
__device__ __forceinline__ void mma3(float* d, const unsigned* ah, const unsigned* al,
                                     unsigned bh0, unsigned bh1,
                                     unsigned bl0, unsigned bl1) {
    mma_tf32(d, ah, bl0, bl1);
    mma_tf32(d, al, bh0, bh1);
    mma_tf32(d, ah, bh0, bh1);
}

// ======================================================================
// weight repack kernels (run once per launch; tiny)
// ======================================================================
__global__ void repack_res(const float* __restrict__ w1,
                           float2* __restrict__ out, int cvt) {
    int i = blockIdx.x * 256 + threadIdx.x;
    if (i >= 9216) return;
    int lane = i & 31, oct = (i >> 5) & 7, kk = (i >> 8) & 3, s = i >> 10;
    int grp = lane >> 2, tig = lane & 3;
    int oc = oct * 8 + grp, ic = kk * 8 + tig;
    float b0 = w1[oc * 288 + ic * 9 + s];
    float b1 = w1[oc * 288 + (ic + 4) * 9 + s];
    if (cvt) { b0 = to_tf32(b0); b1 = to_tf32(b1); }
    out[i] = make_float2(b0, b1);
}

__global__ void repack_c2(const float* __restrict__ w,
                          float2* __restrict__ out) {
    int i = blockIdx.x * 256 + threadIdx.x;
    if (i >= 4096) return;
    int lane = i & 31, oct = (i >> 5) & 3, kk = (i >> 7) & 1, s = i >> 8;
    int grp = lane >> 2, tig = lane & 3;
    int oc = oct * 8 + grp, ic = kk * 8 + tig;
    out[i] = make_float2(w[oc * 256 + ic * 16 + s],
                         w[oc * 256 + (ic + 4) * 16 + s]);
}

// ======================================================================
// FUSED conv1+conv2 (encoder): 4 img/CTA, 512 thr (16 warps).
// warp = (img, mh, nh) — exact round-12 per-warp workload, doubled
// warps/SM (smem 107.6 KB -> 2 CTA/SM = 32 warps). Bit-identical math.
// ======================================================================
#define C14_ZOFF 18432                   // zero block (5th image slot)
#define C14_XIN  23040                   // 5 * 4608
#define C14_XP   C14_XIN                 // x padded: 4 * 900 = 3600
#define C14_W1   (C14_XP + 3600)         // 26640
#define C14_B1   (C14_W1 + 256)          // 26896
#define C14_TOT  26912
#define C14_SMEM (C14_TOT * 4)           // 107648 B

__global__ void __launch_bounds__(512) conv12_tc3(
        const float* __restrict__ x,
        const float* __restrict__ c1wg,
        const float* __restrict__ c1bg,
        const float2* __restrict__ wf,
        const float* __restrict__ bias,
        float* __restrict__ out) {
    extern __shared__ float sm[];
    float* xin = sm;
    float* xp  = sm + C14_XP;
    float* c1w = sm + C14_W1;
    float* c1b = sm + C14_B1;
    int t = threadIdx.x;
    int b0 = blockIdx.x * 4;

    for (int i = t; i < C14_XIN; i += 512) xin[i] = 0.f;
    for (int i = t; i < 3600; i += 512) xp[i] = 0.f;
    if (t < 256) c1w[t] = c1wg[t];
    if (t < 16)  c1b[t] = c1bg[t];
    __syncthreads();
    for (int i = t; i < 4 * 784; i += 512) {
        int im = i / 784, j = i % 784;
        int iy = j / 28, ix = j % 28;
        xp[im * 900 + (iy + 1) * 30 + (ix + 1)] = x[(size_t)(b0 + im) * 784 + j];
    }
    __syncthreads();

    // conv1 phase: 784 pixel-tasks (4 img x 196), each computes all 16 oc
    for (int pi = t; pi < 784; pi += 512) {
        int im = pi / 196, pix = pi % 196;
        int oy = pix / 14, ox = pix % 14;
        const float* basep = xp + im * 900 + (2 * oy) * 30 + 2 * ox;
        float patch[16];
        #pragma unroll
        for (int ky = 0; ky < 4; ky++)
            #pragma unroll
            for (int kx = 0; kx < 4; kx++)
                patch[ky * 4 + kx] = basep[ky * 30 + kx];
        float* dst = xin + im * 4608 + ((oy + 1) * 16 + (ox + 1)) * 18;
        #pragma unroll
        for (int oc = 0; oc < 16; oc++) {
            float acc = c1b[oc];
            #pragma unroll
            for (int tap = 0; tap < 16; tap++)
                acc += patch[tap] * c1w[oc * 16 + tap];
            dst[oc] = fmaxf(acc, 0.f);
        }
    }
    __syncthreads();

    // conv2 mma phase: warp = (img, mh, nh) [round-12 workload]
    int lane = t & 31, wrp = t >> 5;
    int grp = lane >> 2, tig = lane & 3;
    int img = wrp >> 2, mh = (wrp >> 1) & 1, nh = wrp & 1;

    int rb[2][2];
    #pragma unroll
    for (int mi = 0; mi < 2; mi++)
        #pragma unroll
        for (int h = 0; h < 2; h++) {
            int p = mh * 32 + mi * 16 + grp + h * 8;
            rb[mi][h] = (p < 49)
                ? img * 4608 + ((p / 7) * 32 + (p % 7) * 2) * 18
                : C14_ZOFF;
        }

    float acc[2][2][4];
    #pragma unroll
    for (int mi = 0; mi < 2; mi++)
        #pragma unroll
        for (int ni = 0; ni < 2; ni++)
            #pragma unroll
            for (int c = 0; c < 4; c++) acc[mi][ni][c] = 0.f;

    #pragma unroll
    for (int ky = 0; ky < 4; ky++) {
        #pragma unroll
        for (int kx = 0; kx < 4; kx++) {
            int s = ky * 4 + kx;
            int soff = (ky * 16 + kx) * 18;
            #pragma unroll
            for (int kk = 0; kk < 2; kk++) {
                int kb = kk * 8;
                unsigned ah[2][4], al[2][4];
                #pragma unroll
                for (int mi = 0; mi < 2; mi++) {
                    split_tf32(xin[rb[mi][0] + soff + kb + tig],     ah[mi][0], al[mi][0]);
                    split_tf32(xin[rb[mi][1] + soff + kb + tig],     ah[mi][1], al[mi][1]);
                    split_tf32(xin[rb[mi][0] + soff + kb + tig + 4], ah[mi][2], al[mi][2]);
                    split_tf32(xin[rb[mi][1] + soff + kb + tig + 4], ah[mi][3], al[mi][3]);
                }
                #pragma unroll
                for (int ni = 0; ni < 2; ni++) {
                    int oct = nh * 2 + ni;
                    float2 bw = __ldg(wf + (size_t)s * 256 + kk * 128 + oct * 32 + lane);
                    unsigned bh0, bl0, bh1, bl1;
                    split_tf32(bw.x, bh0, bl0);
                    split_tf32(bw.y, bh1, bl1);
                    mma3(acc[0][ni], ah[0], al[0], bh0, bh1, bl0, bl1);
                    mma3(acc[1][ni], ah[1], al[1], bh0, bh1, bl0, bl1);
                }
            }
        }
    }

    #pragma unroll
    for (int mi = 0; mi < 2; mi++) {
        #pragma unroll
        for (int ni = 0; ni < 2; ni++) {
            #pragma unroll
            for (int ci = 0; ci < 4; ci++) {
                int p = mh * 32 + mi * 16 + grp + ((ci >= 2) ? 8 : 0);
                if (p < 49) {
                    int oc = nh * 16 + ni * 8 + tig * 2 + (ci & 1);
                    out[(size_t)(b0 + img) * 1568 + oc * 49 + p] =
                        acc[mi][ni][ci] + __ldg(bias + oc);
                }
            }
        }
    }
}

// ======================================================================
// res stack 3xTF32 (encoder)                           [round-10 proven]
// ======================================================================
#define E3_RS   5832
#define E3_W2   14536
#define E3_TOT  16840
#define E3_SMEM (E3_TOT * 4)

__global__ void __launch_bounds__(256) res_tc3(
        float* __restrict__ buf,
        const float2* __restrict__ wf,
        const float* __restrict__ pw2) {
    extern __shared__ float sm[];
    float* xin = sm;
    float* rs  = sm + E3_RS;
    float* w2s = sm + E3_W2;
    int t = threadIdx.x;
    int b0 = blockIdx.x * 2;

    for (int i = t; i < E3_RS; i += 256) xin[i] = 0.f;
    __syncthreads();
    for (int i = t; i < 2048; i += 256) {
        int oc = i >> 6, ic = i & 63;
        w2s[ic * 36 + oc] = pw2[i];
    }
    for (int i = t; i < 2 * 1568; i += 256) {
        int img = i / 1568, j = i % 1568;
        int ch = j / 49, p = j % 49;
        float v = buf[(size_t)(b0 + img) * 1568 + j];
        xin[img * 2916 + ((p / 7 + 1) * 9 + (p % 7 + 1)) * 36 + ch] = fmaxf(v, 0.f);
    }
    __syncthreads();

    int lane = t & 31, wrp = t >> 5;
    int grp = lane >> 2, tig = lane & 3;
    int img = wrp >> 2, mh = (wrp >> 1) & 1, nh = wrp & 1;
    int rbase = img * 64 + mh * 32;

    int rb[2][2];
    #pragma unroll
    for (int mi = 0; mi < 2; mi++)
        #pragma unroll
        for (int h = 0; h < 2; h++) {
            int p = mh * 32 + mi * 16 + grp + h * 8;
            rb[mi][h] = (p < 49) ? img * 2916 + ((p / 7) * 9 + (p % 7)) * 36 : 0;
        }

    float acc[2][4][4];
    #pragma unroll
    for (int mi = 0; mi < 2; mi++)
        #pragma unroll
        for (int ni = 0; ni < 4; ni++)
            #pragma unroll
            for (int c = 0; c < 4; c++) acc[mi][ni][c] = 0.f;

    #pragma unroll
    for (int ky = 0; ky < 3; ky++) {
        #pragma unroll
        for (int kx = 0; kx < 3; kx++) {
            int s = ky * 3 + kx;
            int soff = (ky * 9 + kx) * 36;
            #pragma unroll
            for (int kk = 0; kk < 4; kk++) {
                int kb = kk * 8;
                unsigned ah[2][4], al[2][4];
                #pragma unroll
                for (int mi = 0; mi < 2; mi++) {
                    split_tf32(xin[rb[mi][0] + soff + kb + tig],     ah[mi][0], al[mi][0]);
                    split_tf32(xin[rb[mi][1] + soff + kb + tig],     ah[mi][1], al[mi][1]);
                    split_tf32(xin[rb[mi][0] + soff + kb + tig + 4], ah[mi][2], al[mi][2]);
                    split_tf32(xin[rb[mi][1] + soff + kb + tig + 4], ah[mi][3], al[mi][3]);
                }
                #pragma unroll
                for (int ni = 0; ni < 4; ni++) {
                    int oct = nh * 4 + ni;
                    float2 bw = __ldg(wf + (size_t)s * 1024 + kk * 256 + oct * 32 + lane);
                    unsigned bh0, bl0, bh1, bl1;
                    split_tf32(bw.x, bh0, bl0);
                    split_tf32(bw.y, bh1, bl1);
                    mma3(acc[0][ni], ah[0], al[0], bh0, bh1, bl0, bl1);
                    mma3(acc[1][ni], ah[1], al[1], bh0, bh1, bl0, bl1);
                }
            }
        }
    }

    #pragma unroll
    for (int mi = 0; mi < 2; mi++) {
        int rlo = rbase + mi * 16 + grp, rhi = rlo + 8;
        #pragma unroll
        for (int ni = 0; ni < 4; ni++) {
            int c0 = nh * 32 + ni * 8 + tig * 2;
            rs[rlo * 68 + c0]     = fmaxf(acc[mi][ni][0], 0.f);
            rs[rlo * 68 + c0 + 1] = fmaxf(acc[mi][ni][1], 0.f);
            rs[rhi * 68 + c0]     = fmaxf(acc[mi][ni][2], 0.f);
            rs[rhi * 68 + c0 + 1] = fmaxf(acc[mi][ni][3], 0.f);
        }
    }
    __syncthreads();

    float acc2[2][2][4];
    #pragma unroll
    for (int mi = 0; mi < 2; mi++)
        #pragma unroll
        for (int ni = 0; ni < 2; ni++)
            #pragma unroll
            for (int c = 0; c < 4; c++) acc2[mi][ni][c] = 0.f;

    #pragma unroll
    for (int kk = 0; kk < 8; kk++) {
        int kb = kk * 8;
        unsigned ah[2][4], al[2][4];
        #pragma unroll
        for (int mi = 0; mi < 2; mi++) {
            int rlo = rbase + mi * 16 + grp;
            split_tf32(rs[rlo * 68 + kb + tig],           ah[mi][0], al[mi][0]);
            split_tf32(rs[(rlo + 8) * 68 + kb + tig],     ah[mi][1], al[mi][1]);
            split_tf32(rs[rlo * 68 + kb + tig + 4],       ah[mi][2], al[mi][2]);
            split_tf32(rs[(rlo + 8) * 68 + kb + tig + 4], ah[mi][3], al[mi][3]);
        }
        #pragma unroll
        for (int ni = 0; ni < 2; ni++) {
            int c = nh * 16 + ni * 8 + grp;
            unsigned bh0, bl0, bh1, bl1;
            split_tf32(w2s[(kb + tig) * 36 + c],     bh0, bl0);
            split_tf32(w2s[(kb + tig + 4) * 36 + c], bh1, bl1);
            mma3(acc2[0][ni], ah[0], al[0], bh0, bh1, bl0, bl1);
            mma3(acc2[1][ni], ah[1], al[1], bh0, bh1, bl0, bl1);
        }
    }

    #pragma unroll
    for (int mi = 0; mi < 2; mi++) {
        #pragma unroll
        for (int ni = 0; ni < 2; ni++) {
            #pragma unroll
            for (int ci = 0; ci < 4; ci++) {
                int p = mh * 32 + mi * 16 + grp + ((ci >= 2) ? 8 : 0);
                if (p < 49) {
                    int ch = nh * 16 + ni * 8 + tig * 2 + (ci & 1);
                    size_t g = (size_t)(b0 + img) * 1568 + ch * 49 + p;
                    float v = acc2[mi][ni][ci] + __ldg(buf + g);
                    buf[g] = fmaxf(v, 0.f);
                }
            }
        }
    }
}

// ======================================================================
// res stack single-TF32 (decoder)                      [round-10 proven]
// ======================================================================
#define D3_RS   5346
#define D3_W2   14050
#define D3_TOT  16354
#define D3_SMEM (D3_TOT * 4)

__global__ void __launch_bounds__(256) res_tcd(
        float* __restrict__ buf,
        const float2* __restrict__ wf,
        const float* __restrict__ pw2) {
    extern __shared__ float sm[];
    float* xin = sm;
    float* rs  = sm + D3_RS;
    float* w2s = sm + D3_W2;
    int t = threadIdx.x;
    int b0 = blockIdx.x * 2;

    for (int i = t; i < D3_RS; i += 256) xin[i] = 0.f;
    __syncthreads();
    for (int i = t; i < 2048; i += 256) {
        int oc = i >> 6, ic = i & 63;
        w2s[ic * 36 + oc] = to_tf32(pw2[i]);
    }
    for (int i = t; i < 2 * 1568; i += 256) {
        int img = i / 1568, j = i % 1568;
        int ch = j / 49, p = j % 49;
        float v = buf[(size_t)(b0 + img) * 1568 + j];
        xin[img * 2673 + ((p / 7 + 1) * 9 + (p % 7 + 1)) * 33 + ch] =
            to_tf32(fmaxf(v, 0.f));
    }
    __syncthreads();

    int lane = t & 31, wrp = t >> 5;
    int grp = lane >> 2, tig = lane & 3;
    int img = wrp >> 2, mh = (wrp >> 1) & 1, nh = wrp & 1;
    int rbase = img * 64 + mh * 32;

    int rb[2][2];
    #pragma unroll
    for (int mi = 0; mi < 2; mi++)
        #pragma unroll
        for (int h = 0; h < 2; h++) {
            int p = mh * 32 + mi * 16 + grp + h * 8;
            rb[mi][h] = (p < 49) ? img * 2673 + ((p / 7) * 9 + (p % 7)) * 33 : 0;
        }

    float acc[2][4][4];
    #pragma unroll
    for (int mi = 0; mi < 2; mi++)
        #pragma unroll
        for (int ni = 0; ni < 4; ni++)
            #pragma unroll
            for (int c = 0; c < 4; c++) acc[mi][ni][c] = 0.f;

    #pragma unroll
    for (int ky = 0; ky < 3; ky++) {
        #pragma unroll
        for (int kx = 0; kx < 3; kx++) {
            int s = ky * 3 + kx;
            int soff = (ky * 9 + kx) * 33;
            #pragma unroll
            for (int kk = 0; kk < 4; kk++) {
                int kb = kk * 8;
                unsigned a[2][4];
                #pragma unroll
                for (int mi = 0; mi < 2; mi++) {
                    a[mi][0] = __float_as_uint(xin[rb[mi][0] + soff + kb + tig]);
                    a[mi][1] = __float_as_uint(xin[rb[mi][1] + soff + kb + tig]);
                    a[mi][2] = __float_as_uint(xin[rb[mi][0] + soff + kb + tig + 4]);
                    a[mi][3] = __float_as_uint(xin[rb[mi][1] + soff + kb + tig + 4]);
                }
                #pragma unroll
                for (int ni = 0; ni < 4; ni++) {
                    int oct = nh * 4 + ni;
                    float2 bw = __ldg(wf + (size_t)s * 1024 + kk * 256 + oct * 32 + lane);
                    unsigned bb0 = __float_as_uint(bw.x);
                    unsigned bb1 = __float_as_uint(bw.y);
                    mma_tf32(acc[0][ni], a[0], bb0, bb1);
                    mma_tf32(acc[1][ni], a[1], bb0, bb1);
                }
            }
        }
    }

    #pragma unroll
    for (int mi = 0; mi < 2; mi++) {
        int rlo = rbase + mi * 16 + grp, rhi = rlo + 8;
        #pragma unroll
        for (int ni = 0; ni < 4; ni++) {
            int c0 = nh * 32 + ni * 8 + tig * 2;
            rs[rlo * 68 + c0]     = to_tf32(fmaxf(acc[mi][ni][0], 0.f));
            rs[rlo * 68 + c0 + 1] = to_tf32(fmaxf(acc[mi][ni][1], 0.f));
            rs[rhi * 68 + c0]     = to_tf32(fmaxf(acc[mi][ni][2], 0.f));
            rs[rhi * 68 + c0 + 1] = to_tf32(fmaxf(acc[mi][ni][3], 0.f));
        }
    }
    __syncthreads();

    float acc2[2][2][4];
    #pragma unroll
    for (int mi = 0; mi < 2; mi++)
        #pragma unroll
        for (int ni = 0; ni < 2; ni++)
            #pragma unroll
            for (int c = 0; c < 4; c++) acc2[mi][ni][c] = 0.f;

    #pragma unroll
    for (int kk = 0; kk < 8; kk++) {
        int kb = kk * 8;
        unsigned a[2][4];
        #pragma unroll
        for (int mi = 0; mi < 2; mi++) {
            int rlo = rbase + mi * 16 + grp;
            a[mi][0] = __float_as_uint(rs[rlo * 68 + kb + tig]);
            a[mi][1] = __float_as_uint(rs[(rlo + 8) * 68 + kb + tig]);
            a[mi][2] = __float_as_uint(rs[rlo * 68 + kb + tig + 4]);
            a[mi][3] = __float_as_uint(rs[(rlo + 8) * 68 + kb + tig + 4]);
        }
        #pragma unroll
        for (int ni = 0; ni < 2; ni++) {
            int c = nh * 16 + ni * 8 + grp;
            unsigned bb0 = __float_as_uint(w2s[(kb + tig) * 36 + c]);
            unsigned bb1 = __float_as_uint(w2s[(kb + tig + 4) * 36 + c]);
            mma_tf32(acc2[0][ni], a[0], bb0, bb1);
            mma_tf32(acc2[1][ni], a[1], bb0, bb1);
        }
    }

    #pragma unroll
    for (int mi = 0; mi < 2; mi++) {
        #pragma unroll
        for (int ni = 0; ni < 2; ni++) {
            #pragma unroll
            for (int ci = 0; ci < 4; ci++) {
                int p = mh * 32 + mi * 16 + grp + ((ci >= 2) ? 8 : 0);
                if (p < 49) {
                    int ch = nh * 16 + ni * 8 + tig * 2 + (ci & 1);
                    size_t g = (size_t)(b0 + img) * 1568 + ch * 49 + p;
                    float v = acc2[mi][ni][ci] + __ldg(buf + g);
                    buf[g] = fmaxf(v, 0.f);
                }
            }
        }
    }
}

// ======================================================================
// TF32 GEMM (decoder fc4): double-buffered smem        [round-13]
// ======================================================================
__global__ void __launch_bounds__(256) gemm_tc(
        const float* __restrict__ A,
        const float* __restrict__ W,
        const float* __restrict__ bias,
        float* __restrict__ C,
        int M, int N, int K) {
    __shared__ float As[2][128][17];
    __shared__ float Ws[2][64][17];
    int t = threadIdx.x, lane = t & 31, w = t >> 5;
    int grp = lane >> 2, tig = lane & 3;
    int m0 = blockIdx.x * 128, n0 = blockIdx.y * 64;
    int mw = (w & 3) * 32, nw = (w >> 2) * 32;
    float acc[2][4][4];
    #pragma unroll
    for (int mi = 0; mi < 2; mi++)
        #pragma unroll
        for (int ni = 0; ni < 4; ni++)
            #pragma unroll
            for (int c = 0; c < 4; c++) acc[mi][ni][c] = 0.f;

    int ar = t >> 1, ak = (t & 1) * 8;
    int wr = t >> 2, wk = (t & 3) * 4;
    const float* apb = A + (size_t)(m0 + ar) * K + ak;
    bool wval = (n0 + wr < N);
    const float* wpb = W + (size_t)(n0 + wr) * K + wk;

    float4 v0 = *(const float4*)apb;
    float4 v1 = *(const float4*)(apb + 4);
    float4 wv = wval ? *(const float4*)wpb : make_float4(0.f, 0.f, 0.f, 0.f);
    int s = 0;
    As[0][ar][ak + 0] = to_tf32(v0.x); As[0][ar][ak + 1] = to_tf32(v0.y);
    As[0][ar][ak + 2] = to_tf32(v0.z); As[0][ar][ak + 3] = to_tf32(v0.w);
    As[0][ar][ak + 4] = to_tf32(v1.x); As[0][ar][ak + 5] = to_tf32(v1.y);
    As[0][ar][ak + 6] = to_tf32(v1.z); As[0][ar][ak + 7] = to_tf32(v1.w);
    Ws[0][wr][wk + 0] = to_tf32(wv.x); Ws[0][wr][wk + 1] = to_tf32(wv.y);
    Ws[0][wr][wk + 2] = to_tf32(wv.z); Ws[0][wr][wk + 3] = to_tf32(wv.w);
    __syncthreads();

    for (int k0 = 0; k0 < K; k0 += 16) {
        bool more = (k0 + 16 < K);
        if (more) {
            v0 = *(const float4*)(apb + k0 + 16);
            v1 = *(const float4*)(apb + k0 + 20);
            wv = wval ? *(const float4*)(wpb + k0 + 16)
                      : make_float4(0.f, 0.f, 0.f, 0.f);
        }
        #pragma unroll
        for (int kk = 0; kk < 2; kk++) {
            int kb = kk * 8;
            unsigned a[2][4];
            #pragma unroll
            for (int mi = 0; mi < 2; mi++) {
                int r = mw + mi * 16 + grp;
                a[mi][0] = __float_as_uint(As[s][r][kb + tig]);
                a[mi][1] = __float_as_uint(As[s][r + 8][kb + tig]);
                a[mi][2] = __float_as_uint(As[s][r][kb + tig + 4]);
                a[mi][3] = __float_as_uint(As[s][r + 8][kb + tig + 4]);
            }
            #pragma unroll
            for (int ni = 0; ni < 4; ni++) {
                int n = nw + ni * 8 + grp;
                unsigned bb0 = __float_as_uint(Ws[s][n][kb + tig]);
                unsigned bb1 = __float_as_uint(Ws[s][n][kb + tig + 4]);
                mma_tf32(acc[0][ni], a[0], bb0, bb1);
                mma_tf32(acc[1][ni], a[1], bb0, bb1);
            }
        }
        if (more) {
            int d = s ^ 1;
            As[d][ar][ak + 0] = to_tf32(v0.x); As[d][ar][ak + 1] = to_tf32(v0.y);
            As[d][ar][ak + 2] = to_tf32(v0.z); As[d][ar][ak + 3] = to_tf32(v0.w);
            As[d][ar][ak + 4] = to_tf32(v1.x); As[d][ar][ak + 5] = to_tf32(v1.y);
            As[d][ar][ak + 6] = to_tf32(v1.z); As[d][ar][ak + 7] = to_tf32(v1.w);
            Ws[d][wr][wk + 0] = to_tf32(wv.x); Ws[d][wr][wk + 1] = to_tf32(wv.y);
            Ws[d][wr][wk + 2] = to_tf32(wv.z); Ws[d][wr][wk + 3] = to_tf32(wv.w);
            __syncthreads();
            s = d;
        }
    }
    #pragma unroll
    for (int mi = 0; mi < 2; mi++) {
        #pragma unroll
        for (int ni = 0; ni < 4; ni++) {
            #pragma unroll
            for (int ci = 0; ci < 4; ci++) {
                int r = m0 + mw + mi * 16 + grp + ((ci >= 2) ? 8 : 0);
                int n = n0 + nw + ni * 8 + tig * 2 + (ci & 1);
                if (n < N)
                    C[(size_t)r * N + n] = fmaxf(acc[mi][ni][ci] + bias[n], 0.f);
            }
        }
    }
}

// ======================================================================
// 3xTF32 GEMM (encoder fc1): double-buffered smem      [round-13]
// ======================================================================
__global__ void __launch_bounds__(256) gemm_tc3(
        const float* __restrict__ A,
        const float* __restrict__ W,
        const float* __restrict__ bias,
        float* __restrict__ C,
        int M, int N, int K) {
    __shared__ float As[2][128][17];
    __shared__ float Ws[2][64][17];
    int t = threadIdx.x, lane = t & 31, w = t >> 5;
    int grp = lane >> 2, tig = lane & 3;
    int m0 = blockIdx.x * 128, n0 = blockIdx.y * 64;
    int mw = (w & 3) * 32, nw = (w >> 2) * 32;
    float acc[2][4][4];
    #pragma unroll
    for (int mi = 0; mi < 2; mi++)
        #pragma unroll
        for (int ni = 0; ni < 4; ni++)
            #pragma unroll
            for (int c = 0; c < 4; c++) acc[mi][ni][c] = 0.f;

    int ar = t >> 1, ak = (t & 1) * 8;
    int wr = t >> 2, wk = (t & 3) * 4;
    const float* apb = A + (size_t)(m0 + ar) * K + ak;
    bool wval = (n0 + wr < N);
    const float* wpb = W + (size_t)(n0 + wr) * K + wk;

    float4 v0 = *(const float4*)apb;
    float4 v1 = *(const float4*)(apb + 4);
    float4 wv = wval ? *(const float4*)wpb : make_float4(0.f, 0.f, 0.f, 0.f);
    int s = 0;
    As[0][ar][ak + 0] = v0.x; As[0][ar][ak + 1] = v0.y;
    As[0][ar][ak + 2] = v0.z; As[0][ar][ak + 3] = v0.w;
    As[0][ar][ak + 4] = v1.x; As[0][ar][ak + 5] = v1.y;
    As[0][ar][ak + 6] = v1.z; As[0][ar][ak + 7] = v1.w;
    Ws[0][wr][wk + 0] = wv.x; Ws[0][wr][wk + 1] = wv.y;
    Ws[0][wr][wk + 2] = wv.z; Ws[0][wr][wk + 3] = wv.w;
    __syncthreads();

    for (int k0 = 0; k0 < K; k0 += 16) {
        bool more = (k0 + 16 < K);
        if (more) {
            v0 = *(const float4*)(apb + k0 + 16);
            v1 = *(const float4*)(apb + k0 + 20);
            wv = wval ? *(const float4*)(wpb + k0 + 16)
                      : make_float4(0.f, 0.f, 0.f, 0.f);
        }
        #pragma unroll
        for (int kk = 0; kk < 2; kk++) {
            int kb = kk * 8;
            unsigned ah[2][4], al[2][4];
            #pragma unroll
            for (int mi = 0; mi < 2; mi++) {
                int r = mw + mi * 16 + grp;
                split_tf32(As[s][r][kb + tig],         ah[mi][0], al[mi][0]);
                split_tf32(As[s][r + 8][kb + tig],     ah[mi][1], al[mi][1]);
                split_tf32(As[s][r][kb + tig + 4],     ah[mi][2], al[mi][2]);
                split_tf32(As[s][r + 8][kb + tig + 4], ah[mi][3], al[mi][3]);
            }
            #pragma unroll
            for (int ni = 0; ni < 4; ni++) {
                int n = nw + ni * 8 + grp;
                unsigned bh0, bl0, bh1, bl1;
                split_tf32(Ws[s][n][kb + tig],     bh0, bl0);
                split_tf32(Ws[s][n][kb + tig + 4], bh1, bl1);
                mma3(acc[0][ni], ah[0], al[0], bh0, bh1, bl0, bl1);
                mma3(acc[1][ni], ah[1], al[1], bh0, bh1, bl0, bl1);
            }
        }
        if (more) {
            int d = s ^ 1;
            As[d][ar][ak + 0] = v0.x; As[d][ar][ak + 1] = v0.y;
            As[d][ar][ak + 2] = v0.z; As[d][ar][ak + 3] = v0.w;
            As[d][ar][ak + 4] = v1.x; As[d][ar][ak + 5] = v1.y;
            As[d][ar][ak + 6] = v1.z; As[d][ar][ak + 7] = v1.w;
            Ws[d][wr][wk + 0] = wv.x; Ws[d][wr][wk + 1] = wv.y;
            Ws[d][wr][wk + 2] = wv.z; Ws[d][wr][wk + 3] = wv.w;
            __syncthreads();
            s = d;
        }
    }
    #pragma unroll
    for (int mi = 0; mi < 2; mi++) {
        #pragma unroll
        for (int ni = 0; ni < 4; ni++) {
            #pragma unroll
            for (int ci = 0; ci < 4; ci++) {
                int r = m0 + mw + mi * 16 + grp + ((ci >= 2) ? 8 : 0);
                int n = n0 + nw + ni * 8 + tig * 2 + (ci & 1);
                if (n < N)
                    C[(size_t)r * N + n] = fmaxf(acc[mi][ni][ci] + bias[n], 0.f);
            }
        }
    }
}

// ======================================================================
// convt2 inner body (compile-time tap tables)          [round-7 proven]
// ======================================================================
template<int DY0, int KY0, int DY1, int KY1,
         int DX0, int KX0, int DX1, int KX1>
__device__ __forceinline__ void ct2_body(
        const float* __restrict__ base, const float* __restrict__ w,
        float bv, float* __restrict__ outp, int m) {
    float acc[14];
    #pragma unroll
    for (int j = 0; j < 14; j++) acc[j] = bv;
    for (int ic = 0; ic < 16; ic++) {
        const float* xc = base + ic * 256;
        #pragma unroll
        for (int sy = 0; sy < 2; sy++) {
            int iy = m + (sy ? DY1 : DY0);
            float row[16];
            #pragma unroll
            for (int j = 0; j < 16; j++) row[j] = xc[(iy + 1) * 16 + j];
            {
                float wv = __ldg(w + ic * 16 + (sy ? KY1 : KY0) * 4 + KX0);
                #pragma unroll
                for (int n = 0; n < 14; n++) acc[n] += row[n + DX0 + 1] * wv;
            }
            {
                float wv = __ldg(w + ic * 16 + (sy ? KY1 : KY0) * 4 + KX1);
                #pragma unroll
                for (int n = 0; n < 14; n++) acc[n] += row[n + DX1 + 1] * wv;
            }
        }
    }
    #pragma unroll
    for (int n = 0; n < 14; n++) outp[2 * n] = acc[n];
}

// ======================================================================
// FUSED convt1+convt2 (decoder)                        [round-12 proven]
// ======================================================================
#define T12_IMSZ 2916
#define T12_ZB   6240
#define T12_XIN  6664
#define T12_W    T12_XIN
#define T12_HP   (T12_W + 16 * 32 * 24)
#define T12_TOT  (T12_HP + 2 * 4096)
#define T12_SMEM (T12_TOT * 4)

__global__ void __launch_bounds__(256) convt12_tc(
        const float* __restrict__ in,
        const float* __restrict__ w,
        const float* __restrict__ bias,
        const float* __restrict__ c2w,
        const float* __restrict__ c2b,
        float* __restrict__ out) {
    extern __shared__ float sm[];
    float* xin = sm;
    float* wt  = sm + T12_W;
    float* hp  = sm + T12_HP;
    int t = threadIdx.x;
    int b0 = blockIdx.x * 2;

    for (int i = t; i < T12_XIN; i += 256) xin[i] = 0.f;
    for (int i = t; i < 8192; i += 256) hp[i] = 0.f;
    __syncthreads();
    for (int i = t; i < 2 * 1568; i += 256) {
        int img = i / 1568, j = i % 1568;
        int ic = j / 49, p = j % 49, iy = p / 7, ix = p % 7;
        xin[img * T12_IMSZ + ((iy + 1) * 9 + (ix + 1)) * 36 + ic] =
            to_tf32(in[(size_t)(b0 + img) * 1568 + j]);
    }
    for (int i = t; i < 32 * 256; i += 256) {
        int ic = i / 256, r = i % 256, oc = r / 16, s = r % 16;
        wt[s * 768 + ic * 24 + oc] = to_tf32(w[i]);
    }
    __syncthreads();

    int lane = t & 31, wrp = t >> 5;
    int grp = lane >> 2, tig = lane & 3;
    int img = wrp >> 2, ph = wrp & 3;
    int a = ph >> 1, bp = ph & 1;
    int dyv[2], kyv[2], dxv[2], kxv[2];
    if (a == 0) { dyv[0] = 0; kyv[0] = 1; dyv[1] = -1; kyv[1] = 3; }
    else        { dyv[0] = 1; kyv[0] = 0; dyv[1] =  0; kyv[1] = 2; }
    if (bp == 0) { dxv[0] = 0; kxv[0] = 1; dxv[1] = -1; kxv[1] = 3; }
    else         { dxv[0] = 1; kxv[0] = 0; dxv[1] =  0; kxv[1] = 2; }

    int rb[4][2];
    #pragma unroll
    for (int mi = 0; mi < 4; mi++)
        #pragma unroll
        for (int h = 0; h < 2; h++) {
            int p = mi * 16 + grp + h * 8;
            rb[mi][h] = (p < 49)
                ? img * T12_IMSZ + ((p / 7 + 1) * 9 + (p % 7 + 1)) * 36
                : T12_ZB;
        }

    float acc[4][2][4];
    #pragma unroll
    for (int mi = 0; mi < 4; mi++)
        #pragma unroll
        for (int ni = 0; ni < 2; ni++)
            #pragma unroll
            for (int c = 0; c < 4; c++) acc[mi][ni][c] = 0.f;

    #pragma unroll
    for (int sy = 0; sy < 2; sy++) {
        #pragma unroll
        for (int sx = 0; sx < 2; sx++) {
            int soff = (dyv[sy] * 9 + dxv[sx]) * 36;
            const float* wsl = wt + (kyv[sy] * 4 + kxv[sx]) * 768;
            #pragma unroll
            for (int kk = 0; kk < 4; kk++) {
                int kb = kk * 8;
                unsigned afr[4][4];
                #pragma unroll
                for (int mi = 0; mi < 4; mi++) {
                    afr[mi][0] = __float_as_uint(xin[rb[mi][0] + soff + kb + tig]);
                    afr[mi][1] = __float_as_uint(xin[rb[mi][1] + soff + kb + tig]);
                    afr[mi][2] = __float_as_uint(xin[rb[mi][0] + soff + kb + tig + 4]);
                    afr[mi][3] = __float_as_uint(xin[rb[mi][1] + soff + kb + tig + 4]);
                }
                #pragma unroll
                for (int ni = 0; ni < 2; ni++) {
                    unsigned bb0 = __float_as_uint(wsl[(kb + tig) * 24 + ni * 8 + grp]);
                    unsigned bb1 = __float_as_uint(wsl[(kb + tig + 4) * 24 + ni * 8 + grp]);
                    #pragma unroll
                    for (int mi = 0; mi < 4; mi++)
                        mma_tf32(acc[mi][ni], afr[mi], bb0, bb1);
                }
            }
        }
    }

    #pragma unroll
    for (int mi = 0; mi < 4; mi++) {
        #pragma unroll
        for (int ni = 0; ni < 2; ni++) {
            #pragma unroll
            for (int ci = 0; ci < 4; ci++) {
                int p = mi * 16 + grp + ((ci >= 2) ? 8 : 0);
                if (p < 49) {
                    int m = p / 7, n = p % 7;
                    int oc = ni * 8 + tig * 2 + (ci & 1);
                    int oy = 2 * m + a, ox = 2 * n + bp;
                    float v = acc[mi][ni][ci] + __ldg(bias + oc);
                    hp[img * 4096 + oc * 256 + (oy + 1) * 16 + (ox + 1)] =
                        fmaxf(v, 0.f);
                }
            }
        }
    }
    __syncthreads();

    if (t < 112) {
        int ph2 = t / 28, r2 = t % 28;
        int img2 = r2 / 14, m2 = r2 % 14;
        int a2 = ph2 >> 1, b2 = ph2 & 1;
        const float* base2 = hp + img2 * 4096;
        float bv2 = c2b[0];
        float* outp = out + (size_t)(b0 + img2) * 784 + (2 * m2 + a2) * 28 + b2;
        if (ph2 == 0)      ct2_body<0, 1, -1, 3,  0, 1, -1, 3>(base2, c2w, bv2, outp, m2);
        else if (ph2 == 1) ct2_body<0, 1, -1, 3,  1, 0,  0, 2>(base2, c2w, bv2, outp, m2);
        else if (ph2 == 2) ct2_body<1, 0,  0, 2,  0, 1, -1, 3>(base2, c2w, bv2, outp, m2);
        else               ct2_body<1, 0,  0, 2,  1, 0,  0, 2>(base2, c2w, bv2, outp, m2);
    }
}

// ======================================================================
// fc2: z[B,32] = A[B,224] @ w^T + b  (fp32, feeds VQ)   [round-8]
// ======================================================================
__global__ void __launch_bounds__(256) fc2_kernel(
        const float* __restrict__ A,
        const float* __restrict__ w,
        const float* __restrict__ bias,
        float* __restrict__ out) {
    __shared__ float ws[32 * 224];
    int t = threadIdx.x;
    for (int i = t; i < 7168; i += 256) ws[i] = w[i];
    __syncthreads();
    int n = t & 31, r = t >> 5;
    float bv = bias[n];
    const float* wp = ws + n * 224;
    #pragma unroll
    for (int rr = 0; rr < 4; rr++) {
        int b = blockIdx.x * 32 + rr * 8 + r;
        const float* ap = A + (size_t)b * 224;
        float acc = bv;
        #pragma unroll 8
        for (int k = 0; k < 224; k++) acc += ap[k] * wp[k];
        out[(size_t)b * 32 + n] = acc;
    }
}

// ======================================================================
// VQ helpers (fp32 exact)
// ======================================================================
__global__ void enorm_kernel(const float* __restrict__ emb, float* __restrict__ enorm) {
    int e = blockIdx.x * blockDim.x + threadIdx.x;
    if (e < NE) {
        float s = 0.f;
        #pragma unroll
        for (int d = 0; d < ZD; d++) { float v = emb[e * ZD + d]; s += v * v; }
        enorm[e] = s;
    }
}

__global__ void zero_kernel(float* __restrict__ counts, float* __restrict__ sums,
                            float* __restrict__ loss) {
    int i = blockIdx.x * blockDim.x + threadIdx.x;
    if (i < NE) counts[i] = 0.f;
    if (i < NE * ZD) sums[i] = 0.f;
    if (i == 0) loss[0] = 0.f;
}

#define VQ_SMEM (NE * 36 * 4)

__global__ void __launch_bounds__(256) vq_kernel(
        const float* __restrict__ z,
        const float* __restrict__ emb,
        const float* __restrict__ enorm,
        int* __restrict__ idx,
        float* __restrict__ counts,
        float* __restrict__ sums,
        float* __restrict__ loss) {
    extern __shared__ float es[];          // [512][36]
    __shared__ float en[NE];
    __shared__ float zs[8][ZD];
    int t = threadIdx.x, lane = t & 31, wl = t >> 5;
    for (int i = t; i < NE * ZD; i += 256) {
        int e = i >> 5, d = i & 31;
        es[e * 36 + d] = emb[i];
    }
    for (int i = t; i < NE; i += 256) en[i] = enorm[i];
    __syncthreads();

    for (int rr = 0; rr < 8; rr++) {
        int row = blockIdx.x * 64 + wl * 8 + rr;
        zs[wl][lane] = z[(size_t)row * ZD + lane];
        __syncwarp();
        float best = 3.4e38f; int bi = NE;
        for (int e = lane; e < NE; e += 32) {
            const float* ep = es + e * 36;
            float dot = 0.f;
            #pragma unroll
            for (int d = 0; d < ZD; d += 4) {
                float4 v = *(const float4*)(ep + d);
                dot += zs[wl][d + 0] * v.x;
                dot += zs[wl][d + 1] * v.y;
                dot += zs[wl][d + 2] * v.z;
                dot += zs[wl][d + 3] * v.w;
            }
            float s = en[e] - 2.f * dot;
            if (s < best) { best = s; bi = e; }
        }
        #pragma unroll
        for (int off = 16; off; off >>= 1) {
            float ob = __shfl_xor_sync(0xffffffffu, best, off);
            int   oi = __shfl_xor_sync(0xffffffffu, bi, off);
            if (ob < best || (ob == best && oi < bi)) { best = ob; bi = oi; }
        }
        float zl = zs[wl][lane];
        float diff = es[bi * 36 + lane] - zl;
        float d2 = diff * diff;
        #pragma unroll
        for (int off = 16; off; off >>= 1)
            d2 += __shfl_xor_sync(0xffffffffu, d2, off);
        if (lane == 0) {
            idx[row] = bi;
            atomicAdd(&counts[bi], 1.f);
            atomicAdd(loss, d2);
        }
        atomicAdd(&sums[bi * ZD + lane], zl);
        __syncwarp();
    }
}

__global__ void embnew_kernel(const float* __restrict__ m_mat,
                              const float* __restrict__ n_mat,
                              const float* __restrict__ sums,
                              const float* __restrict__ counts,
                              float* __restrict__ out) {
    int i = blockIdx.x * blockDim.x + threadIdx.x;
    if (i < NE * ZD) {
        int e = i >> 5;
        float m = m_mat[i] * GAMMA + sums[i] * ONE_M_GAMMA;
        float n = n_mat[e] * GAMMA + counts[e] * ONE_M_GAMMA;
        out[i] = m / n;
    }
}

__global__ void finalize_kernel(const float* __restrict__ counts,
                                const float* __restrict__ loss,
                                float* __restrict__ out_scalars) {
    __shared__ float red[NE];
    int t = threadIdx.x;
    float c = counts[t];
    float em = c * (1.f / (float)BATCH);
    red[t] = em * logf(em + 1e-10f);
    __syncthreads();
    for (int s = 256; s; s >>= 1) {
        if (t < s) red[t] += red[t + s];
        __syncthreads();
    }
    if (t == 0) {
        float q = loss[0] * (1.f / ((float)BATCH * (float)ZD));
        out_scalars[0] = q;
        out_scalars[1] = BETA * q;
        out_scalars[2] = expf(-red[0]);
    }
}

// ======================================================================
// fc3 (fp32): 16 images/CTA                           [round-8, proven]
// ======================================================================
__global__ void __launch_bounds__(224) fc3_kernel(
        const float* __restrict__ emb,
        const int* __restrict__ idx,
        const float* __restrict__ w,
        const float* __restrict__ bias,
        float* __restrict__ out) {
    __shared__ float ws[224 * ZD];
    __shared__ float zq[16][ZD + 1];
    int b0 = blockIdx.x * 16, t = threadIdx.x;
    for (int i = t; i < 224 * ZD; i += 224) ws[i] = w[i];
    for (int i = t; i < 16 * ZD; i += 224) {
        int im = i >> 5, d = i & 31;
        zq[im][d] = emb[(size_t)idx[b0 + im] * ZD + d];
    }
    __syncthreads();
    float bv = bias[t];
    float wreg[ZD];
    const float* wp = ws + t * ZD;
    #pragma unroll
    for (int k = 0; k < ZD; k++) wreg[k] = wp[k];
    #pragma unroll 4
    for (int im = 0; im < 16; im++) {
        float acc = bv;
        #pragma unroll
        for (int k = 0; k < ZD; k++) acc += zq[im][k] * wreg[k];
        out[(size_t)(b0 + im) * 224 + t] = fmaxf(acc, 0.f);
    }
}

// ======================================================================
// launch
// ======================================================================
extern "C" void kernel_launch(void* const* d_in, const int* in_sizes, int n_in,
                              void* d_out, int out_size) {
    const float* x        = (const float*)d_in[0];
    const float* conv1_w  = (const float*)d_in[1];
    const float* conv1_b  = (const float*)d_in[2];
    const float* conv2_w  = (const float*)d_in[3];
    const float* conv2_b  = (const float*)d_in[4];
    const float* res1_w1  = (const float*)d_in[5];
    const float* res1_w2  = (const float*)d_in[6];
    const float* fc1_w    = (const float*)d_in[7];
    const float* fc1_b    = (const float*)d_in[8];
    const float* fc2_w    = (const float*)d_in[9];
    const float* fc2_b    = (const float*)d_in[10];
    const float* emb      = (const float*)d_in[11];
    const float* n_mat    = (const float*)d_in[12];
    const float* m_mat    = (const float*)d_in[13];
    const float* fc3_w    = (const float*)d_in[14];
    const float* fc3_b    = (const float*)d_in[15];
    const float* fc4_w    = (const float*)d_in[16];
    const float* fc4_b    = (const float*)d_in[17];
    const float* res2_w1  = (const float*)d_in[18];
    const float* res2_w2  = (const float*)d_in[19];
    const float* convt1_w = (const float*)d_in[20];
    const float* convt1_b = (const float*)d_in[21];
    const float* convt2_w = (const float*)d_in[22];
    const float* convt2_b = (const float*)d_in[23];
    float* out = (float*)d_out;

    float *h2, *a, *z, *enorm, *counts, *sums, *loss;
    int* idx;
    float2 *wf_r1, *wf_r2, *wf_c2;
    cudaGetSymbolAddress((void**)&h2,     g_h2);
    cudaGetSymbolAddress((void**)&a,      g_a);
    cudaGetSymbolAddress((void**)&z,      g_z);
    cudaGetSymbolAddress((void**)&idx,    g_idx);
    cudaGetSymbolAddress((void**)&enorm,  g_enorm);
    cudaGetSymbolAddress((void**)&counts, g_counts);
    cudaGetSymbolAddress((void**)&sums,   g_sums);
    cudaGetSymbolAddress((void**)&loss,   g_loss);
    cudaGetSymbolAddress((void**)&wf_r1,  g_wf_r1);
    cudaGetSymbolAddress((void**)&wf_r2,  g_wf_r2);
    cudaGetSymbolAddress((void**)&wf_c2,  g_wf_c2);

    cudaFuncSetAttribute(conv12_tc3,
                         cudaFuncAttributeMaxDynamicSharedMemorySize, C14_SMEM);
    cudaFuncSetAttribute(res_tc3,
                         cudaFuncAttributeMaxDynamicSharedMemorySize, E3_SMEM);
    cudaFuncSetAttribute(res_tcd,
                         cudaFuncAttributeMaxDynamicSharedMemorySize, D3_SMEM);
    cudaFuncSetAttribute(convt12_tc,
                         cudaFuncAttributeMaxDynamicSharedMemorySize, T12_SMEM);
    cudaFuncSetAttribute(vq_kernel,
                         cudaFuncAttributeMaxDynamicSharedMemorySize, VQ_SMEM);

    // weight repack (fragment-order textures)
    repack_res<<<36, 256>>>(res1_w1, wf_r1, 0);
    repack_res<<<36, 256>>>(res2_w1, wf_r2, 1);
    repack_c2 <<<16, 256>>>(conv2_w, wf_c2);

    // encoder (3xTF32 = fp32-class accuracy; VQ path preserved)
    conv12_tc3<<<BATCH / 4, 512, C14_SMEM>>>(x, conv1_w, conv1_b, wf_c2,
                                             conv2_b, h2);
    res_tc3  <<<BATCH / 2, 256, E3_SMEM>>>(h2, wf_r1, res1_w2);
    gemm_tc3<<<dim3(BATCH / 128, 4), 256>>>(h2, fc1_w, fc1_b, a,
                                            BATCH, 224, 1568);
    fc2_kernel<<<BATCH / 32, 256>>>(a, fc2_w, fc2_b, z);

    // VQ
    zero_kernel <<<(NE * ZD + 255) / 256, 256>>>(counts, sums, loss);
    enorm_kernel<<<2, 256>>>(emb, enorm);
    vq_kernel   <<<BATCH / 64, 256, VQ_SMEM>>>(z, emb, enorm, idx, counts,
                                               sums, loss);
    embnew_kernel  <<<(NE * ZD + 255) / 256, 256>>>(m_mat, n_mat, sums, counts,
                                                    out + OFF_SCAL + 3);
    finalize_kernel<<<1, NE>>>(counts, loss, out + OFF_SCAL);

    // decoder (single tf32)
    fc3_kernel<<<BATCH / 16, 224>>>(emb, idx, fc3_w, fc3_b, a);
    gemm_tc<<<dim3(BATCH / 128, 25), 256>>>(a, fc4_w, fc4_b, h2,
                                            BATCH, 1568, 224);
    res_tcd<<<BATCH / 2, 256, D3_SMEM>>>(h2, wf_r2, res2_w2);
    convt12_tc<<<BATCH / 2, 256, T12_SMEM>>>(h2, convt1_w, convt1_b,
                                             convt2_w, convt2_b, out);
}

// round 16
// speedup vs baseline: 1.0285x; 1.0006x over previous
#include <cuda_runtime.h>
#include <cstdint>
#include <math.h>

// ---------------- problem constants ----------------
#define BATCH 16384
#define ZD 32
#define NE 512
#define GAMMA 0.99f
#define ONE_M_GAMMA 0.01f
#define BETA 1.0f

#define OFF_SCAL (BATCH * 784)   // x_rec size
// d_out layout: [x_rec (B*784)][quant][commit][perplexity][emb_new (512*32)]

// ---------------- scratch ----------------
__device__ float g_h2[BATCH * 32 * 7 * 7];
__device__ float g_a [BATCH * 224];
__device__ float g_z [BATCH * ZD];
__device__ int   g_idx[BATCH];
__device__ float g_enorm[NE];
__device__ float g_counts[NE];
__device__ float g_sums[NE * ZD];
__device__ float g_loss[1];
// fragment-order weight textures: [s][kk][oct][lane] -> (b0,b1)
__device__ float2 g_wf_r1[9216];   // res1 w1 (raw fp32)
__device__ float2 g_wf_r2[9216];   // res2 w1 (tf32)
__device__ float2 g_wf_c2[4096];   // conv2 w  (raw fp32)

// ---------------- tf32 mma helpers ----------------
__device__ __forceinline__ float to_tf32(float x) {
    float y;
    asm("cvt.rna.tf32.f32 %0, %1;" : "=f"(y) : "f"(x));
    return y;
}

// Bitwise hi/lo split: hi = RZ-truncated tf32 (LOP3), lo = v - hi (exact FADD).
__device__ __forceinline__ void split_tf32(float v, unsigned& hi, unsigned& lo) {
    unsigned h = __float_as_uint(v) & 0xffffe000u;
    hi = h;
    lo = __float_as_uint(v - __uint_as_float(h));
}

__device__ __forceinline__ void mma_tf32(float* d, const unsigned* a,
                                         unsigned b0, unsigned b1) {
    asm volatile(
        "mma.sync.aligned.m16n8k8.row.col.f32.tf32.tf32.f32 "
        "{%0,%1,%2,%3}, {%4,%5,%6,%7}, {%8,%9}, {%0,%1,%2,%3};\n"
        : "+f"(d[0]), "+f"(d[1]), "+f"(d[2]), "+f"(d[3])
        : "r"(a[0]), "r"(a[1]), "r"(a[2]), "r"(a[3]), "r"(b0), "r"(b1));
}

// 3-pass split mma: acc += a*b with ~fp32 accuracy
__device__ __forceinline__ void mma3(float* d, const unsigned* ah, const unsigned* al,
                                     unsigned bh0, unsigned bh1,
                                     unsigned bl0, unsigned bl1) {
    mma_tf32(d, ah, bl0, bl1);
    mma_tf32(d, al, bh0, bh1);
    mma_tf32(d, ah, bh0, bh1);
}

// ======================================================================
// weight repack kernels (run once per launch; tiny)
// ======================================================================
__global__ void repack_res(const float* __restrict__ w1,
                           float2* __restrict__ out, int cvt) {
    int i = blockIdx.x * 256 + threadIdx.x;
    if (i >= 9216) return;
    int lane = i & 31, oct = (i >> 5) & 7, kk = (i >> 8) & 3, s = i >> 10;
    int grp = lane >> 2, tig = lane & 3;
    int oc = oct * 8 + grp, ic = kk * 8 + tig;
    float b0 = w1[oc * 288 + ic * 9 + s];
    float b1 = w1[oc * 288 + (ic + 4) * 9 + s];
    if (cvt) { b0 = to_tf32(b0); b1 = to_tf32(b1); }
    out[i] = make_float2(b0, b1);
}

__global__ void repack_c2(const float* __restrict__ w,
                          float2* __restrict__ out) {
    int i = blockIdx.x * 256 + threadIdx.x;
    if (i >= 4096) return;
    int lane = i & 31, oct = (i >> 5) & 3, kk = (i >> 7) & 1, s = i >> 8;
    int grp = lane >> 2, tig = lane & 3;
    int oc = oct * 8 + grp, ic = kk * 8 + tig;
    out[i] = make_float2(w[oc * 256 + ic * 16 + s],
                         w[oc * 256 + (ic + 4) * 16 + s]);
}

// ======================================================================
// FUSED conv1+conv2 (encoder): PACKED 5 img/CTA, 512 thr.
// 245 real output rows packed into one 256-row M-tile (95.7% util vs
// 76.6% padded) -> 23% fewer mma. Warp = 16 rows, all 4 oc-octets.
// Bit-identical math; dead rows clamp rb to 0 and are discarded.
// ======================================================================
#define C15_XIN  23040                   // 5 * 4608
#define C15_XP   C15_XIN                 // x padded: 5 * 900 = 4500
#define C15_W1   (C15_XP + 4500)         // 27540
#define C15_B1   (C15_W1 + 256)          // 27796
#define C15_TOT  27812
#define C15_SMEM (C15_TOT * 4)           // 111248 B -> 2 CTA/SM (32 warps)

__global__ void __launch_bounds__(512) conv12_tc3(
        const float* __restrict__ x,
        const float* __restrict__ c1wg,
        const float* __restrict__ c1bg,
        const float2* __restrict__ wf,
        const float* __restrict__ bias,
        float* __restrict__ out) {
    extern __shared__ float sm[];
    float* xin = sm;
    float* xp  = sm + C15_XP;
    float* c1w = sm + C15_W1;
    float* c1b = sm + C15_B1;
    int t = threadIdx.x;
    int b0 = blockIdx.x * 5;
    int nimg = BATCH - b0; if (nimg > 5) nimg = 5;

    for (int i = t; i < C15_XIN; i += 512) xin[i] = 0.f;
    for (int i = t; i < 4500; i += 512) xp[i] = 0.f;
    if (t < 256) c1w[t] = c1wg[t];
    if (t < 16)  c1b[t] = c1bg[t];
    __syncthreads();
    for (int i = t; i < nimg * 784; i += 512) {
        int im = i / 784, j = i % 784;
        int iy = j / 28, ix = j % 28;
        xp[im * 900 + (iy + 1) * 30 + (ix + 1)] = x[(size_t)(b0 + im) * 784 + j];
    }
    __syncthreads();

    // conv1 phase: nimg*196 pixel-tasks, each computes all 16 oc
    for (int pi = t; pi < nimg * 196; pi += 512) {
        int im = pi / 196, pix = pi % 196;
        int oy = pix / 14, ox = pix % 14;
        const float* basep = xp + im * 900 + (2 * oy) * 30 + 2 * ox;
        float patch[16];
        #pragma unroll
        for (int ky = 0; ky < 4; ky++)
            #pragma unroll
            for (int kx = 0; kx < 4; kx++)
                patch[ky * 4 + kx] = basep[ky * 30 + kx];
        float* dst = xin + im * 4608 + ((oy + 1) * 16 + (ox + 1)) * 18;
        #pragma unroll
        for (int oc = 0; oc < 16; oc++) {
            float acc = c1b[oc];
            #pragma unroll
            for (int tap = 0; tap < 16; tap++)
                acc += patch[tap] * c1w[oc * 16 + tap];
            dst[oc] = fmaxf(acc, 0.f);
        }
    }
    __syncthreads();

    // conv2 mma phase: warp w covers packed rows [w*16, w*16+16), 4 octs
    int lane = t & 31, wrp = t >> 5;
    int grp = lane >> 2, tig = lane & 3;
    int r0 = wrp * 16;

    int rb[2];
    #pragma unroll
    for (int h = 0; h < 2; h++) {
        int r = r0 + grp + h * 8;
        if (r < 245) {
            int img = r / 49, p = r % 49;
            rb[h] = img * 4608 + ((p / 7) * 32 + (p % 7) * 2) * 18;
        } else {
            rb[h] = 0;   // safe garbage; discarded at store
        }
    }

    float acc[4][4];
    #pragma unroll
    for (int ni = 0; ni < 4; ni++)
        #pragma unroll
        for (int c = 0; c < 4; c++) acc[ni][c] = 0.f;

    #pragma unroll
    for (int ky = 0; ky < 4; ky++) {
        #pragma unroll
        for (int kx = 0; kx < 4; kx++) {
            int s = ky * 4 + kx;
            int soff = (ky * 16 + kx) * 18;
            #pragma unroll
            for (int kk = 0; kk < 2; kk++) {
                int kb = kk * 8;
                unsigned ah[4], al[4];
                split_tf32(xin[rb[0] + soff + kb + tig],     ah[0], al[0]);
                split_tf32(xin[rb[1] + soff + kb + tig],     ah[1], al[1]);
                split_tf32(xin[rb[0] + soff + kb + tig + 4], ah[2], al[2]);
                split_tf32(xin[rb[1] + soff + kb + tig + 4], ah[3], al[3]);
                #pragma unroll
                for (int ni = 0; ni < 4; ni++) {
                    float2 bw = __ldg(wf + (size_t)s * 256 + kk * 128 + ni * 32 + lane);
                    unsigned bh0, bl0, bh1, bl1;
                    split_tf32(bw.x, bh0, bl0);
                    split_tf32(bw.y, bh1, bl1);
                    mma3(acc[ni], ah, al, bh0, bh1, bl0, bl1);
                }
            }
        }
    }

    #pragma unroll
    for (int ni = 0; ni < 4; ni++) {
        #pragma unroll
        for (int ci = 0; ci < 4; ci++) {
            int r = r0 + grp + ((ci >= 2) ? 8 : 0);
            if (r < 245) {
                int img = r / 49, p = r % 49;
                if (b0 + img < BATCH) {
                    int oc = ni * 8 + tig * 2 + (ci & 1);
                    out[(size_t)(b0 + img) * 1568 + oc * 49 + p] =
                        acc[ni][ci] + __ldg(bias + oc);
                }
            }
        }
    }
}

// ======================================================================
// res stack 3xTF32 (encoder)                           [round-10 proven]
// ======================================================================
#define E3_RS   5832
#define E3_W2   14536
#define E3_TOT  16840
#define E3_SMEM (E3_TOT * 4)

__global__ void __launch_bounds__(256) res_tc3(
        float* __restrict__ buf,
        const float2* __restrict__ wf,
        const float* __restrict__ pw2) {
    extern __shared__ float sm[];
    float* xin = sm;
    float* rs  = sm + E3_RS;
    float* w2s = sm + E3_W2;
    int t = threadIdx.x;
    int b0 = blockIdx.x * 2;

    for (int i = t; i < E3_RS; i += 256) xin[i] = 0.f;
    __syncthreads();
    for (int i = t; i < 2048; i += 256) {
        int oc = i >> 6, ic = i & 63;
        w2s[ic * 36 + oc] = pw2[i];
    }
    for (int i = t; i < 2 * 1568; i += 256) {
        int img = i / 1568, j = i % 1568;
        int ch = j / 49, p = j % 49;
        float v = buf[(size_t)(b0 + img) * 1568 + j];
        xin[img * 2916 + ((p / 7 + 1) * 9 + (p % 7 + 1)) * 36 + ch] = fmaxf(v, 0.f);
    }
    __syncthreads();

    int lane = t & 31, wrp = t >> 5;
    int grp = lane >> 2, tig = lane & 3;
    int img = wrp >> 2, mh = (wrp >> 1) & 1, nh = wrp & 1;
    int rbase = img * 64 + mh * 32;

    int rb[2][2];
    #pragma unroll
    for (int mi = 0; mi < 2; mi++)
        #pragma unroll
        for (int h = 0; h < 2; h++) {
            int p = mh * 32 + mi * 16 + grp + h * 8;
            rb[mi][h] = (p < 49) ? img * 2916 + ((p / 7) * 9 + (p % 7)) * 36 : 0;
        }

    float acc[2][4][4];
    #pragma unroll
    for (int mi = 0; mi < 2; mi++)
        #pragma unroll
        for (int ni = 0; ni < 4; ni++)
            #pragma unroll
            for (int c = 0; c < 4; c++) acc[mi][ni][c] = 0.f;

    #pragma unroll
    for (int ky = 0; ky < 3; ky++) {
        #pragma unroll
        for (int kx = 0; kx < 3; kx++) {
            int s = ky * 3 + kx;
            int soff = (ky * 9 + kx) * 36;
            #pragma unroll
            for (int kk = 0; kk < 4; kk++) {
                int kb = kk * 8;
                unsigned ah[2][4], al[2][4];
                #pragma unroll
                for (int mi = 0; mi < 2; mi++) {
                    split_tf32(xin[rb[mi][0] + soff + kb + tig],     ah[mi][0], al[mi][0]);
                    split_tf32(xin[rb[mi][1] + soff + kb + tig],     ah[mi][1], al[mi][1]);
                    split_tf32(xin[rb[mi][0] + soff + kb + tig + 4], ah[mi][2], al[mi][2]);
                    split_tf32(xin[rb[mi][1] + soff + kb + tig + 4], ah[mi][3], al[mi][3]);
                }
                #pragma unroll
                for (int ni = 0; ni < 4; ni++) {
                    int oct = nh * 4 + ni;
                    float2 bw = __ldg(wf + (size_t)s * 1024 + kk * 256 + oct * 32 + lane);
                    unsigned bh0, bl0, bh1, bl1;
                    split_tf32(bw.x, bh0, bl0);
                    split_tf32(bw.y, bh1, bl1);
                    mma3(acc[0][ni], ah[0], al[0], bh0, bh1, bl0, bl1);
                    mma3(acc[1][ni], ah[1], al[1], bh0, bh1, bl0, bl1);
                }
            }
        }
    }

    #pragma unroll
    for (int mi = 0; mi < 2; mi++) {
        int rlo = rbase + mi * 16 + grp, rhi = rlo + 8;
        #pragma unroll
        for (int ni = 0; ni < 4; ni++) {
            int c0 = nh * 32 + ni * 8 + tig * 2;
            rs[rlo * 68 + c0]     = fmaxf(acc[mi][ni][0], 0.f);
            rs[rlo * 68 + c0 + 1] = fmaxf(acc[mi][ni][1], 0.f);
            rs[rhi * 68 + c0]     = fmaxf(acc[mi][ni][2], 0.f);
            rs[rhi * 68 + c0 + 1] = fmaxf(acc[mi][ni][3], 0.f);
        }
    }
    __syncthreads();

    float acc2[2][2][4];
    #pragma unroll
    for (int mi = 0; mi < 2; mi++)
        #pragma unroll
        for (int ni = 0; ni < 2; ni++)
            #pragma unroll
            for (int c = 0; c < 4; c++) acc2[mi][ni][c] = 0.f;

    #pragma unroll
    for (int kk = 0; kk < 8; kk++) {
        int kb = kk * 8;
        unsigned ah[2][4], al[2][4];
        #pragma unroll
        for (int mi = 0; mi < 2; mi++) {
            int rlo = rbase + mi * 16 + grp;
            split_tf32(rs[rlo * 68 + kb + tig],           ah[mi][0], al[mi][0]);
            split_tf32(rs[(rlo + 8) * 68 + kb + tig],     ah[mi][1], al[mi][1]);
            split_tf32(rs[rlo * 68 + kb + tig + 4],       ah[mi][2], al[mi][2]);
            split_tf32(rs[(rlo + 8) * 68 + kb + tig + 4], ah[mi][3], al[mi][3]);
        }
        #pragma unroll
        for (int ni = 0; ni < 2; ni++) {
            int c = nh * 16 + ni * 8 + grp;
            unsigned bh0, bl0, bh1, bl1;
            split_tf32(w2s[(kb + tig) * 36 + c],     bh0, bl0);
            split_tf32(w2s[(kb + tig + 4) * 36 + c], bh1, bl1);
            mma3(acc2[0][ni], ah[0], al[0], bh0, bh1, bl0, bl1);
            mma3(acc2[1][ni], ah[1], al[1], bh0, bh1, bl0, bl1);
        }
    }

    #pragma unroll
    for (int mi = 0; mi < 2; mi++) {
        #pragma unroll
        for (int ni = 0; ni < 2; ni++) {
            #pragma unroll
            for (int ci = 0; ci < 4; ci++) {
                int p = mh * 32 + mi * 16 + grp + ((ci >= 2) ? 8 : 0);
                if (p < 49) {
                    int ch = nh * 16 + ni * 8 + tig * 2 + (ci & 1);
                    size_t g = (size_t)(b0 + img) * 1568 + ch * 49 + p;
                    float v = acc2[mi][ni][ci] + __ldg(buf + g);
                    buf[g] = fmaxf(v, 0.f);
                }
            }
        }
    }
}

// ======================================================================
// res stack single-TF32 (decoder)                      [round-10 proven]
// ======================================================================
#define D3_RS   5346
#define D3_W2   14050
#define D3_TOT  16354
#define D3_SMEM (D3_TOT * 4)

__global__ void __launch_bounds__(256) res_tcd(
        float* __restrict__ buf,
        const float2* __restrict__ wf,
        const float* __restrict__ pw2) {
    extern __shared__ float sm[];
    float* xin = sm;
    float* rs  = sm + D3_RS;
    float* w2s = sm + D3_W2;
    int t = threadIdx.x;
    int b0 = blockIdx.x * 2;

    for (int i = t; i < D3_RS; i += 256) xin[i] = 0.f;
    __syncthreads();
    for (int i = t; i < 2048; i += 256) {
        int oc = i >> 6, ic = i & 63;
        w2s[ic * 36 + oc] = to_tf32(pw2[i]);
    }
    for (int i = t; i < 2 * 1568; i += 256) {
        int img = i / 1568, j = i % 1568;
        int ch = j / 49, p = j % 49;
        float v = buf[(size_t)(b0 + img) * 1568 + j];
        xin[img * 2673 + ((p / 7 + 1) * 9 + (p % 7 + 1)) * 33 + ch] =
            to_tf32(fmaxf(v, 0.f));
    }
    __syncthreads();

    int lane = t & 31, wrp = t >> 5;
    int grp = lane >> 2, tig = lane & 3;
    int img = wrp >> 2, mh = (wrp >> 1) & 1, nh = wrp & 1;
    int rbase = img * 64 + mh * 32;

    int rb[2][2];
    #pragma unroll
    for (int mi = 0; mi < 2; mi++)
        #pragma unroll
        for (int h = 0; h < 2; h++) {
            int p = mh * 32 + mi * 16 + grp + h * 8;
            rb[mi][h] = (p < 49) ? img * 2673 + ((p / 7) * 9 + (p % 7)) * 33 : 0;
        }

    float acc[2][4][4];
    #pragma unroll
    for (int mi = 0; mi < 2; mi++)
        #pragma unroll
        for (int ni = 0; ni < 4; ni++)
            #pragma unroll
            for (int c = 0; c < 4; c++) acc[mi][ni][c] = 0.f;

    #pragma unroll
    for (int ky = 0; ky < 3; ky++) {
        #pragma unroll
        for (int kx = 0; kx < 3; kx++) {
            int s = ky * 3 + kx;
            int soff = (ky * 9 + kx) * 33;
            #pragma unroll
            for (int kk = 0; kk < 4; kk++) {
                int kb = kk * 8;
                unsigned a[2][4];
                #pragma unroll
                for (int mi = 0; mi < 2; mi++) {
                    a[mi][0] = __float_as_uint(xin[rb[mi][0] + soff + kb + tig]);
                    a[mi][1] = __float_as_uint(xin[rb[mi][1] + soff + kb + tig]);
                    a[mi][2] = __float_as_uint(xin[rb[mi][0] + soff + kb + tig + 4]);
                    a[mi][3] = __float_as_uint(xin[rb[mi][1] + soff + kb + tig + 4]);
                }
                #pragma unroll
                for (int ni = 0; ni < 4; ni++) {
                    int oct = nh * 4 + ni;
                    float2 bw = __ldg(wf + (size_t)s * 1024 + kk * 256 + oct * 32 + lane);
                    unsigned bb0 = __float_as_uint(bw.x);
                    unsigned bb1 = __float_as_uint(bw.y);
                    mma_tf32(acc[0][ni], a[0], bb0, bb1);
                    mma_tf32(acc[1][ni], a[1], bb0, bb1);
                }
            }
        }
    }

    #pragma unroll
    for (int mi = 0; mi < 2; mi++) {
        int rlo = rbase + mi * 16 + grp, rhi = rlo + 8;
        #pragma unroll
        for (int ni = 0; ni < 4; ni++) {
            int c0 = nh * 32 + ni * 8 + tig * 2;
            rs[rlo * 68 + c0]     = to_tf32(fmaxf(acc[mi][ni][0], 0.f));
            rs[rlo * 68 + c0 + 1] = to_tf32(fmaxf(acc[mi][ni][1], 0.f));
            rs[rhi * 68 + c0]     = to_tf32(fmaxf(acc[mi][ni][2], 0.f));
            rs[rhi * 68 + c0 + 1] = to_tf32(fmaxf(acc[mi][ni][3], 0.f));
        }
    }
    __syncthreads();

    float acc2[2][2][4];
    #pragma unroll
    for (int mi = 0; mi < 2; mi++)
        #pragma unroll
        for (int ni = 0; ni < 2; ni++)
            #pragma unroll
            for (int c = 0; c < 4; c++) acc2[mi][ni][c] = 0.f;

    #pragma unroll
    for (int kk = 0; kk < 8; kk++) {
        int kb = kk * 8;
        unsigned a[2][4];
        #pragma unroll
        for (int mi = 0; mi < 2; mi++) {
            int rlo = rbase + mi * 16 + grp;
            a[mi][0] = __float_as_uint(rs[rlo * 68 + kb + tig]);
            a[mi][1] = __float_as_uint(rs[(rlo + 8) * 68 + kb + tig]);
            a[mi][2] = __float_as_uint(rs[rlo * 68 + kb + tig + 4]);
            a[mi][3] = __float_as_uint(rs[(rlo + 8) * 68 + kb + tig + 4]);
        }
        #pragma unroll
        for (int ni = 0; ni < 2; ni++) {
            int c = nh * 16 + ni * 8 + grp;
            unsigned bb0 = __float_as_uint(w2s[(kb + tig) * 36 + c]);
            unsigned bb1 = __float_as_uint(w2s[(kb + tig + 4) * 36 + c]);
            mma_tf32(acc2[0][ni], a[0], bb0, bb1);
            mma_tf32(acc2[1][ni], a[1], bb0, bb1);
        }
    }

    #pragma unroll
    for (int mi = 0; mi < 2; mi++) {
        #pragma unroll
        for (int ni = 0; ni < 2; ni++) {
            #pragma unroll
            for (int ci = 0; ci < 4; ci++) {
                int p = mh * 32 + mi * 16 + grp + ((ci >= 2) ? 8 : 0);
                if (p < 49) {
                    int ch = nh * 16 + ni * 8 + tig * 2 + (ci & 1);
                    size_t g = (size_t)(b0 + img) * 1568 + ch * 49 + p;
                    float v = acc2[mi][ni][ci] + __ldg(buf + g);
                    buf[g] = fmaxf(v, 0.f);
                }
            }
        }
    }
}

// ======================================================================
// TF32 GEMM (decoder fc4): double-buffered smem        [round-13]
// ======================================================================
__global__ void __launch_bounds__(256) gemm_tc(
        const float* __restrict__ A,
        const float* __restrict__ W,
        const float* __restrict__ bias,
        float* __restrict__ C,
        int M, int N, int K) {
    __shared__ float As[2][128][17];
    __shared__ float Ws[2][64][17];
    int t = threadIdx.x, lane = t & 31, w = t >> 5;
    int grp = lane >> 2, tig = lane & 3;
    int m0 = blockIdx.x * 128, n0 = blockIdx.y * 64;
    int mw = (w & 3) * 32, nw = (w >> 2) * 32;
    float acc[2][4][4];
    #pragma unroll
    for (int mi = 0; mi < 2; mi++)
        #pragma unroll
        for (int ni = 0; ni < 4; ni++)
            #pragma unroll
            for (int c = 0; c < 4; c++) acc[mi][ni][c] = 0.f;

    int ar = t >> 1, ak = (t & 1) * 8;
    int wr = t >> 2, wk = (t & 3) * 4;
    const float* apb = A + (size_t)(m0 + ar) * K + ak;
    bool wval = (n0 + wr < N);
    const float* wpb = W + (size_t)(n0 + wr) * K + wk;

    float4 v0 = *(const float4*)apb;
    float4 v1 = *(const float4*)(apb + 4);
    float4 wv = wval ? *(const float4*)wpb : make_float4(0.f, 0.f, 0.f, 0.f);
    int s = 0;
    As[0][ar][ak + 0] = to_tf32(v0.x); As[0][ar][ak + 1] = to_tf32(v0.y);
    As[0][ar][ak + 2] = to_tf32(v0.z); As[0][ar][ak + 3] = to_tf32(v0.w);
    As[0][ar][ak + 4] = to_tf32(v1.x); As[0][ar][ak + 5] = to_tf32(v1.y);
    As[0][ar][ak + 6] = to_tf32(v1.z); As[0][ar][ak + 7] = to_tf32(v1.w);
    Ws[0][wr][wk + 0] = to_tf32(wv.x); Ws[0][wr][wk + 1] = to_tf32(wv.y);
    Ws[0][wr][wk + 2] = to_tf32(wv.z); Ws[0][wr][wk + 3] = to_tf32(wv.w);
    __syncthreads();

    for (int k0 = 0; k0 < K; k0 += 16) {
        bool more = (k0 + 16 < K);
        if (more) {
            v0 = *(const float4*)(apb + k0 + 16);
            v1 = *(const float4*)(apb + k0 + 20);
            wv = wval ? *(const float4*)(wpb + k0 + 16)
                      : make_float4(0.f, 0.f, 0.f, 0.f);
        }
        #pragma unroll
        for (int kk = 0; kk < 2; kk++) {
            int kb = kk * 8;
            unsigned a[2][4];
            #pragma unroll
            for (int mi = 0; mi < 2; mi++) {
                int r = mw + mi * 16 + grp;
                a[mi][0] = __float_as_uint(As[s][r][kb + tig]);
                a[mi][1] = __float_as_uint(As[s][r + 8][kb + tig]);
                a[mi][2] = __float_as_uint(As[s][r][kb + tig + 4]);
                a[mi][3] = __float_as_uint(As[s][r + 8][kb + tig + 4]);
            }
            #pragma unroll
            for (int ni = 0; ni < 4; ni++) {
                int n = nw + ni * 8 + grp;
                unsigned bb0 = __float_as_uint(Ws[s][n][kb + tig]);
                unsigned bb1 = __float_as_uint(Ws[s][n][kb + tig + 4]);
                mma_tf32(acc[0][ni], a[0], bb0, bb1);
                mma_tf32(acc[1][ni], a[1], bb0, bb1);
            }
        }
        if (more) {
            int d = s ^ 1;
            As[d][ar][ak + 0] = to_tf32(v0.x); As[d][ar][ak + 1] = to_tf32(v0.y);
            As[d][ar][ak + 2] = to_tf32(v0.z); As[d][ar][ak + 3] = to_tf32(v0.w);
            As[d][ar][ak + 4] = to_tf32(v1.x); As[d][ar][ak + 5] = to_tf32(v1.y);
            As[d][ar][ak + 6] = to_tf32(v1.z); As[d][ar][ak + 7] = to_tf32(v1.w);
            Ws[d][wr][wk + 0] = to_tf32(wv.x); Ws[d][wr][wk + 1] = to_tf32(wv.y);
            Ws[d][wr][wk + 2] = to_tf32(wv.z); Ws[d][wr][wk + 3] = to_tf32(wv.w);
            __syncthreads();
            s = d;
        }
    }
    #pragma unroll
    for (int mi = 0; mi < 2; mi++) {
        #pragma unroll
        for (int ni = 0; ni < 4; ni++) {
            #pragma unroll
            for (int ci = 0; ci < 4; ci++) {
                int r = m0 + mw + mi * 16 + grp + ((ci >= 2) ? 8 : 0);
                int n = n0 + nw + ni * 8 + tig * 2 + (ci & 1);
                if (n < N)
                    C[(size_t)r * N + n] = fmaxf(acc[mi][ni][ci] + bias[n], 0.f);
            }
        }
    }
}

// ======================================================================
// 3xTF32 GEMM (encoder fc1): double-buffered smem      [round-13]
// ======================================================================
__global__ void __launch_bounds__(256) gemm_tc3(
        const float* __restrict__ A,
        const float* __restrict__ W,
        const float* __restrict__ bias,
        float* __restrict__ C,
        int M, int N, int K) {
    __shared__ float As[2][128][17];
    __shared__ float Ws[2][64][17];
    int t = threadIdx.x, lane = t & 31, w = t >> 5;
    int grp = lane >> 2, tig = lane & 3;
    int m0 = blockIdx.x * 128, n0 = blockIdx.y * 64;
    int mw = (w & 3) * 32, nw = (w >> 2) * 32;
    float acc[2][4][4];
    #pragma unroll
    for (int mi = 0; mi < 2; mi++)
        #pragma unroll
        for (int ni = 0; ni < 4; ni++)
            #pragma unroll
            for (int c = 0; c < 4; c++) acc[mi][ni][c] = 0.f;

    int ar = t >> 1, ak = (t & 1) * 8;
    int wr = t >> 2, wk = (t & 3) * 4;
    const float* apb = A + (size_t)(m0 + ar) * K + ak;
    bool wval = (n0 + wr < N);
    const float* wpb = W + (size_t)(n0 + wr) * K + wk;

    float4 v0 = *(const float4*)apb;
    float4 v1 = *(const float4*)(apb + 4);
    float4 wv = wval ? *(const float4*)wpb : make_float4(0.f, 0.f, 0.f, 0.f);
    int s = 0;
    As[0][ar][ak + 0] = v0.x; As[0][ar][ak + 1] = v0.y;
    As[0][ar][ak + 2] = v0.z; As[0][ar][ak + 3] = v0.w;
    As[0][ar][ak + 4] = v1.x; As[0][ar][ak + 5] = v1.y;
    As[0][ar][ak + 6] = v1.z; As[0][ar][ak + 7] = v1.w;
    Ws[0][wr][wk + 0] = wv.x; Ws[0][wr][wk + 1] = wv.y;
    Ws[0][wr][wk + 2] = wv.z; Ws[0][wr][wk + 3] = wv.w;
    __syncthreads();

    for (int k0 = 0; k0 < K; k0 += 16) {
        bool more = (k0 + 16 < K);
        if (more) {
            v0 = *(const float4*)(apb + k0 + 16);
            v1 = *(const float4*)(apb + k0 + 20);
            wv = wval ? *(const float4*)(wpb + k0 + 16)
                      : make_float4(0.f, 0.f, 0.f, 0.f);
        }
        #pragma unroll
        for (int kk = 0; kk < 2; kk++) {
            int kb = kk * 8;
            unsigned ah[2][4], al[2][4];
            #pragma unroll
            for (int mi = 0; mi < 2; mi++) {
                int r = mw + mi * 16 + grp;
                split_tf32(As[s][r][kb + tig],         ah[mi][0], al[mi][0]);
                split_tf32(As[s][r + 8][kb + tig],     ah[mi][1], al[mi][1]);
                split_tf32(As[s][r][kb + tig + 4],     ah[mi][2], al[mi][2]);
                split_tf32(As[s][r + 8][kb + tig + 4], ah[mi][3], al[mi][3]);
            }
            #pragma unroll
            for (int ni = 0; ni < 4; ni++) {
                int n = nw + ni * 8 + grp;
                unsigned bh0, bl0, bh1, bl1;
                split_tf32(Ws[s][n][kb + tig],     bh0, bl0);
                split_tf32(Ws[s][n][kb + tig + 4], bh1, bl1);
                mma3(acc[0][ni], ah[0], al[0], bh0, bh1, bl0, bl1);
                mma3(acc[1][ni], ah[1], al[1], bh0, bh1, bl0, bl1);
            }
        }
        if (more) {
            int d = s ^ 1;
            As[d][ar][ak + 0] = v0.x; As[d][ar][ak + 1] = v0.y;
            As[d][ar][ak + 2] = v0.z; As[d][ar][ak + 3] = v0.w;
            As[d][ar][ak + 4] = v1.x; As[d][ar][ak + 5] = v1.y;
            As[d][ar][ak + 6] = v1.z; As[d][ar][ak + 7] = v1.w;
            Ws[d][wr][wk + 0] = wv.x; Ws[d][wr][wk + 1] = wv.y;
            Ws[d][wr][wk + 2] = wv.z; Ws[d][wr][wk + 3] = wv.w;
            __syncthreads();
            s = d;
        }
    }
    #pragma unroll
    for (int mi = 0; mi < 2; mi++) {
        #pragma unroll
        for (int ni = 0; ni < 4; ni++) {
            #pragma unroll
            for (int ci = 0; ci < 4; ci++) {
                int r = m0 + mw + mi * 16 + grp + ((ci >= 2) ? 8 : 0);
                int n = n0 + nw + ni * 8 + tig * 2 + (ci & 1);
                if (n < N)
                    C[(size_t)r * N + n] = fmaxf(acc[mi][ni][ci] + bias[n], 0.f);
            }
        }
    }
}

// ======================================================================
// convt2 inner body (compile-time tap tables)          [round-7 proven]
// ======================================================================
template<int DY0, int KY0, int DY1, int KY1,
         int DX0, int KX0, int DX1, int KX1>
__device__ __forceinline__ void ct2_body(
        const float* __restrict__ base, const float* __restrict__ w,
        float bv, float* __restrict__ outp, int m) {
    float acc[14];
    #pragma unroll
    for (int j = 0; j < 14; j++) acc[j] = bv;
    for (int ic = 0; ic < 16; ic++) {
        const float* xc = base + ic * 256;
        #pragma unroll
        for (int sy = 0; sy < 2; sy++) {
            int iy = m + (sy ? DY1 : DY0);
            float row[16];
            #pragma unroll
            for (int j = 0; j < 16; j++) row[j] = xc[(iy + 1) * 16 + j];
            {
                float wv = __ldg(w + ic * 16 + (sy ? KY1 : KY0) * 4 + KX0);
                #pragma unroll
                for (int n = 0; n < 14; n++) acc[n] += row[n + DX0 + 1] * wv;
            }
            {
                float wv = __ldg(w + ic * 16 + (sy ? KY1 : KY0) * 4 + KX1);
                #pragma unroll
                for (int n = 0; n < 14; n++) acc[n] += row[n + DX1 + 1] * wv;
            }
        }
    }
    #pragma unroll
    for (int n = 0; n < 14; n++) outp[2 * n] = acc[n];
}

// ======================================================================
// FUSED convt1+convt2 (decoder)                        [round-12 proven]
// ======================================================================
#define T12_IMSZ 2916
#define T12_ZB   6240
#define T12_XIN  6664
#define T12_W    T12_XIN
#define T12_HP   (T12_W + 16 * 32 * 24)
#define T12_TOT  (T12_HP + 2 * 4096)
#define T12_SMEM (T12_TOT * 4)

__global__ void __launch_bounds__(256) convt12_tc(
        const float* __restrict__ in,
        const float* __restrict__ w,
        const float* __restrict__ bias,
        const float* __restrict__ c2w,
        const float* __restrict__ c2b,
        float* __restrict__ out) {
    extern __shared__ float sm[];
    float* xin = sm;
    float* wt  = sm + T12_W;
    float* hp  = sm + T12_HP;
    int t = threadIdx.x;
    int b0 = blockIdx.x * 2;

    for (int i = t; i < T12_XIN; i += 256) xin[i] = 0.f;
    for (int i = t; i < 8192; i += 256) hp[i] = 0.f;
    __syncthreads();
    for (int i = t; i < 2 * 1568; i += 256) {
        int img = i / 1568, j = i % 1568;
        int ic = j / 49, p = j % 49, iy = p / 7, ix = p % 7;
        xin[img * T12_IMSZ + ((iy + 1) * 9 + (ix + 1)) * 36 + ic] =
            to_tf32(in[(size_t)(b0 + img) * 1568 + j]);
    }
    for (int i = t; i < 32 * 256; i += 256) {
        int ic = i / 256, r = i % 256, oc = r / 16, s = r % 16;
        wt[s * 768 + ic * 24 + oc] = to_tf32(w[i]);
    }
    __syncthreads();

    int lane = t & 31, wrp = t >> 5;
    int grp = lane >> 2, tig = lane & 3;
    int img = wrp >> 2, ph = wrp & 3;
    int a = ph >> 1, bp = ph & 1;
    int dyv[2], kyv[2], dxv[2], kxv[2];
    if (a == 0) { dyv[0] = 0; kyv[0] = 1; dyv[1] = -1; kyv[1] = 3; }
    else        { dyv[0] = 1; kyv[0] = 0; dyv[1] =  0; kyv[1] = 2; }
    if (bp == 0) { dxv[0] = 0; kxv[0] = 1; dxv[1] = -1; kxv[1] = 3; }
    else         { dxv[0] = 1; kxv[0] = 0; dxv[1] =  0; kxv[1] = 2; }

    int rb[4][2];
    #pragma unroll
    for (int mi = 0; mi < 4; mi++)
        #pragma unroll
        for (int h = 0; h < 2; h++) {
            int p = mi * 16 + grp + h * 8;
            rb[mi][h] = (p < 49)
                ? img * T12_IMSZ + ((p / 7 + 1) * 9 + (p % 7 + 1)) * 36
                : T12_ZB;
        }

    float acc[4][2][4];
    #pragma unroll
    for (int mi = 0; mi < 4; mi++)
        #pragma unroll
        for (int ni = 0; ni < 2; ni++)
            #pragma unroll
            for (int c = 0; c < 4; c++) acc[mi][ni][c] = 0.f;

    #pragma unroll
    for (int sy = 0; sy < 2; sy++) {
        #pragma unroll
        for (int sx = 0; sx < 2; sx++) {
            int soff = (dyv[sy] * 9 + dxv[sx]) * 36;
            const float* wsl = wt + (kyv[sy] * 4 + kxv[sx]) * 768;
            #pragma unroll
            for (int kk = 0; kk < 4; kk++) {
                int kb = kk * 8;
                unsigned afr[4][4];
                #pragma unroll
                for (int mi = 0; mi < 4; mi++) {
                    afr[mi][0] = __float_as_uint(xin[rb[mi][0] + soff + kb + tig]);
                    afr[mi][1] = __float_as_uint(xin[rb[mi][1] + soff + kb + tig]);
                    afr[mi][2] = __float_as_uint(xin[rb[mi][0] + soff + kb + tig + 4]);
                    afr[mi][3] = __float_as_uint(xin[rb[mi][1] + soff + kb + tig + 4]);
                }
                #pragma unroll
                for (int ni = 0; ni < 2; ni++) {
                    unsigned bb0 = __float_as_uint(wsl[(kb + tig) * 24 + ni * 8 + grp]);
                    unsigned bb1 = __float_as_uint(wsl[(kb + tig + 4) * 24 + ni * 8 + grp]);
                    #pragma unroll
                    for (int mi = 0; mi < 4; mi++)
                        mma_tf32(acc[mi][ni], afr[mi], bb0, bb1);
                }
            }
        }
    }

    #pragma unroll
    for (int mi = 0; mi < 4; mi++) {
        #pragma unroll
        for (int ni = 0; ni < 2; ni++) {
            #pragma unroll
            for (int ci = 0; ci < 4; ci++) {
                int p = mi * 16 + grp + ((ci >= 2) ? 8 : 0);
                if (p < 49) {
                    int m = p / 7, n = p % 7;
                    int oc = ni * 8 + tig * 2 + (ci & 1);
                    int oy = 2 * m + a, ox = 2 * n + bp;
                    float v = acc[mi][ni][ci] + __ldg(bias + oc);
                    hp[img * 4096 + oc * 256 + (oy + 1) * 16 + (ox + 1)] =
                        fmaxf(v, 0.f);
                }
            }
        }
    }
    __syncthreads();

    if (t < 112) {
        int ph2 = t / 28, r2 = t % 28;
        int img2 = r2 / 14, m2 = r2 % 14;
        int a2 = ph2 >> 1, b2 = ph2 & 1;
        const float* base2 = hp + img2 * 4096;
        float bv2 = c2b[0];
        float* outp = out + (size_t)(b0 + img2) * 784 + (2 * m2 + a2) * 28 + b2;
        if (ph2 == 0)      ct2_body<0, 1, -1, 3,  0, 1, -1, 3>(base2, c2w, bv2, outp, m2);
        else if (ph2 == 1) ct2_body<0, 1, -1, 3,  1, 0,  0, 2>(base2, c2w, bv2, outp, m2);
        else if (ph2 == 2) ct2_body<1, 0,  0, 2,  0, 1, -1, 3>(base2, c2w, bv2, outp, m2);
        else               ct2_body<1, 0,  0, 2,  1, 0,  0, 2>(base2, c2w, bv2, outp, m2);
    }
}

// ======================================================================
// fc2: z[B,32] = A[B,224] @ w^T + b  (fp32, feeds VQ)   [round-8]
// ======================================================================
__global__ void __launch_bounds__(256) fc2_kernel(
        const float* __restrict__ A,
        const float* __restrict__ w,
        const float* __restrict__ bias,
        float* __restrict__ out) {
    __shared__ float ws[32 * 224];
    int t = threadIdx.x;
    for (int i = t; i < 7168; i += 256) ws[i] = w[i];
    __syncthreads();
    int n = t & 31, r = t >> 5;
    float bv = bias[n];
    const float* wp = ws + n * 224;
    #pragma unroll
    for (int rr = 0; rr < 4; rr++) {
        int b = blockIdx.x * 32 + rr * 8 + r;
        const float* ap = A + (size_t)b * 224;
        float acc = bv;
        #pragma unroll 8
        for (int k = 0; k < 224; k++) acc += ap[k] * wp[k];
        out[(size_t)b * 32 + n] = acc;
    }
}

// ======================================================================
// VQ helpers (fp32 exact)
// ======================================================================
__global__ void enorm_kernel(const float* __restrict__ emb, float* __restrict__ enorm) {
    int e = blockIdx.x * blockDim.x + threadIdx.x;
    if (e < NE) {
        float s = 0.f;
        #pragma unroll
        for (int d = 0; d < ZD; d++) { float v = emb[e * ZD + d]; s += v * v; }
        enorm[e] = s;
    }
}

__global__ void zero_kernel(float* __restrict__ counts, float* __restrict__ sums,
                            float* __restrict__ loss) {
    int i = blockIdx.x * blockDim.x + threadIdx.x;
    if (i < NE) counts[i] = 0.f;
    if (i < NE * ZD) sums[i] = 0.f;
    if (i == 0) loss[0] = 0.f;
}

#define VQ_SMEM (NE * 36 * 4)

__global__ void __launch_bounds__(256) vq_kernel(
        const float* __restrict__ z,
        const float* __restrict__ emb,
        const float* __restrict__ enorm,
        int* __restrict__ idx,
        float* __restrict__ counts,
        float* __restrict__ sums,
        float* __restrict__ loss) {
    extern __shared__ float es[];          // [512][36]
    __shared__ float en[NE];
    __shared__ float zs[8][ZD];
    int t = threadIdx.x, lane = t & 31, wl = t >> 5;
    for (int i = t; i < NE * ZD; i += 256) {
        int e = i >> 5, d = i & 31;
        es[e * 36 + d] = emb[i];
    }
    for (int i = t; i < NE; i += 256) en[i] = enorm[i];
    __syncthreads();

    for (int rr = 0; rr < 8; rr++) {
        int row = blockIdx.x * 64 + wl * 8 + rr;
        zs[wl][lane] = z[(size_t)row * ZD + lane];
        __syncwarp();
        float best = 3.4e38f; int bi = NE;
        for (int e = lane; e < NE; e += 32) {
            const float* ep = es + e * 36;
            float dot = 0.f;
            #pragma unroll
            for (int d = 0; d < ZD; d += 4) {
                float4 v = *(const float4*)(ep + d);
                dot += zs[wl][d + 0] * v.x;
                dot += zs[wl][d + 1] * v.y;
                dot += zs[wl][d + 2] * v.z;
                dot += zs[wl][d + 3] * v.w;
            }
            float s = en[e] - 2.f * dot;
            if (s < best) { best = s; bi = e; }
        }
        #pragma unroll
        for (int off = 16; off; off >>= 1) {
            float ob = __shfl_xor_sync(0xffffffffu, best, off);
            int   oi = __shfl_xor_sync(0xffffffffu, bi, off);
            if (ob < best || (ob == best && oi < bi)) { best = ob; bi = oi; }
        }
        float zl = zs[wl][lane];
        float diff = es[bi * 36 + lane] - zl;
        float d2 = diff * diff;
        #pragma unroll
        for (int off = 16; off; off >>= 1)
            d2 += __shfl_xor_sync(0xffffffffu, d2, off);
        if (lane == 0) {
            idx[row] = bi;
            atomicAdd(&counts[bi], 1.f);
            atomicAdd(loss, d2);
        }
        atomicAdd(&sums[bi * ZD + lane], zl);
        __syncwarp();
    }
}

__global__ void embnew_kernel(const float* __restrict__ m_mat,
                              const float* __restrict__ n_mat,
                              const float* __restrict__ sums,
                              const float* __restrict__ counts,
                              float* __restrict__ out) {
    int i = blockIdx.x * blockDim.x + threadIdx.x;
    if (i < NE * ZD) {
        int e = i >> 5;
        float m = m_mat[i] * GAMMA + sums[i] * ONE_M_GAMMA;
        float n = n_mat[e] * GAMMA + counts[e] * ONE_M_GAMMA;
        out[i] = m / n;
    }
}

__global__ void finalize_kernel(const float* __restrict__ counts,
                                const float* __restrict__ loss,
                                float* __restrict__ out_scalars) {
    __shared__ float red[NE];
    int t = threadIdx.x;
    float c = counts[t];
    float em = c * (1.f / (float)BATCH);
    red[t] = em * logf(em + 1e-10f);
    __syncthreads();
    for (int s = 256; s; s >>= 1) {
        if (t < s) red[t] += red[t + s];
        __syncthreads();
    }
    if (t == 0) {
        float q = loss[0] * (1.f / ((float)BATCH * (float)ZD));
        out_scalars[0] = q;
        out_scalars[1] = BETA * q;
        out_scalars[2] = expf(-red[0]);
    }
}

// ======================================================================
// fc3 (fp32): 16 images/CTA                           [round-8, proven]
// ======================================================================
__global__ void __launch_bounds__(224) fc3_kernel(
        const float* __restrict__ emb,
        const int* __restrict__ idx,
        const float* __restrict__ w,
        const float* __restrict__ bias,
        float* __restrict__ out) {
    __shared__ float ws[224 * ZD];
    __shared__ float zq[16][ZD + 1];
    int b0 = blockIdx.x * 16, t = threadIdx.x;
    for (int i = t; i < 224 * ZD; i += 224) ws[i] = w[i];
    for (int i = t; i < 16 * ZD; i += 224) {
        int im = i >> 5, d = i & 31;
        zq[im][d] = emb[(size_t)idx[b0 + im] * ZD + d];
    }
    __syncthreads();
    float bv = bias[t];
    float wreg[ZD];
    const float* wp = ws + t * ZD;
    #pragma unroll
    for (int k = 0; k < ZD; k++) wreg[k] = wp[k];
    #pragma unroll 4
    for (int im = 0; im < 16; im++) {
        float acc = bv;
        #pragma unroll
        for (int k = 0; k < ZD; k++) acc += zq[im][k] * wreg[k];
        out[(size_t)(b0 + im) * 224 + t] = fmaxf(acc, 0.f);
    }
}

// ======================================================================
// launch
// ======================================================================
extern "C" void kernel_launch(void* const* d_in, const int* in_sizes, int n_in,
                              void* d_out, int out_size) {
    const float* x        = (const float*)d_in[0];
    const float* conv1_w  = (const float*)d_in[1];
    const float* conv1_b  = (const float*)d_in[2];
    const float* conv2_w  = (const float*)d_in[3];
    const float* conv2_b  = (const float*)d_in[4];
    const float* res1_w1  = (const float*)d_in[5];
    const float* res1_w2  = (const float*)d_in[6];
    const float* fc1_w    = (const float*)d_in[7];
    const float* fc1_b    = (const float*)d_in[8];
    const float* fc2_w    = (const float*)d_in[9];
    const float* fc2_b    = (const float*)d_in[10];
    const float* emb      = (const float*)d_in[11];
    const float* n_mat    = (const float*)d_in[12];
    const float* m_mat    = (const float*)d_in[13];
    const float* fc3_w    = (const float*)d_in[14];
    const float* fc3_b    = (const float*)d_in[15];
    const float* fc4_w    = (const float*)d_in[16];
    const float* fc4_b    = (const float*)d_in[17];
    const float* res2_w1  = (const float*)d_in[18];
    const float* res2_w2  = (const float*)d_in[19];
    const float* convt1_w = (const float*)d_in[20];
    const float* convt1_b = (const float*)d_in[21];
    const float* convt2_w = (const float*)d_in[22];
    const float* convt2_b = (const float*)d_in[23];
    float* out = (float*)d_out;

    float *h2, *a, *z, *enorm, *counts, *sums, *loss;
    int* idx;
    float2 *wf_r1, *wf_r2, *wf_c2;
    cudaGetSymbolAddress((void**)&h2,     g_h2);
    cudaGetSymbolAddress((void**)&a,      g_a);
    cudaGetSymbolAddress((void**)&z,      g_z);
    cudaGetSymbolAddress((void**)&idx,    g_idx);
    cudaGetSymbolAddress((void**)&enorm,  g_enorm);
    cudaGetSymbolAddress((void**)&counts, g_counts);
    cudaGetSymbolAddress((void**)&sums,   g_sums);
    cudaGetSymbolAddress((void**)&loss,   g_loss);
    cudaGetSymbolAddress((void**)&wf_r1,  g_wf_r1);
    cudaGetSymbolAddress((void**)&wf_r2,  g_wf_r2);
    cudaGetSymbolAddress((void**)&wf_c2,  g_wf_c2);

    cudaFuncSetAttribute(conv12_tc3,
                         cudaFuncAttributeMaxDynamicSharedMemorySize, C15_SMEM);
    cudaFuncSetAttribute(res_tc3,
                         cudaFuncAttributeMaxDynamicSharedMemorySize, E3_SMEM);
    cudaFuncSetAttribute(res_tcd,
                         cudaFuncAttributeMaxDynamicSharedMemorySize, D3_SMEM);
    cudaFuncSetAttribute(convt12_tc,
                         cudaFuncAttributeMaxDynamicSharedMemorySize, T12_SMEM);
    cudaFuncSetAttribute(vq_kernel,
                         cudaFuncAttributeMaxDynamicSharedMemorySize, VQ_SMEM);

    // weight repack (fragment-order textures)
    repack_res<<<36, 256>>>(res1_w1, wf_r1, 0);
    repack_res<<<36, 256>>>(res2_w1, wf_r2, 1);
    repack_c2 <<<16, 256>>>(conv2_w, wf_c2);

    // encoder (3xTF32 = fp32-class accuracy; VQ path preserved)
    conv12_tc3<<<(BATCH + 4) / 5, 512, C15_SMEM>>>(x, conv1_w, conv1_b, wf_c2,
                                                   conv2_b, h2);
    res_tc3  <<<BATCH / 2, 256, E3_SMEM>>>(h2, wf_r1, res1_w2);
    gemm_tc3<<<dim3(BATCH / 128, 4), 256>>>(h2, fc1_w, fc1_b, a,
                                            BATCH, 224, 1568);
    fc2_kernel<<<BATCH / 32, 256>>>(a, fc2_w, fc2_b, z);

    // VQ
    zero_kernel <<<(NE * ZD + 255) / 256, 256>>>(counts, sums, loss);
    enorm_kernel<<<2, 256>>>(emb, enorm);
    vq_kernel   <<<BATCH / 64, 256, VQ_SMEM>>>(z, emb, enorm, idx, counts,
                                               sums, loss);
    embnew_kernel  <<<(NE * ZD + 255) / 256, 256>>>(m_mat, n_mat, sums, counts,
                                                    out + OFF_SCAL + 3);
    finalize_kernel<<<1, NE>>>(counts, loss, out + OFF_SCAL);

    // decoder (single tf32)
    fc3_kernel<<<BATCH / 16, 224>>>(emb, idx, fc3_w, fc3_b, a);
    gemm_tc<<<dim3(BATCH / 128, 25), 256>>>(a, fc4_w, fc4_b, h2,
                                            BATCH, 1568, 224);
    res_tcd<<<BATCH / 2, 256, D3_SMEM>>>(h2, wf_r2, res2_w2);
    convt12_tc<<<BATCH / 2, 256, T12_SMEM>>>(h2, convt1_w, convt1_b,
                                             convt2_w, convt2_b, out);
}

// round 17
// speedup vs baseline: 1.1001x; 1.0696x over previous
#include <cuda_runtime.h>
#include <cstdint>
#include <math.h>

// ---------------- problem constants ----------------
#define BATCH 16384
#define ZD 32
#define NE 512
#define GAMMA 0.99f
#define ONE_M_GAMMA 0.01f
#define BETA 1.0f

#define OFF_SCAL (BATCH * 784)   // x_rec size
// d_out layout: [x_rec (B*784)][quant][commit][perplexity][emb_new (512*32)]

// ---------------- scratch ----------------
__device__ float g_h2[BATCH * 32 * 7 * 7];
__device__ float g_a [BATCH * 224];
__device__ float g_z [BATCH * ZD];
__device__ int   g_idx[BATCH];
__device__ float g_enorm[NE];
__device__ float g_counts[NE];
__device__ float g_sums[NE * ZD];
__device__ float g_loss[1];
// fragment-order weight textures: [s][kk][oct][lane] -> (b0,b1)
__device__ float2 g_wf_r1[9216];   // res1 w1 (raw fp32)
__device__ float2 g_wf_r2[9216];   // res2 w1 (tf32)
__device__ float2 g_wf_c2[4096];   // conv2 w  (raw fp32)
__device__ float2 g_wf_t1[4096];   // convt1 w (tf32)

// ---------------- tf32 mma helpers ----------------
__device__ __forceinline__ float to_tf32(float x) {
    float y;
    asm("cvt.rna.tf32.f32 %0, %1;" : "=f"(y) : "f"(x));
    return y;
}

// Bitwise hi/lo split: hi = RZ-truncated tf32 (LOP3), lo = v - hi (exact FADD).
__device__ __forceinline__ void split_tf32(float v, unsigned& hi, unsigned& lo) {
    unsigned h = __float_as_uint(v) & 0xffffe000u;
    hi = h;
    lo = __float_as_uint(v - __uint_as_float(h));
}

__device__ __forceinline__ void mma_tf32(float* d, const unsigned* a,
                                         unsigned b0, unsigned b1) {
    asm volatile(
        "mma.sync.aligned.m16n8k8.row.col.f32.tf32.tf32.f32 "
        "{%0,%1,%2,%3}, {%4,%5,%6,%7}, {%8,%9}, {%0,%1,%2,%3};\n"
        : "+f"(d[0]), "+f"(d[1]), "+f"(d[2]), "+f"(d[3])
        : "r"(a[0]), "r"(a[1]), "r"(a[2]), "r"(a[3]), "r"(b0), "r"(b1));
}

// 3-pass split mma: acc += a*b with ~fp32 accuracy
__device__ __forceinline__ void mma3(float* d, const unsigned* ah, const unsigned* al,
                                     unsigned bh0, unsigned bh1,
                                     unsigned bl0, unsigned bl1) {
    mma_tf32(d, ah, bl0, bl1);
    mma_tf32(d, al, bh0, bh1);
    mma_tf32(d, ah, bh0, bh1);
}

// ======================================================================
// weight repack kernels (run once per launch; tiny)
// ======================================================================
__global__ void repack_res(const float* __restrict__ w1,
                           float2* __restrict__ out, int cvt) {
    int i = blockIdx.x * 256 + threadIdx.x;
    if (i >= 9216) return;
    int lane = i & 31, oct = (i >> 5) & 7, kk = (i >> 8) & 3, s = i >> 10;
    int grp = lane >> 2, tig = lane & 3;
    int oc = oct * 8 + grp, ic = kk * 8 + tig;
    float b0 = w1[oc * 288 + ic * 9 + s];
    float b1 = w1[oc * 288 + (ic + 4) * 9 + s];
    if (cvt) { b0 = to_tf32(b0); b1 = to_tf32(b1); }
    out[i] = make_float2(b0, b1);
}

__global__ void repack_c2(const float* __restrict__ w,
                          float2* __restrict__ out) {
    int i = blockIdx.x * 256 + threadIdx.x;
    if (i >= 4096) return;
    int lane = i & 31, oct = (i >> 5) & 3, kk = (i >> 7) & 1, s = i >> 8;
    int grp = lane >> 2, tig = lane & 3;
    int oc = oct * 8 + grp, ic = kk * 8 + tig;
    out[i] = make_float2(w[oc * 256 + ic * 16 + s],
                         w[oc * 256 + (ic + 4) * 16 + s]);
}

// convt1 w[ic 32][oc 16][s 16] -> [s 16][kk 4][oct 2][lane 32] (tf32)
__global__ void repack_t1(const float* __restrict__ w,
                          float2* __restrict__ out) {
    int i = blockIdx.x * 256 + threadIdx.x;
    if (i >= 4096) return;
    int lane = i & 31, oct = (i >> 5) & 1, kk = (i >> 6) & 3, s = i >> 8;
    int grp = lane >> 2, tig = lane & 3;
    int oc = oct * 8 + grp, ic = kk * 8 + tig;
    out[i] = make_float2(to_tf32(w[ic * 256 + oc * 16 + s]),
                         to_tf32(w[(ic + 4) * 256 + oc * 16 + s]));
}

// ======================================================================
// FUSED conv1+conv2 (encoder)                        [round-12/13 proven]
// 2 img/CTA, 256 thr, smem 63.6 KB -> 3 CTA/SM (24 warps).
// ======================================================================
#define C12_ZOFF 9216
#define C12_XIN  13824
#define C12_XP   13824
#define C12_W1   (C12_XP + 1800)
#define C12_B1   (C12_W1 + 256)
#define C12_TOT  15896
#define C12_SMEM (C12_TOT * 4)

__global__ void __launch_bounds__(256) conv12_tc3(
        const float* __restrict__ x,
        const float* __restrict__ c1wg,
        const float* __restrict__ c1bg,
        const float2* __restrict__ wf,
        const float* __restrict__ bias,
        float* __restrict__ out) {
    extern __shared__ float sm[];
    float* xin = sm;
    float* xp  = sm + C12_XP;
    float* c1w = sm + C12_W1;
    float* c1b = sm + C12_B1;
    int t = threadIdx.x;
    int b0 = blockIdx.x * 2;

    for (int i = t; i < C12_XIN; i += 256) xin[i] = 0.f;
    for (int i = t; i < 1800; i += 256) xp[i] = 0.f;
    if (t < 256) c1w[t] = c1wg[t];
    if (t < 16)  c1b[t] = c1bg[t];
    __syncthreads();
    for (int i = t; i < 1568; i += 256) {
        int im = i / 784, j = i % 784;
        int iy = j / 28, ix = j % 28;
        xp[im * 900 + (iy + 1) * 30 + (ix + 1)] = x[(size_t)(b0 + im) * 784 + j];
    }
    __syncthreads();

    for (int pi = t; pi < 392; pi += 256) {
        int im = pi / 196, pix = pi % 196;
        int oy = pix / 14, ox = pix % 14;
        const float* basep = xp + im * 900 + (2 * oy) * 30 + 2 * ox;
        float patch[16];
        #pragma unroll
        for (int ky = 0; ky < 4; ky++)
            #pragma unroll
            for (int kx = 0; kx < 4; kx++)
                patch[ky * 4 + kx] = basep[ky * 30 + kx];
        float* dst = xin + im * 4608 + ((oy + 1) * 16 + (ox + 1)) * 18;
        #pragma unroll
        for (int oc = 0; oc < 16; oc++) {
            float acc = c1b[oc];
            #pragma unroll
            for (int tap = 0; tap < 16; tap++)
                acc += patch[tap] * c1w[oc * 16 + tap];
            dst[oc] = fmaxf(acc, 0.f);
        }
    }
    __syncthreads();

    int lane = t & 31, wrp = t >> 5;
    int grp = lane >> 2, tig = lane & 3;
    int img = wrp >> 2, mh = (wrp >> 1) & 1, nh = wrp & 1;

    int rb[2][2];
    #pragma unroll
    for (int mi = 0; mi < 2; mi++)
        #pragma unroll
        for (int h = 0; h < 2; h++) {
            int p = mh * 32 + mi * 16 + grp + h * 8;
            rb[mi][h] = (p < 49)
                ? img * 4608 + ((p / 7) * 32 + (p % 7) * 2) * 18
                : C12_ZOFF;
        }

    float acc[2][2][4];
    #pragma unroll
    for (int mi = 0; mi < 2; mi++)
        #pragma unroll
        for (int ni = 0; ni < 2; ni++)
            #pragma unroll
            for (int c = 0; c < 4; c++) acc[mi][ni][c] = 0.f;

    #pragma unroll
    for (int ky = 0; ky < 4; ky++) {
        #pragma unroll
        for (int kx = 0; kx < 4; kx++) {
            int s = ky * 4 + kx;
            int soff = (ky * 16 + kx) * 18;
            #pragma unroll
            for (int kk = 0; kk < 2; kk++) {
                int kb = kk * 8;
                unsigned ah[2][4], al[2][4];
                #pragma unroll
                for (int mi = 0; mi < 2; mi++) {
                    split_tf32(xin[rb[mi][0] + soff + kb + tig],     ah[mi][0], al[mi][0]);
                    split_tf32(xin[rb[mi][1] + soff + kb + tig],     ah[mi][1], al[mi][1]);
                    split_tf32(xin[rb[mi][0] + soff + kb + tig + 4], ah[mi][2], al[mi][2]);
                    split_tf32(xin[rb[mi][1] + soff + kb + tig + 4], ah[mi][3], al[mi][3]);
                }
                #pragma unroll
                for (int ni = 0; ni < 2; ni++) {
                    int oct = nh * 2 + ni;
                    float2 bw = __ldg(wf + (size_t)s * 256 + kk * 128 + oct * 32 + lane);
                    unsigned bh0, bl0, bh1, bl1;
                    split_tf32(bw.x, bh0, bl0);
                    split_tf32(bw.y, bh1, bl1);
                    mma3(acc[0][ni], ah[0], al[0], bh0, bh1, bl0, bl1);
                    mma3(acc[1][ni], ah[1], al[1], bh0, bh1, bl0, bl1);
                }
            }
        }
    }

    #pragma unroll
    for (int mi = 0; mi < 2; mi++) {
        #pragma unroll
        for (int ni = 0; ni < 2; ni++) {
            #pragma unroll
            for (int ci = 0; ci < 4; ci++) {
                int p = mh * 32 + mi * 16 + grp + ((ci >= 2) ? 8 : 0);
                if (p < 49) {
                    int oc = nh * 16 + ni * 8 + tig * 2 + (ci & 1);
                    out[(size_t)(b0 + img) * 1568 + oc * 49 + p] =
                        acc[mi][ni][ci] + __ldg(bias + oc);
                }
            }
        }
    }
}

// ======================================================================
// res stack 3xTF32 (encoder)                           [round-10 proven]
// ======================================================================
#define E3_RS   5832
#define E3_W2   14536
#define E3_TOT  16840
#define E3_SMEM (E3_TOT * 4)

__global__ void __launch_bounds__(256) res_tc3(
        float* __restrict__ buf,
        const float2* __restrict__ wf,
        const float* __restrict__ pw2) {
    extern __shared__ float sm[];
    float* xin = sm;
    float* rs  = sm + E3_RS;
    float* w2s = sm + E3_W2;
    int t = threadIdx.x;
    int b0 = blockIdx.x * 2;

    for (int i = t; i < E3_RS; i += 256) xin[i] = 0.f;
    __syncthreads();
    for (int i = t; i < 2048; i += 256) {
        int oc = i >> 6, ic = i & 63;
        w2s[ic * 36 + oc] = pw2[i];
    }
    for (int i = t; i < 2 * 1568; i += 256) {
        int img = i / 1568, j = i % 1568;
        int ch = j / 49, p = j % 49;
        float v = buf[(size_t)(b0 + img) * 1568 + j];
        xin[img * 2916 + ((p / 7 + 1) * 9 + (p % 7 + 1)) * 36 + ch] = fmaxf(v, 0.f);
    }
    __syncthreads();

    int lane = t & 31, wrp = t >> 5;
    int grp = lane >> 2, tig = lane & 3;
    int img = wrp >> 2, mh = (wrp >> 1) & 1, nh = wrp & 1;
    int rbase = img * 64 + mh * 32;

    int rb[2][2];
    #pragma unroll
    for (int mi = 0; mi < 2; mi++)
        #pragma unroll
        for (int h = 0; h < 2; h++) {
            int p = mh * 32 + mi * 16 + grp + h * 8;
            rb[mi][h] = (p < 49) ? img * 2916 + ((p / 7) * 9 + (p % 7)) * 36 : 0;
        }

    float acc[2][4][4];
    #pragma unroll
    for (int mi = 0; mi < 2; mi++)
        #pragma unroll
        for (int ni = 0; ni < 4; ni++)
            #pragma unroll
            for (int c = 0; c < 4; c++) acc[mi][ni][c] = 0.f;

    #pragma unroll
    for (int ky = 0; ky < 3; ky++) {
        #pragma unroll
        for (int kx = 0; kx < 3; kx++) {
            int s = ky * 3 + kx;
            int soff = (ky * 9 + kx) * 36;
            #pragma unroll
            for (int kk = 0; kk < 4; kk++) {
                int kb = kk * 8;
                unsigned ah[2][4], al[2][4];
                #pragma unroll
                for (int mi = 0; mi < 2; mi++) {
                    split_tf32(xin[rb[mi][0] + soff + kb + tig],     ah[mi][0], al[mi][0]);
                    split_tf32(xin[rb[mi][1] + soff + kb + tig],     ah[mi][1], al[mi][1]);
                    split_tf32(xin[rb[mi][0] + soff + kb + tig + 4], ah[mi][2], al[mi][2]);
                    split_tf32(xin[rb[mi][1] + soff + kb + tig + 4], ah[mi][3], al[mi][3]);
                }
                #pragma unroll
                for (int ni = 0; ni < 4; ni++) {
                    int oct = nh * 4 + ni;
                    float2 bw = __ldg(wf + (size_t)s * 1024 + kk * 256 + oct * 32 + lane);
                    unsigned bh0, bl0, bh1, bl1;
                    split_tf32(bw.x, bh0, bl0);
                    split_tf32(bw.y, bh1, bl1);
                    mma3(acc[0][ni], ah[0], al[0], bh0, bh1, bl0, bl1);
                    mma3(acc[1][ni], ah[1], al[1], bh0, bh1, bl0, bl1);
                }
            }
        }
    }

    #pragma unroll
    for (int mi = 0; mi < 2; mi++) {
        int rlo = rbase + mi * 16 + grp, rhi = rlo + 8;
        #pragma unroll
        for (int ni = 0; ni < 4; ni++) {
            int c0 = nh * 32 + ni * 8 + tig * 2;
            rs[rlo * 68 + c0]     = fmaxf(acc[mi][ni][0], 0.f);
            rs[rlo * 68 + c0 + 1] = fmaxf(acc[mi][ni][1], 0.f);
            rs[rhi * 68 + c0]     = fmaxf(acc[mi][ni][2], 0.f);
            rs[rhi * 68 + c0 + 1] = fmaxf(acc[mi][ni][3], 0.f);
        }
    }
    __syncthreads();

    float acc2[2][2][4];
    #pragma unroll
    for (int mi = 0; mi < 2; mi++)
        #pragma unroll
        for (int ni = 0; ni < 2; ni++)
            #pragma unroll
            for (int c = 0; c < 4; c++) acc2[mi][ni][c] = 0.f;

    #pragma unroll
    for (int kk = 0; kk < 8; kk++) {
        int kb = kk * 8;
        unsigned ah[2][4], al[2][4];
        #pragma unroll
        for (int mi = 0; mi < 2; mi++) {
            int rlo = rbase + mi * 16 + grp;
            split_tf32(rs[rlo * 68 + kb + tig],           ah[mi][0], al[mi][0]);
            split_tf32(rs[(rlo + 8) * 68 + kb + tig],     ah[mi][1], al[mi][1]);
            split_tf32(rs[rlo * 68 + kb + tig + 4],       ah[mi][2], al[mi][2]);
            split_tf32(rs[(rlo + 8) * 68 + kb + tig + 4], ah[mi][3], al[mi][3]);
        }
        #pragma unroll
        for (int ni = 0; ni < 2; ni++) {
            int c = nh * 16 + ni * 8 + grp;
            unsigned bh0, bl0, bh1, bl1;
            split_tf32(w2s[(kb + tig) * 36 + c],     bh0, bl0);
            split_tf32(w2s[(kb + tig + 4) * 36 + c], bh1, bl1);
            mma3(acc2[0][ni], ah[0], al[0], bh0, bh1, bl0, bl1);
            mma3(acc2[1][ni], ah[1], al[1], bh0, bh1, bl0, bl1);
        }
    }

    #pragma unroll
    for (int mi = 0; mi < 2; mi++) {
        #pragma unroll
        for (int ni = 0; ni < 2; ni++) {
            #pragma unroll
            for (int ci = 0; ci < 4; ci++) {
                int p = mh * 32 + mi * 16 + grp + ((ci >= 2) ? 8 : 0);
                if (p < 49) {
                    int ch = nh * 16 + ni * 8 + tig * 2 + (ci & 1);
                    size_t g = (size_t)(b0 + img) * 1568 + ch * 49 + p;
                    float v = acc2[mi][ni][ci] + __ldg(buf + g);
                    buf[g] = fmaxf(v, 0.f);
                }
            }
        }
    }
}

// ======================================================================
// res stack single-TF32 (decoder)                      [round-10 proven]
// ======================================================================
#define D3_RS   5346
#define D3_W2   14050
#define D3_TOT  16354
#define D3_SMEM (D3_TOT * 4)

__global__ void __launch_bounds__(256) res_tcd(
        float* __restrict__ buf,
        const float2* __restrict__ wf,
        const float* __restrict__ pw2) {
    extern __shared__ float sm[];
    float* xin = sm;
    float* rs  = sm + D3_RS;
    float* w2s = sm + D3_W2;
    int t = threadIdx.x;
    int b0 = blockIdx.x * 2;

    for (int i = t; i < D3_RS; i += 256) xin[i] = 0.f;
    __syncthreads();
    for (int i = t; i < 2048; i += 256) {
        int oc = i >> 6, ic = i & 63;
        w2s[ic * 36 + oc] = to_tf32(pw2[i]);
    }
    for (int i = t; i < 2 * 1568; i += 256) {
        int img = i / 1568, j = i % 1568;
        int ch = j / 49, p = j % 49;
        float v = buf[(size_t)(b0 + img) * 1568 + j];
        xin[img * 2673 + ((p / 7 + 1) * 9 + (p % 7 + 1)) * 33 + ch] =
            to_tf32(fmaxf(v, 0.f));
    }
    __syncthreads();

    int lane = t & 31, wrp = t >> 5;
    int grp = lane >> 2, tig = lane & 3;
    int img = wrp >> 2, mh = (wrp >> 1) & 1, nh = wrp & 1;
    int rbase = img * 64 + mh * 32;

    int rb[2][2];
    #pragma unroll
    for (int mi = 0; mi < 2; mi++)
        #pragma unroll
        for (int h = 0; h < 2; h++) {
            int p = mh * 32 + mi * 16 + grp + h * 8;
            rb[mi][h] = (p < 49) ? img * 2673 + ((p / 7) * 9 + (p % 7)) * 33 : 0;
        }

    float acc[2][4][4];
    #pragma unroll
    for (int mi = 0; mi < 2; mi++)
        #pragma unroll
        for (int ni = 0; ni < 4; ni++)
            #pragma unroll
            for (int c = 0; c < 4; c++) acc[mi][ni][c] = 0.f;

    #pragma unroll
    for (int ky = 0; ky < 3; ky++) {
        #pragma unroll
        for (int kx = 0; kx < 3; kx++) {
            int s = ky * 3 + kx;
            int soff = (ky * 9 + kx) * 33;
            #pragma unroll
            for (int kk = 0; kk < 4; kk++) {
                int kb = kk * 8;
                unsigned a[2][4];
                #pragma unroll
                for (int mi = 0; mi < 2; mi++) {
                    a[mi][0] = __float_as_uint(xin[rb[mi][0] + soff + kb + tig]);
                    a[mi][1] = __float_as_uint(xin[rb[mi][1] + soff + kb + tig]);
                    a[mi][2] = __float_as_uint(xin[rb[mi][0] + soff + kb + tig + 4]);
                    a[mi][3] = __float_as_uint(xin[rb[mi][1] + soff + kb + tig + 4]);
                }
                #pragma unroll
                for (int ni = 0; ni < 4; ni++) {
                    int oct = nh * 4 + ni;
                    float2 bw = __ldg(wf + (size_t)s * 1024 + kk * 256 + oct * 32 + lane);
                    unsigned bb0 = __float_as_uint(bw.x);
                    unsigned bb1 = __float_as_uint(bw.y);
                    mma_tf32(acc[0][ni], a[0], bb0, bb1);
                    mma_tf32(acc[1][ni], a[1], bb0, bb1);
                }
            }
        }
    }

    #pragma unroll
    for (int mi = 0; mi < 2; mi++) {
        int rlo = rbase + mi * 16 + grp, rhi = rlo + 8;
        #pragma unroll
        for (int ni = 0; ni < 4; ni++) {
            int c0 = nh * 32 + ni * 8 + tig * 2;
            rs[rlo * 68 + c0]     = to_tf32(fmaxf(acc[mi][ni][0], 0.f));
            rs[rlo * 68 + c0 + 1] = to_tf32(fmaxf(acc[mi][ni][1], 0.f));
            rs[rhi * 68 + c0]     = to_tf32(fmaxf(acc[mi][ni][2], 0.f));
            rs[rhi * 68 + c0 + 1] = to_tf32(fmaxf(acc[mi][ni][3], 0.f));
        }
    }
    __syncthreads();

    float acc2[2][2][4];
    #pragma unroll
    for (int mi = 0; mi < 2; mi++)
        #pragma unroll
        for (int ni = 0; ni < 2; ni++)
            #pragma unroll
            for (int c = 0; c < 4; c++) acc2[mi][ni][c] = 0.f;

    #pragma unroll
    for (int kk = 0; kk < 8; kk++) {
        int kb = kk * 8;
        unsigned a[2][4];
        #pragma unroll
        for (int mi = 0; mi < 2; mi++) {
            int rlo = rbase + mi * 16 + grp;
            a[mi][0] = __float_as_uint(rs[rlo * 68 + kb + tig]);
            a[mi][1] = __float_as_uint(rs[(rlo + 8) * 68 + kb + tig]);
            a[mi][2] = __float_as_uint(rs[rlo * 68 + kb + tig + 4]);
            a[mi][3] = __float_as_uint(rs[(rlo + 8) * 68 + kb + tig + 4]);
        }
        #pragma unroll
        for (int ni = 0; ni < 2; ni++) {
            int c = nh * 16 + ni * 8 + grp;
            unsigned bb0 = __float_as_uint(w2s[(kb + tig) * 36 + c]);
            unsigned bb1 = __float_as_uint(w2s[(kb + tig + 4) * 36 + c]);
            mma_tf32(acc2[0][ni], a[0], bb0, bb1);
            mma_tf32(acc2[1][ni], a[1], bb0, bb1);
        }
    }

    #pragma unroll
    for (int mi = 0; mi < 2; mi++) {
        #pragma unroll
        for (int ni = 0; ni < 2; ni++) {
            #pragma unroll
            for (int ci = 0; ci < 4; ci++) {
                int p = mh * 32 + mi * 16 + grp + ((ci >= 2) ? 8 : 0);
                if (p < 49) {
                    int ch = nh * 16 + ni * 8 + tig * 2 + (ci & 1);
                    size_t g = (size_t)(b0 + img) * 1568 + ch * 49 + p;
                    float v = acc2[mi][ni][ci] + __ldg(buf + g);
                    buf[g] = fmaxf(v, 0.f);
                }
            }
        }
    }
}

// ======================================================================
// TF32 GEMM (decoder fc4): double-buffered smem        [round-13]
// ======================================================================
__global__ void __launch_bounds__(256) gemm_tc(
        const float* __restrict__ A,
        const float* __restrict__ W,
        const float* __restrict__ bias,
        float* __restrict__ C,
        int M, int N, int K) {
    __shared__ float As[2][128][17];
    __shared__ float Ws[2][64][17];
    int t = threadIdx.x, lane = t & 31, w = t >> 5;
    int grp = lane >> 2, tig = lane & 3;
    int m0 = blockIdx.x * 128, n0 = blockIdx.y * 64;
    int mw = (w & 3) * 32, nw = (w >> 2) * 32;
    float acc[2][4][4];
    #pragma unroll
    for (int mi = 0; mi < 2; mi++)
        #pragma unroll
        for (int ni = 0; ni < 4; ni++)
            #pragma unroll
            for (int c = 0; c < 4; c++) acc[mi][ni][c] = 0.f;

    int ar = t >> 1, ak = (t & 1) * 8;
    int wr = t >> 2, wk = (t & 3) * 4;
    const float* apb = A + (size_t)(m0 + ar) * K + ak;
    bool wval = (n0 + wr < N);
    const float* wpb = W + (size_t)(n0 + wr) * K + wk;

    float4 v0 = *(const float4*)apb;
    float4 v1 = *(const float4*)(apb + 4);
    float4 wv = wval ? *(const float4*)wpb : make_float4(0.f, 0.f, 0.f, 0.f);
    int s = 0;
    As[0][ar][ak + 0] = to_tf32(v0.x); As[0][ar][ak + 1] = to_tf32(v0.y);
    As[0][ar][ak + 2] = to_tf32(v0.z); As[0][ar][ak + 3] = to_tf32(v0.w);
    As[0][ar][ak + 4] = to_tf32(v1.x); As[0][ar][ak + 5] = to_tf32(v1.y);
    As[0][ar][ak + 6] = to_tf32(v1.z); As[0][ar][ak + 7] = to_tf32(v1.w);
    Ws[0][wr][wk + 0] = to_tf32(wv.x); Ws[0][wr][wk + 1] = to_tf32(wv.y);
    Ws[0][wr][wk + 2] = to_tf32(wv.z); Ws[0][wr][wk + 3] = to_tf32(wv.w);
    __syncthreads();

    for (int k0 = 0; k0 < K; k0 += 16) {
        bool more = (k0 + 16 < K);
        if (more) {
            v0 = *(const float4*)(apb + k0 + 16);
            v1 = *(const float4*)(apb + k0 + 20);
            wv = wval ? *(const float4*)(wpb + k0 + 16)
                      : make_float4(0.f, 0.f, 0.f, 0.f);
        }
        #pragma unroll
        for (int kk = 0; kk < 2; kk++) {
            int kb = kk * 8;
            unsigned a[2][4];
            #pragma unroll
            for (int mi = 0; mi < 2; mi++) {
                int r = mw + mi * 16 + grp;
                a[mi][0] = __float_as_uint(As[s][r][kb + tig]);
                a[mi][1] = __float_as_uint(As[s][r + 8][kb + tig]);
                a[mi][2] = __float_as_uint(As[s][r][kb + tig + 4]);
                a[mi][3] = __float_as_uint(As[s][r + 8][kb + tig + 4]);
            }
            #pragma unroll
            for (int ni = 0; ni < 4; ni++) {
                int n = nw + ni * 8 + grp;
                unsigned bb0 = __float_as_uint(Ws[s][n][kb + tig]);
                unsigned bb1 = __float_as_uint(Ws[s][n][kb + tig + 4]);
                mma_tf32(acc[0][ni], a[0], bb0, bb1);
                mma_tf32(acc[1][ni], a[1], bb0, bb1);
            }
        }
        if (more) {
            int d = s ^ 1;
            As[d][ar][ak + 0] = to_tf32(v0.x); As[d][ar][ak + 1] = to_tf32(v0.y);
            As[d][ar][ak + 2] = to_tf32(v0.z); As[d][ar][ak + 3] = to_tf32(v0.w);
            As[d][ar][ak + 4] = to_tf32(v1.x); As[d][ar][ak + 5] = to_tf32(v1.y);
            As[d][ar][ak + 6] = to_tf32(v1.z); As[d][ar][ak + 7] = to_tf32(v1.w);
            Ws[d][wr][wk + 0] = to_tf32(wv.x); Ws[d][wr][wk + 1] = to_tf32(wv.y);
            Ws[d][wr][wk + 2] = to_tf32(wv.z); Ws[d][wr][wk + 3] = to_tf32(wv.w);
            __syncthreads();
            s = d;
        }
    }
    #pragma unroll
    for (int mi = 0; mi < 2; mi++) {
        #pragma unroll
        for (int ni = 0; ni < 4; ni++) {
            #pragma unroll
            for (int ci = 0; ci < 4; ci++) {
                int r = m0 + mw + mi * 16 + grp + ((ci >= 2) ? 8 : 0);
                int n = n0 + nw + ni * 8 + tig * 2 + (ci & 1);
                if (n < N)
                    C[(size_t)r * N + n] = fmaxf(acc[mi][ni][ci] + bias[n], 0.f);
            }
        }
    }
}

// ======================================================================
// 3xTF32 GEMM (encoder fc1): double-buffered smem      [round-13]
// ======================================================================
__global__ void __launch_bounds__(256) gemm_tc3(
        const float* __restrict__ A,
        const float* __restrict__ W,
        const float* __restrict__ bias,
        float* __restrict__ C,
        int M, int N, int K) {
    __shared__ float As[2][128][17];
    __shared__ float Ws[2][64][17];
    int t = threadIdx.x, lane = t & 31, w = t >> 5;
    int grp = lane >> 2, tig = lane & 3;
    int m0 = blockIdx.x * 128, n0 = blockIdx.y * 64;
    int mw = (w & 3) * 32, nw = (w >> 2) * 32;
    float acc[2][4][4];
    #pragma unroll
    for (int mi = 0; mi < 2; mi++)
        #pragma unroll
        for (int ni = 0; ni < 4; ni++)
            #pragma unroll
            for (int c = 0; c < 4; c++) acc[mi][ni][c] = 0.f;

    int ar = t >> 1, ak = (t & 1) * 8;
    int wr = t >> 2, wk = (t & 3) * 4;
    const float* apb = A + (size_t)(m0 + ar) * K + ak;
    bool wval = (n0 + wr < N);
    const float* wpb = W + (size_t)(n0 + wr) * K + wk;

    float4 v0 = *(const float4*)apb;
    float4 v1 = *(const float4*)(apb + 4);
    float4 wv = wval ? *(const float4*)wpb : make_float4(0.f, 0.f, 0.f, 0.f);
    int s = 0;
    As[0][ar][ak + 0] = v0.x; As[0][ar][ak + 1] = v0.y;
    As[0][ar][ak + 2] = v0.z; As[0][ar][ak + 3] = v0.w;
    As[0][ar][ak + 4] = v1.x; As[0][ar][ak + 5] = v1.y;
    As[0][ar][ak + 6] = v1.z; As[0][ar][ak + 7] = v1.w;
    Ws[0][wr][wk + 0] = wv.x; Ws[0][wr][wk + 1] = wv.y;
    Ws[0][wr][wk + 2] = wv.z; Ws[0][wr][wk + 3] = wv.w;
    __syncthreads();

    for (int k0 = 0; k0 < K; k0 += 16) {
        bool more = (k0 + 16 < K);
        if (more) {
            v0 = *(const float4*)(apb + k0 + 16);
            v1 = *(const float4*)(apb + k0 + 20);
            wv = wval ? *(const float4*)(wpb + k0 + 16)
                      : make_float4(0.f, 0.f, 0.f, 0.f);
        }
        #pragma unroll
        for (int kk = 0; kk < 2; kk++) {
            int kb = kk * 8;
            unsigned ah[2][4], al[2][4];
            #pragma unroll
            for (int mi = 0; mi < 2; mi++) {
                int r = mw + mi * 16 + grp;
                split_tf32(As[s][r][kb + tig],         ah[mi][0], al[mi][0]);
                split_tf32(As[s][r + 8][kb + tig],     ah[mi][1], al[mi][1]);
                split_tf32(As[s][r][kb + tig + 4],     ah[mi][2], al[mi][2]);
                split_tf32(As[s][r + 8][kb + tig + 4], ah[mi][3], al[mi][3]);
            }
            #pragma unroll
            for (int ni = 0; ni < 4; ni++) {
                int n = nw + ni * 8 + grp;
                unsigned bh0, bl0, bh1, bl1;
                split_tf32(Ws[s][n][kb + tig],     bh0, bl0);
                split_tf32(Ws[s][n][kb + tig + 4], bh1, bl1);
                mma3(acc[0][ni], ah[0], al[0], bh0, bh1, bl0, bl1);
                mma3(acc[1][ni], ah[1], al[1], bh0, bh1, bl0, bl1);
            }
        }
        if (more) {
            int d = s ^ 1;
            As[d][ar][ak + 0] = v0.x; As[d][ar][ak + 1] = v0.y;
            As[d][ar][ak + 2] = v0.z; As[d][ar][ak + 3] = v0.w;
            As[d][ar][ak + 4] = v1.x; As[d][ar][ak + 5] = v1.y;
            As[d][ar][ak + 6] = v1.z; As[d][ar][ak + 7] = v1.w;
            Ws[d][wr][wk + 0] = wv.x; Ws[d][wr][wk + 1] = wv.y;
            Ws[d][wr][wk + 2] = wv.z; Ws[d][wr][wk + 3] = wv.w;
            __syncthreads();
            s = d;
        }
    }
    #pragma unroll
    for (int mi = 0; mi < 2; mi++) {
        #pragma unroll
        for (int ni = 0; ni < 4; ni++) {
            #pragma unroll
            for (int ci = 0; ci < 4; ci++) {
                int r = m0 + mw + mi * 16 + grp + ((ci >= 2) ? 8 : 0);
                int n = n0 + nw + ni * 8 + tig * 2 + (ci & 1);
                if (n < N)
                    C[(size_t)r * N + n] = fmaxf(acc[mi][ni][ci] + bias[n], 0.f);
            }
        }
    }
}

// ======================================================================
// convt2 inner body (compile-time tap tables)          [round-7 proven]
// ======================================================================
template<int DY0, int KY0, int DY1, int KY1,
         int DX0, int KX0, int DX1, int KX1>
__device__ __forceinline__ void ct2_body(
        const float* __restrict__ base, const float* __restrict__ w,
        float bv, float* __restrict__ outp, int m) {
    float acc[14];
    #pragma unroll
    for (int j = 0; j < 14; j++) acc[j] = bv;
    for (int ic = 0; ic < 16; ic++) {
        const float* xc = base + ic * 256;
        #pragma unroll
        for (int sy = 0; sy < 2; sy++) {
            int iy = m + (sy ? DY1 : DY0);
            float row[16];
            #pragma unroll
            for (int j = 0; j < 16; j++) row[j] = xc[(iy + 1) * 16 + j];
            {
                float wv = __ldg(w + ic * 16 + (sy ? KY1 : KY0) * 4 + KX0);
                #pragma unroll
                for (int n = 0; n < 14; n++) acc[n] += row[n + DX0 + 1] * wv;
            }
            {
                float wv = __ldg(w + ic * 16 + (sy ? KY1 : KY0) * 4 + KX1);
                #pragma unroll
                for (int n = 0; n < 14; n++) acc[n] += row[n + DX1 + 1] * wv;
            }
        }
    }
    #pragma unroll
    for (int n = 0; n < 14; n++) outp[2 * n] = acc[n];
}

// ======================================================================
// FUSED convt1+convt2 (decoder): convt1 weights via fragment texture
// smem = xin + hp = 59.4 KB -> 3 CTA/SM (24 warps/SM, was 16).
// ======================================================================
#define T13_IMSZ 2916
#define T13_ZB   5900                     // zero region inside xin tail
#define T13_XIN  6664                     // 2*2916 + 832 slack (zeroed)
#define T13_HP   T13_XIN                  // hp at 6664
#define T13_TOT  (T13_HP + 2 * 4096)      // 14856
#define T13_SMEM (T13_TOT * 4)            // 59424 B

__global__ void __launch_bounds__(256) convt12_tc(
        const float* __restrict__ in,
        const float2* __restrict__ wf,
        const float* __restrict__ bias,
        const float* __restrict__ c2w,
        const float* __restrict__ c2b,
        float* __restrict__ out) {
    extern __shared__ float sm[];
    float* xin = sm;
    float* hp  = sm + T13_HP;
    int t = threadIdx.x;
    int b0 = blockIdx.x * 2;

    for (int i = t; i < T13_XIN; i += 256) xin[i] = 0.f;
    for (int i = t; i < 8192; i += 256) hp[i] = 0.f;
    __syncthreads();
    for (int i = t; i < 2 * 1568; i += 256) {
        int img = i / 1568, j = i % 1568;
        int ic = j / 49, p = j % 49, iy = p / 7, ix = p % 7;
        xin[img * T13_IMSZ + ((iy + 1) * 9 + (ix + 1)) * 36 + ic] =
            to_tf32(in[(size_t)(b0 + img) * 1568 + j]);
    }
    __syncthreads();

    // ---- convt1 mma phase [round-4 proven, weights from texture] ----
    int lane = t & 31, wrp = t >> 5;
    int grp = lane >> 2, tig = lane & 3;
    int img = wrp >> 2, ph = wrp & 3;
    int a = ph >> 1, bp = ph & 1;
    int dyv[2], kyv[2], dxv[2], kxv[2];
    if (a == 0) { dyv[0] = 0; kyv[0] = 1; dyv[1] = -1; kyv[1] = 3; }
    else        { dyv[0] = 1; kyv[0] = 0; dyv[1] =  0; kyv[1] = 2; }
    if (bp == 0) { dxv[0] = 0; kxv[0] = 1; dxv[1] = -1; kxv[1] = 3; }
    else         { dxv[0] = 1; kxv[0] = 0; dxv[1] =  0; kxv[1] = 2; }

    int rb[4][2];
    #pragma unroll
    for (int mi = 0; mi < 4; mi++)
        #pragma unroll
        for (int h = 0; h < 2; h++) {
            int p = mi * 16 + grp + h * 8;
            rb[mi][h] = (p < 49)
                ? img * T13_IMSZ + ((p / 7 + 1) * 9 + (p % 7 + 1)) * 36
                : T13_ZB;
        }

    float acc[4][2][4];
    #pragma unroll
    for (int mi = 0; mi < 4; mi++)
        #pragma unroll
        for (int ni = 0; ni < 2; ni++)
            #pragma unroll
            for (int c = 0; c < 4; c++) acc[mi][ni][c] = 0.f;

    #pragma unroll
    for (int sy = 0; sy < 2; sy++) {
        #pragma unroll
        for (int sx = 0; sx < 2; sx++) {
            int soff = (dyv[sy] * 9 + dxv[sx]) * 36;
            int s = kyv[sy] * 4 + kxv[sx];
            const float2* wfs = wf + (size_t)s * 256;
            #pragma unroll
            for (int kk = 0; kk < 4; kk++) {
                int kb = kk * 8;
                unsigned afr[4][4];
                #pragma unroll
                for (int mi = 0; mi < 4; mi++) {
                    afr[mi][0] = __float_as_uint(xin[rb[mi][0] + soff + kb + tig]);
                    afr[mi][1] = __float_as_uint(xin[rb[mi][1] + soff + kb + tig]);
                    afr[mi][2] = __float_as_uint(xin[rb[mi][0] + soff + kb + tig + 4]);
                    afr[mi][3] = __float_as_uint(xin[rb[mi][1] + soff + kb + tig + 4]);
                }
                #pragma unroll
                for (int ni = 0; ni < 2; ni++) {
                    float2 bw = __ldg(wfs + kk * 64 + ni * 32 + lane);
                    unsigned bb0 = __float_as_uint(bw.x);
                    unsigned bb1 = __float_as_uint(bw.y);
                    #pragma unroll
                    for (int mi = 0; mi < 4; mi++)
                        mma_tf32(acc[mi][ni], afr[mi], bb0, bb1);
                }
            }
        }
    }

    // epilogue -> padded smem hp [img][oc][16][16] (halo 1), relu
    #pragma unroll
    for (int mi = 0; mi < 4; mi++) {
        #pragma unroll
        for (int ni = 0; ni < 2; ni++) {
            #pragma unroll
            for (int ci = 0; ci < 4; ci++) {
                int p = mi * 16 + grp + ((ci >= 2) ? 8 : 0);
                if (p < 49) {
                    int m = p / 7, n = p % 7;
                    int oc = ni * 8 + tig * 2 + (ci & 1);
                    int oy = 2 * m + a, ox = 2 * n + bp;
                    float v = acc[mi][ni][ci] + __ldg(bias + oc);
                    hp[img * 4096 + oc * 256 + (oy + 1) * 16 + (ox + 1)] =
                        fmaxf(v, 0.f);
                }
            }
        }
    }
    __syncthreads();

    // ---- convt2 phase (ct2_body, from hp) ----
    if (t < 112) {
        int ph2 = t / 28, r2 = t % 28;
        int img2 = r2 / 14, m2 = r2 % 14;
        int a2 = ph2 >> 1, b2 = ph2 & 1;
        const float* base2 = hp + img2 * 4096;
        float bv2 = c2b[0];
        float* outp = out + (size_t)(b0 + img2) * 784 + (2 * m2 + a2) * 28 + b2;
        if (ph2 == 0)      ct2_body<0, 1, -1, 3,  0, 1, -1, 3>(base2, c2w, bv2, outp, m2);
        else if (ph2 == 1) ct2_body<0, 1, -1, 3,  1, 0,  0, 2>(base2, c2w, bv2, outp, m2);
        else if (ph2 == 2) ct2_body<1, 0,  0, 2,  0, 1, -1, 3>(base2, c2w, bv2, outp, m2);
        else               ct2_body<1, 0,  0, 2,  1, 0,  0, 2>(base2, c2w, bv2, outp, m2);
    }
}

// ======================================================================
// fc2: z[B,32] = A[B,224] @ w^T + b  (fp32, feeds VQ)   [round-8]
// ======================================================================
__global__ void __launch_bounds__(256) fc2_kernel(
        const float* __restrict__ A,
        const float* __restrict__ w,
        const float* __restrict__ bias,
        float* __restrict__ out) {
    __shared__ float ws[32 * 224];
    int t = threadIdx.x;
    for (int i = t; i < 7168; i += 256) ws[i] = w[i];
    __syncthreads();
    int n = t & 31, r = t >> 5;
    float bv = bias[n];
    const float* wp = ws + n * 224;
    #pragma unroll
    for (int rr = 0; rr < 4; rr++) {
        int b = blockIdx.x * 32 + rr * 8 + r;
        const float* ap = A + (size_t)b * 224;
        float acc = bv;
        #pragma unroll 8
        for (int k = 0; k < 224; k++) acc += ap[k] * wp[k];
        out[(size_t)b * 32 + n] = acc;
    }
}

// ======================================================================
// VQ helpers (fp32 exact)
// ======================================================================
__global__ void enorm_kernel(const float* __restrict__ emb, float* __restrict__ enorm) {
    int e = blockIdx.x * blockDim.x + threadIdx.x;
    if (e < NE) {
        float s = 0.f;
        #pragma unroll
        for (int d = 0; d < ZD; d++) { float v = emb[e * ZD + d]; s += v * v; }
        enorm[e] = s;
    }
}

__global__ void zero_kernel(float* __restrict__ counts, float* __restrict__ sums,
                            float* __restrict__ loss) {
    int i = blockIdx.x * blockDim.x + threadIdx.x;
    if (i < NE) counts[i] = 0.f;
    if (i < NE * ZD) sums[i] = 0.f;
    if (i == 0) loss[0] = 0.f;
}

#define VQ_SMEM (NE * 36 * 4)

__global__ void __launch_bounds__(256) vq_kernel(
        const float* __restrict__ z,
        const float* __restrict__ emb,
        const float* __restrict__ enorm,
        int* __restrict__ idx,
        float* __restrict__ counts,
        float* __restrict__ sums,
        float* __restrict__ loss) {
    extern __shared__ float es[];          // [512][36]
    __shared__ float en[NE];
    __shared__ float zs[8][ZD];
    int t = threadIdx.x, lane = t & 31, wl = t >> 5;
    for (int i = t; i < NE * ZD; i += 256) {
        int e = i >> 5, d = i & 31;
        es[e * 36 + d] = emb[i];
    }
    for (int i = t; i < NE; i += 256) en[i] = enorm[i];
    __syncthreads();

    for (int rr = 0; rr < 8; rr++) {
        int row = blockIdx.x * 64 + wl * 8 + rr;
        zs[wl][lane] = z[(size_t)row * ZD + lane];
        __syncwarp();
        float best = 3.4e38f; int bi = NE;
        for (int e = lane; e < NE; e += 32) {
            const float* ep = es + e * 36;
            float dot = 0.f;
            #pragma unroll
            for (int d = 0; d < ZD; d += 4) {
                float4 v = *(const float4*)(ep + d);
                dot += zs[wl][d + 0] * v.x;
                dot += zs[wl][d + 1] * v.y;
                dot += zs[wl][d + 2] * v.z;
                dot += zs[wl][d + 3] * v.w;
            }
            float s = en[e] - 2.f * dot;
            if (s < best) { best = s; bi = e; }
        }
        #pragma unroll
        for (int off = 16; off; off >>= 1) {
            float ob = __shfl_xor_sync(0xffffffffu, best, off);
            int   oi = __shfl_xor_sync(0xffffffffu, bi, off);
            if (ob < best || (ob == best && oi < bi)) { best = ob; bi = oi; }
        }
        float zl = zs[wl][lane];
        float diff = es[bi * 36 + lane] - zl;
        float d2 = diff * diff;
        #pragma unroll
        for (int off = 16; off; off >>= 1)
            d2 += __shfl_xor_sync(0xffffffffu, d2, off);
        if (lane == 0) {
            idx[row] = bi;
            atomicAdd(&counts[bi], 1.f);
            atomicAdd(loss, d2);
        }
        atomicAdd(&sums[bi * ZD + lane], zl);
        __syncwarp();
    }
}

__global__ void embnew_kernel(const float* __restrict__ m_mat,
                              const float* __restrict__ n_mat,
                              const float* __restrict__ sums,
                              const float* __restrict__ counts,
                              float* __restrict__ out) {
    int i = blockIdx.x * blockDim.x + threadIdx.x;
    if (i < NE * ZD) {
        int e = i >> 5;
        float m = m_mat[i] * GAMMA + sums[i] * ONE_M_GAMMA;
        float n = n_mat[e] * GAMMA + counts[e] * ONE_M_GAMMA;
        out[i] = m / n;
    }
}

__global__ void finalize_kernel(const float* __restrict__ counts,
                                const float* __restrict__ loss,
                                float* __restrict__ out_scalars) {
    __shared__ float red[NE];
    int t = threadIdx.x;
    float c = counts[t];
    float em = c * (1.f / (float)BATCH);
    red[t] = em * logf(em + 1e-10f);
    __syncthreads();
    for (int s = 256; s; s >>= 1) {
        if (t < s) red[t] += red[t + s];
        __syncthreads();
    }
    if (t == 0) {
        float q = loss[0] * (1.f / ((float)BATCH * (float)ZD));
        out_scalars[0] = q;
        out_scalars[1] = BETA * q;
        out_scalars[2] = expf(-red[0]);
    }
}

// ======================================================================
// fc3 (fp32): 16 images/CTA                           [round-8, proven]
// ======================================================================
__global__ void __launch_bounds__(224) fc3_kernel(
        const float* __restrict__ emb,
        const int* __restrict__ idx,
        const float* __restrict__ w,
        const float* __restrict__ bias,
        float* __restrict__ out) {
    __shared__ float ws[224 * ZD];
    __shared__ float zq[16][ZD + 1];
    int b0 = blockIdx.x * 16, t = threadIdx.x;
    for (int i = t; i < 224 * ZD; i += 224) ws[i] = w[i];
    for (int i = t; i < 16 * ZD; i += 224) {
        int im = i >> 5, d = i & 31;
        zq[im][d] = emb[(size_t)idx[b0 + im] * ZD + d];
    }
    __syncthreads();
    float bv = bias[t];
    float wreg[ZD];
    const float* wp = ws + t * ZD;
    #pragma unroll
    for (int k = 0; k < ZD; k++) wreg[k] = wp[k];
    #pragma unroll 4
    for (int im = 0; im < 16; im++) {
        float acc = bv;
        #pragma unroll
        for (int k = 0; k < ZD; k++) acc += zq[im][k] * wreg[k];
        out[(size_t)(b0 + im) * 224 + t] = fmaxf(acc, 0.f);
    }
}

// ======================================================================
// launch
// ======================================================================
extern "C" void kernel_launch(void* const* d_in, const int* in_sizes, int n_in,
                              void* d_out, int out_size) {
    const float* x        = (const float*)d_in[0];
    const float* conv1_w  = (const float*)d_in[1];
    const float* conv1_b  = (const float*)d_in[2];
    const float* conv2_w  = (const float*)d_in[3];
    const float* conv2_b  = (const float*)d_in[4];
    const float* res1_w1  = (const float*)d_in[5];
    const float* res1_w2  = (const float*)d_in[6];
    const float* fc1_w    = (const float*)d_in[7];
    const float* fc1_b    = (const float*)d_in[8];
    const float* fc2_w    = (const float*)d_in[9];
    const float* fc2_b    = (const float*)d_in[10];
    const float* emb      = (const float*)d_in[11];
    const float* n_mat    = (const float*)d_in[12];
    const float* m_mat    = (const float*)d_in[13];
    const float* fc3_w    = (const float*)d_in[14];
    const float* fc3_b    = (const float*)d_in[15];
    const float* fc4_w    = (const float*)d_in[16];
    const float* fc4_b    = (const float*)d_in[17];
    const float* res2_w1  = (const float*)d_in[18];
    const float* res2_w2  = (const float*)d_in[19];
    const float* convt1_w = (const float*)d_in[20];
    const float* convt1_b = (const float*)d_in[21];
    const float* convt2_w = (const float*)d_in[22];
    const float* convt2_b = (const float*)d_in[23];
    float* out = (float*)d_out;

    float *h2, *a, *z, *enorm, *counts, *sums, *loss;
    int* idx;
    float2 *wf_r1, *wf_r2, *wf_c2, *wf_t1;
    cudaGetSymbolAddress((void**)&h2,     g_h2);
    cudaGetSymbolAddress((void**)&a,      g_a);
    cudaGetSymbolAddress((void**)&z,      g_z);
    cudaGetSymbolAddress((void**)&idx,    g_idx);
    cudaGetSymbolAddress((void**)&enorm,  g_enorm);
    cudaGetSymbolAddress((void**)&counts, g_counts);
    cudaGetSymbolAddress((void**)&sums,   g_sums);
    cudaGetSymbolAddress((void**)&loss,   g_loss);
    cudaGetSymbolAddress((void**)&wf_r1,  g_wf_r1);
    cudaGetSymbolAddress((void**)&wf_r2,  g_wf_r2);
    cudaGetSymbolAddress((void**)&wf_c2,  g_wf_c2);
    cudaGetSymbolAddress((void**)&wf_t1,  g_wf_t1);

    cudaFuncSetAttribute(conv12_tc3,
                         cudaFuncAttributeMaxDynamicSharedMemorySize, C12_SMEM);
    cudaFuncSetAttribute(res_tc3,
                         cudaFuncAttributeMaxDynamicSharedMemorySize, E3_SMEM);
    cudaFuncSetAttribute(res_tcd,
                         cudaFuncAttributeMaxDynamicSharedMemorySize, D3_SMEM);
    cudaFuncSetAttribute(convt12_tc,
                         cudaFuncAttributeMaxDynamicSharedMemorySize, T13_SMEM);
    cudaFuncSetAttribute(vq_kernel,
                         cudaFuncAttributeMaxDynamicSharedMemorySize, VQ_SMEM);

    // weight repack (fragment-order textures)
    repack_res<<<36, 256>>>(res1_w1, wf_r1, 0);
    repack_res<<<36, 256>>>(res2_w1, wf_r2, 1);
    repack_c2 <<<16, 256>>>(conv2_w, wf_c2);
    repack_t1 <<<16, 256>>>(convt1_w, wf_t1);

    // encoder (3xTF32 = fp32-class accuracy; VQ path preserved)
    conv12_tc3<<<BATCH / 2, 256, C12_SMEM>>>(x, conv1_w, conv1_b, wf_c2,
                                             conv2_b, h2);
    res_tc3  <<<BATCH / 2, 256, E3_SMEM>>>(h2, wf_r1, res1_w2);
    gemm_tc3<<<dim3(BATCH / 128, 4), 256>>>(h2, fc1_w, fc1_b, a,
                                            BATCH, 224, 1568);
    fc2_kernel<<<BATCH / 32, 256>>>(a, fc2_w, fc2_b, z);

    // VQ
    zero_kernel <<<(NE * ZD + 255) / 256, 256>>>(counts, sums, loss);
    enorm_kernel<<<2, 256>>>(emb, enorm);
    vq_kernel   <<<BATCH / 64, 256, VQ_SMEM>>>(z, emb, enorm, idx, counts,
                                               sums, loss);
    embnew_kernel  <<<(NE * ZD + 255) / 256, 256>>>(m_mat, n_mat, sums, counts,
                                                    out + OFF_SCAL + 3);
    finalize_kernel<<<1, NE>>>(counts, loss, out + OFF_SCAL);

    // decoder (single tf32)
    fc3_kernel<<<BATCH / 16, 224>>>(emb, idx, fc3_w, fc3_b, a);
    gemm_tc<<<dim3(BATCH / 128, 25), 256>>>(a, fc4_w, fc4_b, h2,
                                            BATCH, 1568, 224);
    res_tcd<<<BATCH / 2, 256, D3_SMEM>>>(h2, wf_r2, res2_w2);
    convt12_tc<<<BATCH / 2, 256, T13_SMEM>>>(h2, wf_t1, convt1_b,
                                             convt2_w, convt2_b, out);
}